// round 1
// baseline (speedup 1.0000x reference)
#include <cuda_runtime.h>
#include <math.h>

#define NTOK  131072
#define DIMV  256
#define HID   512
#define NE    16
#define CAP   18023
#define NSLOT (NTOK*2)
#define ECAP  (NE*CAP)
#define NB    32768

// ---------------- scratch (static device globals; no runtime allocation) -----
__device__ float g_gate[NSLOT];
__device__ int   g_expert[NSLOT];
__device__ unsigned char g_kept[NSLOT];
__device__ int   g_counts[NE];
__device__ int   g_cursor[NE];
__device__ int   g_perm[ECAP];
__device__ int   g_hist[NE*NB];
__device__ int   g_bstar[NE], g_rrem[NE], g_bcnt[NE], g_bbase[NE], g_bcursor[NE];
__device__ int   g_blist[NSLOT];
__device__ int   g_btotal;
__device__ float g_imp[NE];
__device__ float g_ent;
__device__ float g_h[(size_t)ECAP * HID];    // ~590 MB
__device__ float g_y[(size_t)NSLOT * DIMV];  // ~268 MB

// ---------------- zero per-iteration accumulators ---------------------------
__global__ void k_zero() {
    int i = blockIdx.x * blockDim.x + threadIdx.x;
    for (int j = i; j < NE*NB; j += gridDim.x * blockDim.x) g_hist[j] = 0;
    if (i < NE) { g_counts[i] = 0; g_cursor[i] = 0; g_bcursor[i] = 0; g_imp[i] = 0.f; }
    if (i == 0) { g_ent = 0.f; g_btotal = 0; }
}

// ---------------- router: one warp per token --------------------------------
__global__ void k_router(const float* __restrict__ ctx,
                         const float* __restrict__ Wg,
                         const float* __restrict__ bg) {
    __shared__ float sW[NE*DIMV];   // transposed: sW[e*DIMV + d]
    __shared__ float s_imp[NE];
    __shared__ float s_ent;
    int tid = threadIdx.x;
    for (int i = tid; i < NE*DIMV; i += blockDim.x)
        sW[(i & 15) * DIMV + (i >> 4)] = Wg[i];
    if (tid < NE) s_imp[tid] = 0.f;
    if (tid == 0) s_ent = 0.f;
    __syncthreads();

    int warp = tid >> 5, lane = tid & 31;
    int t = blockIdx.x * 8 + warp;
    const float* x = ctx + (size_t)t * DIMV;

    float acc[NE];
#pragma unroll
    for (int e = 0; e < NE; e++) acc[e] = 0.f;
#pragma unroll
    for (int k = 0; k < 8; k++) {
        float xv = x[lane + 32*k];
#pragma unroll
        for (int e = 0; e < NE; e++) acc[e] += xv * sW[e*DIMV + lane + 32*k];
    }
#pragma unroll
    for (int e = 0; e < NE; e++) {
#pragma unroll
        for (int off = 16; off; off >>= 1)
            acc[e] += __shfl_xor_sync(0xffffffffu, acc[e], off);
        acc[e] += bg[e];
    }
    // full softmax stats
    float m = acc[0];
#pragma unroll
    for (int e = 1; e < NE; e++) m = fmaxf(m, acc[e]);
    float sum = 0.f;
#pragma unroll
    for (int e = 0; e < NE; e++) sum += expf(acc[e] - m);

    if (lane < NE) {
        float p = expf(acc[lane] - m) / sum;
        atomicAdd(&s_imp[lane], p);
        float ent = -p * logf(fmaxf(p, 1e-9f));
#pragma unroll
        for (int off = 8; off; off >>= 1)
            ent += __shfl_xor_sync(0xffffu, ent, off);
        if (lane == 0) atomicAdd(&s_ent, ent);
    }

    if (lane == 0) {
        int i0 = 0; float v0 = acc[0];
#pragma unroll
        for (int e = 1; e < NE; e++) if (acc[e] > v0) { v0 = acc[e]; i0 = e; }
        int i1 = (i0 == 0) ? 1 : 0; float v1 = acc[i1];
#pragma unroll
        for (int e = 0; e < NE; e++)
            if (e != i0 && acc[e] > v1) { v1 = acc[e]; i1 = e; }
        float ex = expf(v1 - v0);
        float gg0 = 1.f / (1.f + ex);
        float gg1 = ex / (1.f + ex);
        int s0 = 2*t, s1 = 2*t + 1;
        g_expert[s0] = i0; g_expert[s1] = i1;
        g_gate[s0] = gg0;  g_gate[s1] = gg1;
        atomicAdd(&g_counts[i0], 1);
        atomicAdd(&g_counts[i1], 1);
        atomicAdd(&g_hist[i0*NB + (int)(__float_as_uint(gg0) >> 17)], 1);
        atomicAdd(&g_hist[i1*NB + (int)(__float_as_uint(gg1) >> 17)], 1);
    }
    __syncthreads();
    if (tid < NE) atomicAdd(&g_imp[tid], s_imp[tid]);
    if (tid == 0) atomicAdd(&g_ent, s_ent);
}

// ---------------- exact capacity cutoff per expert ---------------------------
__global__ void k_cutoff() {
    int e = blockIdx.x, tid = threadIdx.x;
    __shared__ int chunk[256], suffix[256];
    if (g_counts[e] <= CAP) {
        if (tid == 0) { g_bstar[e] = -1; g_rrem[e] = 0; g_bcnt[e] = 0; }
        return;
    }
    const int* h = g_hist + e*NB;
    int b0 = tid * 128;
    int s = 0;
    for (int b = b0; b < b0 + 128; b++) s += h[b];
    chunk[tid] = s;
    __syncthreads();
    if (tid == 0) {
        int run = 0;
        for (int i = 255; i >= 0; i--) { suffix[i] = run; run += chunk[i]; }
    }
    __syncthreads();
    int cum = suffix[tid];                 // count strictly above this chunk
    for (int b = b0 + 127; b >= b0; b--) {
        int hb = h[b];
        if (cum < CAP && cum + hb >= CAP) {
            g_bstar[e] = b; g_rrem[e] = CAP - cum; g_bcnt[e] = hb;
        }
        cum += hb;
    }
}

__global__ void k_scan() {
    int base = 0;
    for (int e = 0; e < NE; e++) { g_bbase[e] = base; base += g_bcnt[e]; }
    g_btotal = base;
}

__global__ void k_flags() {
    int s = blockIdx.x * blockDim.x + threadIdx.x;
    if (s >= NSLOT) return;
    int e = g_expert[s];
    unsigned char kept;
    if (g_counts[e] <= CAP) kept = 1;
    else {
        int b  = (int)(__float_as_uint(g_gate[s]) >> 17);
        int bs = g_bstar[e];
        if (b > bs) kept = 1;
        else if (b < bs) kept = 0;
        else {
            kept = 0;
            int p = atomicAdd(&g_bcursor[e], 1);
            g_blist[g_bbase[e] + p] = s;
        }
    }
    g_kept[s] = kept;
}

// exact stable rank within the boundary bucket: (score desc, slot asc)
__global__ void k_boundary() {
    int total = g_btotal;
    for (int i = blockIdx.x * blockDim.x + threadIdx.x; i < total;
         i += gridDim.x * blockDim.x) {
        int si = g_blist[i];
        int e  = g_expert[si];
        int base = g_bbase[e], mm = g_bcnt[e];
        unsigned int ki = __float_as_uint(g_gate[si]);
        int better = 0;
        for (int j = base; j < base + mm; j++) {
            int sj = g_blist[j];
            unsigned int kj = __float_as_uint(g_gate[sj]);
            better += (kj > ki) || (kj == ki && sj < si);
        }
        if (better < g_rrem[e]) g_kept[si] = 1;
    }
}

__global__ void k_compact() {
    int s = blockIdx.x * blockDim.x + threadIdx.x;
    if (s >= NSLOT) return;
    if (g_kept[s]) {
        int e = g_expert[s];
        int p = atomicAdd(&g_cursor[e], 1);
        g_perm[e*CAP + p] = s;
    }
}

// ---------------- GEMM1: H = relu(X_gather @ W1[e] + b1[e]) ------------------
// 128x128 block tile, BK=16, 256 threads, 8x8 micro-tile
__global__ void __launch_bounds__(256, 2)
k_gemm1(const float* __restrict__ ctx,
        const float* __restrict__ W1,
        const float* __restrict__ b1) {
    int e = blockIdx.z;
    int Me = min(g_counts[e], CAP);
    int m0 = blockIdx.x * 128;
    if (m0 >= Me) return;
    int n0 = blockIdx.y * 128;

    __shared__ float As[16][128];
    __shared__ float Bs[16][128];
    __shared__ int s_tok[128];

    int tid = threadIdx.x;
    if (tid < 128) {
        int gr = m0 + tid;
        s_tok[tid] = (gr < Me) ? (g_perm[e*CAP + gr] >> 1) : -1;
    }
    const float* W = W1 + (size_t)e * DIMV * HID;

    float acc[8][8];
#pragma unroll
    for (int i = 0; i < 8; i++)
#pragma unroll
        for (int j = 0; j < 8; j++) acc[i][j] = 0.f;

    int tx = tid & 15, ty = tid >> 4;
    int ar = tid >> 1, aq = tid & 1;
    int bk = tid >> 4, bf = tid & 15;
    __syncthreads();

    for (int k0 = 0; k0 < DIMV; k0 += 16) {
        int tok = s_tok[ar];
        float4 a0, a1;
        if (tok >= 0) {
            const float4* ap = (const float4*)(ctx + (size_t)tok*DIMV + k0 + aq*8);
            a0 = ap[0]; a1 = ap[1];
        } else {
            a0 = make_float4(0.f,0.f,0.f,0.f); a1 = a0;
        }
        float4 bv0 = *(const float4*)(W + (size_t)(k0 + bk)*HID + n0 + bf*4);
        float4 bv1 = *(const float4*)(W + (size_t)(k0 + bk)*HID + n0 + 64 + bf*4);
        __syncthreads();
        As[aq*8+0][ar] = a0.x; As[aq*8+1][ar] = a0.y;
        As[aq*8+2][ar] = a0.z; As[aq*8+3][ar] = a0.w;
        As[aq*8+4][ar] = a1.x; As[aq*8+5][ar] = a1.y;
        As[aq*8+6][ar] = a1.z; As[aq*8+7][ar] = a1.w;
        *(float4*)&Bs[bk][bf*4]      = bv0;
        *(float4*)&Bs[bk][64 + bf*4] = bv1;
        __syncthreads();
#pragma unroll
        for (int kk = 0; kk < 16; kk++) {
            float4 x0 = *(const float4*)&As[kk][ty*8];
            float4 x1 = *(const float4*)&As[kk][ty*8 + 4];
            float4 y0 = *(const float4*)&Bs[kk][tx*8];
            float4 y1 = *(const float4*)&Bs[kk][tx*8 + 4];
            float av[8] = {x0.x,x0.y,x0.z,x0.w,x1.x,x1.y,x1.z,x1.w};
            float bv[8] = {y0.x,y0.y,y0.z,y0.w,y1.x,y1.y,y1.z,y1.w};
#pragma unroll
            for (int i = 0; i < 8; i++)
#pragma unroll
                for (int j = 0; j < 8; j++) acc[i][j] += av[i] * bv[j];
        }
    }
    const float4* bb = (const float4*)(b1 + (size_t)e*HID + n0 + tx*8);
    float4 bias0 = bb[0], bias1 = bb[1];
#pragma unroll
    for (int i = 0; i < 8; i++) {
        int gr = m0 + ty*8 + i;
        if (gr < Me) {
            float* hrow = g_h + (size_t)(e*CAP + gr)*HID + n0 + tx*8;
            float4 o0, o1;
            o0.x = fmaxf(acc[i][0] + bias0.x, 0.f);
            o0.y = fmaxf(acc[i][1] + bias0.y, 0.f);
            o0.z = fmaxf(acc[i][2] + bias0.z, 0.f);
            o0.w = fmaxf(acc[i][3] + bias0.w, 0.f);
            o1.x = fmaxf(acc[i][4] + bias1.x, 0.f);
            o1.y = fmaxf(acc[i][5] + bias1.y, 0.f);
            o1.z = fmaxf(acc[i][6] + bias1.z, 0.f);
            o1.w = fmaxf(acc[i][7] + bias1.w, 0.f);
            *(float4*)hrow       = o0;
            *(float4*)(hrow + 4) = o1;
        }
    }
}

// ---------------- GEMM2: Y = (H @ W2[e] + b2[e]) * gate, scattered per slot --
__global__ void __launch_bounds__(256, 2)
k_gemm2(const float* __restrict__ W2,
        const float* __restrict__ b2) {
    int e = blockIdx.z;
    int Me = min(g_counts[e], CAP);
    int m0 = blockIdx.x * 128;
    if (m0 >= Me) return;
    int n0 = blockIdx.y * 128;

    __shared__ float As[16][128];
    __shared__ float Bs[16][128];
    __shared__ int   s_slot[128];
    __shared__ float s_gate[128];

    int tid = threadIdx.x;
    if (tid < 128) {
        int gr = m0 + tid;
        if (gr < Me) {
            int s = g_perm[e*CAP + gr];
            s_slot[tid] = s;
            s_gate[tid] = g_gate[s];
        } else { s_slot[tid] = -1; s_gate[tid] = 0.f; }
    }
    const float* W = W2 + (size_t)e * HID * DIMV;

    float acc[8][8];
#pragma unroll
    for (int i = 0; i < 8; i++)
#pragma unroll
        for (int j = 0; j < 8; j++) acc[i][j] = 0.f;

    int tx = tid & 15, ty = tid >> 4;
    int ar = tid >> 1, aq = tid & 1;
    int bk = tid >> 4, bf = tid & 15;
    __syncthreads();

    for (int k0 = 0; k0 < HID; k0 += 16) {
        float4 a0, a1;
        if (s_slot[ar] >= 0) {
            const float4* ap = (const float4*)(g_h + (size_t)(e*CAP + m0 + ar)*HID + k0 + aq*8);
            a0 = ap[0]; a1 = ap[1];
        } else {
            a0 = make_float4(0.f,0.f,0.f,0.f); a1 = a0;
        }
        float4 bv0 = *(const float4*)(W + (size_t)(k0 + bk)*DIMV + n0 + bf*4);
        float4 bv1 = *(const float4*)(W + (size_t)(k0 + bk)*DIMV + n0 + 64 + bf*4);
        __syncthreads();
        As[aq*8+0][ar] = a0.x; As[aq*8+1][ar] = a0.y;
        As[aq*8+2][ar] = a0.z; As[aq*8+3][ar] = a0.w;
        As[aq*8+4][ar] = a1.x; As[aq*8+5][ar] = a1.y;
        As[aq*8+6][ar] = a1.z; As[aq*8+7][ar] = a1.w;
        *(float4*)&Bs[bk][bf*4]      = bv0;
        *(float4*)&Bs[bk][64 + bf*4] = bv1;
        __syncthreads();
#pragma unroll
        for (int kk = 0; kk < 16; kk++) {
            float4 x0 = *(const float4*)&As[kk][ty*8];
            float4 x1 = *(const float4*)&As[kk][ty*8 + 4];
            float4 y0 = *(const float4*)&Bs[kk][tx*8];
            float4 y1 = *(const float4*)&Bs[kk][tx*8 + 4];
            float av[8] = {x0.x,x0.y,x0.z,x0.w,x1.x,x1.y,x1.z,x1.w};
            float bv[8] = {y0.x,y0.y,y0.z,y0.w,y1.x,y1.y,y1.z,y1.w};
#pragma unroll
            for (int i = 0; i < 8; i++)
#pragma unroll
                for (int j = 0; j < 8; j++) acc[i][j] += av[i] * bv[j];
        }
    }
    const float4* bb = (const float4*)(b2 + (size_t)e*DIMV + n0 + tx*8);
    float4 bias0 = bb[0], bias1 = bb[1];
#pragma unroll
    for (int i = 0; i < 8; i++) {
        int r = ty*8 + i;
        int slot = s_slot[r];
        if (slot >= 0) {
            float g = s_gate[r];
            float* yr = g_y + (size_t)slot*DIMV + n0 + tx*8;
            float4 o0, o1;
            o0.x = (acc[i][0] + bias0.x) * g;
            o0.y = (acc[i][1] + bias0.y) * g;
            o0.z = (acc[i][2] + bias0.z) * g;
            o0.w = (acc[i][3] + bias0.w) * g;
            o1.x = (acc[i][4] + bias1.x) * g;
            o1.y = (acc[i][5] + bias1.y) * g;
            o1.z = (acc[i][6] + bias1.z) * g;
            o1.w = (acc[i][7] + bias1.w) * g;
            *(float4*)yr       = o0;
            *(float4*)(yr + 4) = o1;
        }
    }
}

// ---------------- combine: deterministic per-token sum of its <=2 slots ------
__global__ void k_combine(float* __restrict__ out) {
    int idx = blockIdx.x * blockDim.x + threadIdx.x;   // NTOK*64 float4 lanes
    if (idx >= NTOK * 64) return;
    int t = idx >> 6, f = idx & 63;
    const float4* y4 = (const float4*)g_y;
    float4 r = make_float4(0.f, 0.f, 0.f, 0.f);
    if (g_kept[2*t]) {
        float4 a = y4[(size_t)(2*t)*64 + f];
        r.x += a.x; r.y += a.y; r.z += a.z; r.w += a.w;
    }
    if (g_kept[2*t + 1]) {
        float4 a = y4[(size_t)(2*t + 1)*64 + f];
        r.x += a.x; r.y += a.y; r.z += a.z; r.w += a.w;
    }
    ((float4*)out)[(size_t)t*64 + f] = r;
}

// ---------------- finalize: aux_loss, entropy, dispatch ----------------------
__global__ void k_final(float* __restrict__ out, int out_size) {
    int lane = threadIdx.x;
    int c = (lane < NE) ? min(g_counts[lane], CAP) : 0;
    int tot = c;
#pragma unroll
    for (int off = 16; off; off >>= 1) tot += __shfl_xor_sync(0xffffffffu, tot, off);
    float denom = fmaxf((float)tot, 1.f);
    float aux = 0.f;
    if (lane < NE)
        aux = (g_imp[lane] / (float)NTOK) * ((float)c / denom) * (float)NE;
#pragma unroll
    for (int off = 16; off; off >>= 1) aux += __shfl_xor_sync(0xffffffffu, aux, off);
    int base = NTOK * DIMV;
    if (lane == 0 && out_size > base)     out[base]     = aux;
    if (lane == 0 && out_size > base + 1) out[base + 1] = g_ent / (float)NTOK;
    if (lane < NE && out_size > base + 2 + lane) out[base + 2 + lane] = (float)c;
}

// ---------------- launch ------------------------------------------------------
extern "C" void kernel_launch(void* const* d_in, const int* in_sizes, int n_in,
                              void* d_out, int out_size) {
    const float* ctx = (const float*)d_in[0];
    const float* Wg  = (const float*)d_in[1];
    const float* bg  = (const float*)d_in[2];
    const float* W1  = (const float*)d_in[3];
    const float* b1  = (const float*)d_in[4];
    const float* W2  = (const float*)d_in[5];
    const float* b2  = (const float*)d_in[6];
    float* out = (float*)d_out;

    k_zero<<<512, 256>>>();
    k_router<<<NTOK/8, 256>>>(ctx, Wg, bg);
    k_cutoff<<<NE, 256>>>();
    k_scan<<<1, 1>>>();
    k_flags<<<NSLOT/256, 256>>>();
    k_boundary<<<256, 256>>>();
    k_compact<<<NSLOT/256, 256>>>();
    dim3 g1((CAP + 127)/128, HID/128, NE);
    k_gemm1<<<g1, 256>>>(ctx, W1, b1);
    dim3 g2((CAP + 127)/128, DIMV/128, NE);
    k_gemm2<<<g2, 256>>>(W2, b2);
    k_combine<<<(NTOK*64)/256, 256>>>(out);
    k_final<<<1, 32>>>(out, out_size);
}

// round 3
// speedup vs baseline: 1.9908x; 1.9908x over previous
#include <cuda_runtime.h>
#include <cuda_fp16.h>
#include <math.h>
#include <stdint.h>

#define NTOK  131072
#define DIMV  256
#define HID   512
#define NE    16
#define CAP   18023
#define NSLOT (NTOK*2)
#define ECAP  (NE*CAP)
#define NB    32768
#define MTILES ((CAP+127)/128)

// ---------------- scratch (static device globals) ----------------------------
__device__ float g_gate[NSLOT];
__device__ int   g_expert[NSLOT];
__device__ unsigned char g_kept[NSLOT];
__device__ int   g_counts[NE];
__device__ int   g_cursor[NE];
__device__ int   g_perm[ECAP];
__device__ int   g_hist[NE*NB];
__device__ int   g_bstar[NE], g_rrem[NE], g_bcnt[NE], g_bbase[NE], g_bcursor[NE];
__device__ int   g_blist[NSLOT];
__device__ int   g_btotal;
__device__ float g_imp[NE];
__device__ float g_ent;

// fp16 operands: activations split hi/lo, weights single fp16 (transposed)
__device__ __half g_ctx_hi[(size_t)NTOK * DIMV];
__device__ __half g_ctx_lo[(size_t)NTOK * DIMV];
__device__ __half g_w1t[(size_t)NE * HID * DIMV];   // [e][h][d]
__device__ __half g_w2t[(size_t)NE * DIMV * HID];   // [e][d][h]
__device__ __half g_h_hi[(size_t)ECAP * HID];
__device__ __half g_h_lo[(size_t)ECAP * HID];
__device__ float  g_y[(size_t)NSLOT * DIMV];

// ---------------- helpers ----------------------------------------------------
__device__ __forceinline__ uint32_t smem_u32(const void* p) {
    uint32_t a;
    asm("{ .reg .u64 t; cvta.to.shared.u64 t, %1; cvt.u32.u64 %0, t; }"
        : "=r"(a) : "l"(p));
    return a;
}
__device__ __forceinline__ uint32_t lds32(uint32_t addr) {
    uint32_t v; asm volatile("ld.shared.b32 %0, [%1];" : "=r"(v) : "r"(addr));
    return v;
}
__device__ __forceinline__ void cpasync16(uint32_t dst, const void* src, int srcsz) {
    asm volatile("cp.async.cg.shared.global [%0], [%1], 16, %2;"
                 :: "r"(dst), "l"(src), "r"(srcsz) : "memory");
}
#define CP_COMMIT() asm volatile("cp.async.commit_group;" ::: "memory")
#define CP_WAIT1()  asm volatile("cp.async.wait_group 1;" ::: "memory")
#define CP_WAIT0()  asm volatile("cp.async.wait_group 0;" ::: "memory")

__device__ __forceinline__ void mma16816(float* c, const uint32_t* a, const uint32_t* b) {
    asm volatile(
        "mma.sync.aligned.m16n8k16.row.col.f32.f16.f16.f32 "
        "{%0,%1,%2,%3}, {%4,%5,%6,%7}, {%8,%9}, {%0,%1,%2,%3};"
        : "+f"(c[0]), "+f"(c[1]), "+f"(c[2]), "+f"(c[3])
        : "r"(a[0]), "r"(a[1]), "r"(a[2]), "r"(a[3]), "r"(b[0]), "r"(b[1]));
}
__device__ __forceinline__ uint32_t packh(__half a, __half b) {
    return (uint32_t)__half_as_ushort(a) | ((uint32_t)__half_as_ushort(b) << 16);
}
__device__ __forceinline__ void splith(float x, __half& h, __half& l) {
    h = __float2half_rn(x);
    l = __float2half_rn(x - __half2float(h));
}

// padded smem row: 32 fp16 data + 8 pad = 40 halves = 80 bytes (conflict-free)
#define AROWB 80
#define ATRM  10240            // one term, 128 rows
#define ASTG  20480            // two terms
#define BSTG  10240
// GEMM1 smem: tok[128] @0, A @512, B @512+2*ASTG
#define G1_A  512
#define G1_B  (512 + 2*ASTG)
#define G1_SZ (G1_B + 2*BSTG)
// GEMM2 smem: slot[128] @0, gate[128] @512, A @1024
#define G2_A  1024
#define G2_B  (1024 + 2*ASTG)
#define G2_SZ (G2_B + 2*BSTG)

// ---------------- zero per-iteration accumulators ----------------------------
__global__ void k_zero() {
    int i = blockIdx.x * blockDim.x + threadIdx.x;
    for (int j = i; j < NE*NB; j += gridDim.x * blockDim.x) g_hist[j] = 0;
    if (i < NE) { g_counts[i] = 0; g_cursor[i] = 0; g_bcursor[i] = 0; g_imp[i] = 0.f; }
    if (i == 0) { g_ent = 0.f; g_btotal = 0; }
}

// ---------------- preps ------------------------------------------------------
__global__ void k_prep_ctx(const float* __restrict__ ctx) {
    int i = blockIdx.x * blockDim.x + threadIdx.x;
    if (i >= NTOK * DIMV / 4) return;
    float4 v = ((const float4*)ctx)[i];
    __half h0,l0,h1,l1,h2,l2,h3,l3;
    splith(v.x,h0,l0); splith(v.y,h1,l1); splith(v.z,h2,l2); splith(v.w,h3,l3);
    uint2 ph, pl;
    ph.x = packh(h0,h1); ph.y = packh(h2,h3);
    pl.x = packh(l0,l1); pl.y = packh(l2,l3);
    ((uint2*)g_ctx_hi)[i] = ph;
    ((uint2*)g_ctx_lo)[i] = pl;
}
__global__ void k_prep_w1(const float* __restrict__ W1) {
    int i = blockIdx.x * blockDim.x + threadIdx.x;
    if (i >= NE * DIMV * HID) return;
    int e = i / (DIMV*HID);
    int rem = i - e * (DIMV*HID);
    int d = rem / HID, h = rem - d * HID;
    g_w1t[((size_t)e*HID + h) * DIMV + d] = __float2half_rn(W1[i]);
}
__global__ void k_prep_w2(const float* __restrict__ W2) {
    int i = blockIdx.x * blockDim.x + threadIdx.x;
    if (i >= NE * HID * DIMV) return;
    int e = i / (HID*DIMV);
    int rem = i - e * (HID*DIMV);
    int h = rem / DIMV, d = rem - h * DIMV;
    g_w2t[((size_t)e*DIMV + d) * HID + h] = __float2half_rn(W2[i]);
}

// ---------------- router: one warp per token ---------------------------------
__global__ void k_router(const float* __restrict__ ctx,
                         const float* __restrict__ Wg,
                         const float* __restrict__ bg) {
    __shared__ float sW[NE*DIMV];
    __shared__ float s_imp[NE];
    __shared__ float s_ent;
    int tid = threadIdx.x;
    for (int i = tid; i < NE*DIMV; i += blockDim.x)
        sW[(i & 15) * DIMV + (i >> 4)] = Wg[i];
    if (tid < NE) s_imp[tid] = 0.f;
    if (tid == 0) s_ent = 0.f;
    __syncthreads();

    int warp = tid >> 5, lane = tid & 31;
    int t = blockIdx.x * 8 + warp;
    const float* x = ctx + (size_t)t * DIMV;

    float acc[NE];
#pragma unroll
    for (int e = 0; e < NE; e++) acc[e] = 0.f;
#pragma unroll
    for (int k = 0; k < 8; k++) {
        float xv = x[lane + 32*k];
#pragma unroll
        for (int e = 0; e < NE; e++) acc[e] += xv * sW[e*DIMV + lane + 32*k];
    }
#pragma unroll
    for (int e = 0; e < NE; e++) {
#pragma unroll
        for (int off = 16; off; off >>= 1)
            acc[e] += __shfl_xor_sync(0xffffffffu, acc[e], off);
        acc[e] += bg[e];
    }
    float m = acc[0];
#pragma unroll
    for (int e = 1; e < NE; e++) m = fmaxf(m, acc[e]);
    float sum = 0.f;
#pragma unroll
    for (int e = 0; e < NE; e++) sum += expf(acc[e] - m);

    if (lane < NE) {
        float p = expf(acc[lane] - m) / sum;
        atomicAdd(&s_imp[lane], p);
        float ent = -p * logf(fmaxf(p, 1e-9f));
#pragma unroll
        for (int off = 8; off; off >>= 1)
            ent += __shfl_xor_sync(0xffffu, ent, off);
        if (lane == 0) atomicAdd(&s_ent, ent);
    }

    if (lane == 0) {
        int i0 = 0; float v0 = acc[0];
#pragma unroll
        for (int e = 1; e < NE; e++) if (acc[e] > v0) { v0 = acc[e]; i0 = e; }
        int i1 = (i0 == 0) ? 1 : 0; float v1 = acc[i1];
#pragma unroll
        for (int e = 0; e < NE; e++)
            if (e != i0 && acc[e] > v1) { v1 = acc[e]; i1 = e; }
        float ex = expf(v1 - v0);
        float gg0 = 1.f / (1.f + ex);
        float gg1 = ex / (1.f + ex);
        int s0 = 2*t, s1 = 2*t + 1;
        g_expert[s0] = i0; g_expert[s1] = i1;
        g_gate[s0] = gg0;  g_gate[s1] = gg1;
        atomicAdd(&g_counts[i0], 1);
        atomicAdd(&g_counts[i1], 1);
        atomicAdd(&g_hist[i0*NB + (int)(__float_as_uint(gg0) >> 17)], 1);
        atomicAdd(&g_hist[i1*NB + (int)(__float_as_uint(gg1) >> 17)], 1);
    }
    __syncthreads();
    if (tid < NE) atomicAdd(&g_imp[tid], s_imp[tid]);
    if (tid == 0) atomicAdd(&g_ent, s_ent);
}

// ---------------- exact capacity cutoff per expert ---------------------------
__global__ void k_cutoff() {
    int e = blockIdx.x, tid = threadIdx.x;
    __shared__ int chunk[256], suffix[256];
    if (g_counts[e] <= CAP) {
        if (tid == 0) { g_bstar[e] = -1; g_rrem[e] = 0; g_bcnt[e] = 0; }
        return;
    }
    const int* h = g_hist + e*NB;
    int b0 = tid * 128;
    int s = 0;
    for (int b = b0; b < b0 + 128; b++) s += h[b];
    chunk[tid] = s;
    __syncthreads();
    if (tid == 0) {
        int run = 0;
        for (int i = 255; i >= 0; i--) { suffix[i] = run; run += chunk[i]; }
    }
    __syncthreads();
    int cum = suffix[tid];
    for (int b = b0 + 127; b >= b0; b--) {
        int hb = h[b];
        if (cum < CAP && cum + hb >= CAP) {
            g_bstar[e] = b; g_rrem[e] = CAP - cum; g_bcnt[e] = hb;
        }
        cum += hb;
    }
}

__global__ void k_scan() {
    int base = 0;
    for (int e = 0; e < NE; e++) { g_bbase[e] = base; base += g_bcnt[e]; }
    g_btotal = base;
}

__global__ void k_flags() {
    int s = blockIdx.x * blockDim.x + threadIdx.x;
    if (s >= NSLOT) return;
    int e = g_expert[s];
    unsigned char kept;
    if (g_counts[e] <= CAP) kept = 1;
    else {
        int b  = (int)(__float_as_uint(g_gate[s]) >> 17);
        int bs = g_bstar[e];
        if (b > bs) kept = 1;
        else if (b < bs) kept = 0;
        else {
            kept = 0;
            int p = atomicAdd(&g_bcursor[e], 1);
            g_blist[g_bbase[e] + p] = s;
        }
    }
    g_kept[s] = kept;
}

__global__ void k_boundary() {
    int total = g_btotal;
    for (int i = blockIdx.x * blockDim.x + threadIdx.x; i < total;
         i += gridDim.x * blockDim.x) {
        int si = g_blist[i];
        int e  = g_expert[si];
        int base = g_bbase[e], mm = g_bcnt[e];
        unsigned int ki = __float_as_uint(g_gate[si]);
        int better = 0;
        for (int j = base; j < base + mm; j++) {
            int sj = g_blist[j];
            unsigned int kj = __float_as_uint(g_gate[sj]);
            better += (kj > ki) || (kj == ki && sj < si);
        }
        if (better < g_rrem[e]) g_kept[si] = 1;
    }
}

__global__ void k_compact() {
    int s = blockIdx.x * blockDim.x + threadIdx.x;
    if (s >= NSLOT) return;
    if (g_kept[s]) {
        int e = g_expert[s];
        int p = atomicAdd(&g_cursor[e], 1);
        g_perm[e*CAP + p] = s;
    }
}

// ---------------- GEMM1 (HMMA): H = relu(Xg @ W1 + b1) -----------------------
__global__ void __launch_bounds__(256, 1)
k_gemm1_mma(const float* __restrict__ b1) {
    int e = blockIdx.z;
    int Me = min(g_counts[e], CAP);
    int m0 = blockIdx.x * 128;
    if (m0 >= Me) return;
    int n0 = blockIdx.y * 128;

    extern __shared__ __align__(16) char smem[];
    uint32_t sb = smem_u32(smem);
    int tid = threadIdx.x;
    int* stok = (int*)smem;
    if (tid < 128) {
        int gr = m0 + tid;
        stok[tid] = (gr < Me) ? (g_perm[e*CAP + gr] >> 1) : -1;
    }
    __syncthreads();

    const __half* W = g_w1t + (size_t)e * HID * DIMV;

    auto fill = [&](int stage, int c) {
#pragma unroll
        for (int i = 0; i < 4; i++) {
            int j = tid + i*256;
            int term = j >> 9, rem = j & 511;
            int row = rem >> 2, ch = rem & 3;
            int tok = stok[row];
            const __half* src = (term ? g_ctx_lo : g_ctx_hi)
                                + (size_t)max(tok, 0)*DIMV + c*32 + ch*8;
            cpasync16(sb + G1_A + stage*ASTG + term*ATRM + row*AROWB + ch*16,
                      src, tok >= 0 ? 16 : 0);
        }
#pragma unroll
        for (int i = 0; i < 2; i++) {
            int j = tid + i*256;
            int row = j >> 2, ch = j & 3;
            cpasync16(sb + G1_B + stage*BSTG + row*AROWB + ch*16,
                      W + (size_t)(n0 + row)*DIMV + c*32 + ch*8, 16);
        }
        CP_COMMIT();
    };

    int warp = tid >> 5, lane = tid & 31;
    int g = lane >> 2, tg = lane & 3;
    int wm = (warp & 3) * 32, wn = (warp >> 2) * 64;

    float acc[2][8][4];
#pragma unroll
    for (int a = 0; a < 2; a++)
#pragma unroll
        for (int b = 0; b < 8; b++)
#pragma unroll
            for (int cc = 0; cc < 4; cc++) acc[a][b][cc] = 0.f;

    fill(0, 0);
    const int NCH = DIMV / 32;  // 8
    for (int c = 0; c < NCH; c++) {
        if (c + 1 < NCH) { fill((c+1)&1, c+1); CP_WAIT1(); }
        else CP_WAIT0();
        __syncthreads();
        uint32_t Ab = sb + G1_A + (c&1)*ASTG;
        uint32_t Bb = sb + G1_B + (c&1)*BSTG;
#pragma unroll
        for (int s = 0; s < 2; s++) {
            uint32_t Bf[8][2];
#pragma unroll
            for (int nf = 0; nf < 8; nf++) {
                uint32_t ad = Bb + (wn + nf*8 + g)*AROWB + s*32 + tg*4;
                Bf[nf][0] = lds32(ad); Bf[nf][1] = lds32(ad + 16);
            }
            uint32_t Ah[2][4], Al[2][4];
#pragma unroll
            for (int mf = 0; mf < 2; mf++) {
                uint32_t ba = Ab + (wm + mf*16 + g)*AROWB + s*32 + tg*4;
                Ah[mf][0] = lds32(ba);        Ah[mf][1] = lds32(ba + 640);
                Ah[mf][2] = lds32(ba + 16);   Ah[mf][3] = lds32(ba + 656);
                Al[mf][0] = lds32(ba + ATRM);       Al[mf][1] = lds32(ba + ATRM + 640);
                Al[mf][2] = lds32(ba + ATRM + 16);  Al[mf][3] = lds32(ba + ATRM + 656);
            }
#pragma unroll
            for (int mf = 0; mf < 2; mf++)
#pragma unroll
                for (int nf = 0; nf < 8; nf++) {
                    mma16816(acc[mf][nf], Ah[mf], Bf[nf]);
                    mma16816(acc[mf][nf], Al[mf], Bf[nf]);
                }
        }
        __syncthreads();
    }

    const float* bias = b1 + (size_t)e * HID;
#pragma unroll
    for (int mf = 0; mf < 2; mf++) {
#pragma unroll
        for (int hv = 0; hv < 2; hv++) {
            int gr = m0 + wm + mf*16 + g + hv*8;
            if (gr >= Me) continue;
            __half* hh = g_h_hi + (size_t)(e*CAP + gr)*HID;
            __half* hl = g_h_lo + (size_t)(e*CAP + gr)*HID;
#pragma unroll
            for (int nf = 0; nf < 8; nf++) {
                int col = n0 + wn + nf*8 + tg*2;
                float2 bb = *(const float2*)(bias + col);
                float v0 = fmaxf(acc[mf][nf][hv*2+0] + bb.x, 0.f);
                float v1 = fmaxf(acc[mf][nf][hv*2+1] + bb.y, 0.f);
                __half h0, l0, h1, l1;
                splith(v0, h0, l0); splith(v1, h1, l1);
                *(uint32_t*)(hh + col) = packh(h0, h1);
                *(uint32_t*)(hl + col) = packh(l0, l1);
            }
        }
    }
}

// ---------------- GEMM2 (HMMA): Y = (H @ W2 + b2)*gate -----------------------
__global__ void __launch_bounds__(256, 1)
k_gemm2_mma(const float* __restrict__ b2) {
    int e = blockIdx.z;
    int Me = min(g_counts[e], CAP);
    int m0 = blockIdx.x * 128;
    if (m0 >= Me) return;
    int n0 = blockIdx.y * 128;

    extern __shared__ __align__(16) char smem[];
    uint32_t sb = smem_u32(smem);
    int tid = threadIdx.x;
    int* sslot = (int*)smem;
    float* sgate = (float*)(smem + 512);
    if (tid < 128) {
        int gr = m0 + tid;
        if (gr < Me) {
            int s = g_perm[e*CAP + gr];
            sslot[tid] = s; sgate[tid] = g_gate[s];
        } else { sslot[tid] = -1; sgate[tid] = 0.f; }
    }
    __syncthreads();

    const __half* W = g_w2t + (size_t)e * DIMV * HID;

    auto fill = [&](int stage, int c) {
#pragma unroll
        for (int i = 0; i < 4; i++) {
            int j = tid + i*256;
            int term = j >> 9, rem = j & 511;
            int row = rem >> 2, ch = rem & 3;
            bool ok = (m0 + row) < Me;
            const __half* src = (term ? g_h_lo : g_h_hi)
                                + (size_t)(e*CAP + m0 + (ok ? row : 0))*HID + c*32 + ch*8;
            cpasync16(sb + G2_A + stage*ASTG + term*ATRM + row*AROWB + ch*16,
                      src, ok ? 16 : 0);
        }
#pragma unroll
        for (int i = 0; i < 2; i++) {
            int j = tid + i*256;
            int row = j >> 2, ch = j & 3;
            cpasync16(sb + G2_B + stage*BSTG + row*AROWB + ch*16,
                      W + (size_t)(n0 + row)*HID + c*32 + ch*8, 16);
        }
        CP_COMMIT();
    };

    int warp = tid >> 5, lane = tid & 31;
    int g = lane >> 2, tg = lane & 3;
    int wm = (warp & 3) * 32, wn = (warp >> 2) * 64;

    float acc[2][8][4];
#pragma unroll
    for (int a = 0; a < 2; a++)
#pragma unroll
        for (int b = 0; b < 8; b++)
#pragma unroll
            for (int cc = 0; cc < 4; cc++) acc[a][b][cc] = 0.f;

    fill(0, 0);
    const int NCH = HID / 32;  // 16
    for (int c = 0; c < NCH; c++) {
        if (c + 1 < NCH) { fill((c+1)&1, c+1); CP_WAIT1(); }
        else CP_WAIT0();
        __syncthreads();
        uint32_t Ab = sb + G2_A + (c&1)*ASTG;
        uint32_t Bb = sb + G2_B + (c&1)*BSTG;
#pragma unroll
        for (int s = 0; s < 2; s++) {
            uint32_t Bf[8][2];
#pragma unroll
            for (int nf = 0; nf < 8; nf++) {
                uint32_t ad = Bb + (wn + nf*8 + g)*AROWB + s*32 + tg*4;
                Bf[nf][0] = lds32(ad); Bf[nf][1] = lds32(ad + 16);
            }
            uint32_t Ah[2][4], Al[2][4];
#pragma unroll
            for (int mf = 0; mf < 2; mf++) {
                uint32_t ba = Ab + (wm + mf*16 + g)*AROWB + s*32 + tg*4;
                Ah[mf][0] = lds32(ba);        Ah[mf][1] = lds32(ba + 640);
                Ah[mf][2] = lds32(ba + 16);   Ah[mf][3] = lds32(ba + 656);
                Al[mf][0] = lds32(ba + ATRM);       Al[mf][1] = lds32(ba + ATRM + 640);
                Al[mf][2] = lds32(ba + ATRM + 16);  Al[mf][3] = lds32(ba + ATRM + 656);
            }
#pragma unroll
            for (int mf = 0; mf < 2; mf++)
#pragma unroll
                for (int nf = 0; nf < 8; nf++) {
                    mma16816(acc[mf][nf], Ah[mf], Bf[nf]);
                    mma16816(acc[mf][nf], Al[mf], Bf[nf]);
                }
        }
        __syncthreads();
    }

    const float* bias = b2 + (size_t)e * DIMV;
#pragma unroll
    for (int mf = 0; mf < 2; mf++) {
#pragma unroll
        for (int hv = 0; hv < 2; hv++) {
            int r = wm + mf*16 + g + hv*8;
            int slot = sslot[r];
            if (slot < 0) continue;
            float gate = sgate[r];
            float* yr = g_y + (size_t)slot * DIMV;
#pragma unroll
            for (int nf = 0; nf < 8; nf++) {
                int col = n0 + wn + nf*8 + tg*2;
                float2 bb = *(const float2*)(bias + col);
                float2 o;
                o.x = (acc[mf][nf][hv*2+0] + bb.x) * gate;
                o.y = (acc[mf][nf][hv*2+1] + bb.y) * gate;
                *(float2*)(yr + col) = o;
            }
        }
    }
}

// ---------------- combine ----------------------------------------------------
__global__ void k_combine(float* __restrict__ out) {
    int idx = blockIdx.x * blockDim.x + threadIdx.x;
    if (idx >= NTOK * 64) return;
    int t = idx >> 6, f = idx & 63;
    const float4* y4 = (const float4*)g_y;
    float4 r = make_float4(0.f, 0.f, 0.f, 0.f);
    if (g_kept[2*t]) {
        float4 a = y4[(size_t)(2*t)*64 + f];
        r.x += a.x; r.y += a.y; r.z += a.z; r.w += a.w;
    }
    if (g_kept[2*t + 1]) {
        float4 a = y4[(size_t)(2*t + 1)*64 + f];
        r.x += a.x; r.y += a.y; r.z += a.z; r.w += a.w;
    }
    ((float4*)out)[(size_t)t*64 + f] = r;
}

// ---------------- finalize ---------------------------------------------------
__global__ void k_final(float* __restrict__ out, int out_size) {
    int lane = threadIdx.x;
    int c = (lane < NE) ? min(g_counts[lane], CAP) : 0;
    int tot = c;
#pragma unroll
    for (int off = 16; off; off >>= 1) tot += __shfl_xor_sync(0xffffffffu, tot, off);
    float denom = fmaxf((float)tot, 1.f);
    float aux = 0.f;
    if (lane < NE)
        aux = (g_imp[lane] / (float)NTOK) * ((float)c / denom) * (float)NE;
#pragma unroll
    for (int off = 16; off; off >>= 1) aux += __shfl_xor_sync(0xffffffffu, aux, off);
    int base = NTOK * DIMV;
    if (lane == 0 && out_size > base)     out[base]     = aux;
    if (lane == 0 && out_size > base + 1) out[base + 1] = g_ent / (float)NTOK;
    if (lane < NE && out_size > base + 2 + lane) out[base + 2 + lane] = (float)c;
}

// ---------------- launch -----------------------------------------------------
extern "C" void kernel_launch(void* const* d_in, const int* in_sizes, int n_in,
                              void* d_out, int out_size) {
    const float* ctx = (const float*)d_in[0];
    const float* Wg  = (const float*)d_in[1];
    const float* bg  = (const float*)d_in[2];
    const float* W1  = (const float*)d_in[3];
    const float* b1  = (const float*)d_in[4];
    const float* W2  = (const float*)d_in[5];
    const float* b2  = (const float*)d_in[6];
    float* out = (float*)d_out;

    static bool attr_done = false;
    if (!attr_done) {
        cudaFuncSetAttribute(k_gemm1_mma, cudaFuncAttributeMaxDynamicSharedMemorySize, G1_SZ);
        cudaFuncSetAttribute(k_gemm2_mma, cudaFuncAttributeMaxDynamicSharedMemorySize, G2_SZ);
        attr_done = true;
    }

    k_zero<<<512, 256>>>();
    k_prep_ctx<<<(NTOK*DIMV/4 + 255)/256, 256>>>(ctx);
    k_prep_w1<<<(NE*DIMV*HID + 255)/256, 256>>>(W1);
    k_prep_w2<<<(NE*HID*DIMV + 255)/256, 256>>>(W2);
    k_router<<<NTOK/8, 256>>>(ctx, Wg, bg);
    k_cutoff<<<NE, 256>>>();
    k_scan<<<1, 1>>>();
    k_flags<<<NSLOT/256, 256>>>();
    k_boundary<<<256, 256>>>();
    k_compact<<<NSLOT/256, 256>>>();

    dim3 g1(MTILES, HID/128, NE);
    k_gemm1_mma<<<g1, 256, G1_SZ>>>(b1);
    dim3 g2(MTILES, DIMV/128, NE);
    k_gemm2_mma<<<g2, 256, G2_SZ>>>(b2);

    k_combine<<<(NTOK*64)/256, 256>>>(out);
    k_final<<<1, 32>>>(out, out_size);
}

// round 4
// speedup vs baseline: 3.1573x; 1.5859x over previous
#include <cuda_runtime.h>
#include <cuda_fp16.h>
#include <math.h>
#include <stdint.h>

#define NTOK  131072
#define DIMV  256
#define HID   512
#define NE    16
#define CAP   18023
#define NSLOT (NTOK*2)
#define ECAP  (NE*CAP)
#define NB    32768
#define MTILES ((CAP+127)/128)

// ---------------- scratch (static device globals) ----------------------------
__device__ float g_gate[NSLOT];
__device__ int   g_expert[NSLOT];
__device__ unsigned char g_kept[NSLOT];
__device__ int   g_counts[NE];
__device__ int   g_cursor[NE];
__device__ int   g_perm[ECAP];
__device__ int   g_hist[NE*NB];
__device__ int   g_bstar[NE], g_rrem[NE];
__device__ int   g_blist[NSLOT];
__device__ int   g_btotal;
__device__ float g_imp[NE];
__device__ float g_ent;

// fp16 operands (single precision pass)
__device__ __half g_ctx_h[(size_t)NTOK * DIMV];
__device__ __half g_w1t[(size_t)NE * HID * DIMV];   // [e][h][d]
__device__ __half g_w2t[(size_t)NE * DIMV * HID];   // [e][d][h]
__device__ __half g_hh[(size_t)ECAP * HID];
__device__ float  g_y[(size_t)NSLOT * DIMV];

// ---------------- helpers ----------------------------------------------------
__device__ __forceinline__ uint32_t smem_u32(const void* p) {
    uint32_t a;
    asm("{ .reg .u64 t; cvta.to.shared.u64 t, %1; cvt.u32.u64 %0, t; }"
        : "=r"(a) : "l"(p));
    return a;
}
__device__ __forceinline__ uint32_t lds32(uint32_t addr) {
    uint32_t v; asm volatile("ld.shared.b32 %0, [%1];" : "=r"(v) : "r"(addr));
    return v;
}
__device__ __forceinline__ void cpasync16(uint32_t dst, const void* src, int srcsz) {
    asm volatile("cp.async.cg.shared.global [%0], [%1], 16, %2;"
                 :: "r"(dst), "l"(src), "r"(srcsz) : "memory");
}
#define CP_COMMIT() asm volatile("cp.async.commit_group;" ::: "memory")
#define CP_WAIT1()  asm volatile("cp.async.wait_group 1;" ::: "memory")
#define CP_WAIT0()  asm volatile("cp.async.wait_group 0;" ::: "memory")

__device__ __forceinline__ void mma16816(float* c, const uint32_t* a, const uint32_t* b) {
    asm volatile(
        "mma.sync.aligned.m16n8k16.row.col.f32.f16.f16.f32 "
        "{%0,%1,%2,%3}, {%4,%5,%6,%7}, {%8,%9}, {%0,%1,%2,%3};"
        : "+f"(c[0]), "+f"(c[1]), "+f"(c[2]), "+f"(c[3])
        : "r"(a[0]), "r"(a[1]), "r"(a[2]), "r"(a[3]), "r"(b[0]), "r"(b[1]));
}
__device__ __forceinline__ uint32_t packh(__half a, __half b) {
    return (uint32_t)__half_as_ushort(a) | ((uint32_t)__half_as_ushort(b) << 16);
}

// padded smem row: 32 fp16 data + 8 pad = 40 halves = 80 bytes (conflict-free)
#define AROWB 80
#define STG   10240            // 128 rows * 80B, one stage
// GEMM1 smem: tok[128] @0, A @512 (2 stages), B after
#define G1_A  512
#define G1_B  (G1_A + 2*STG)
#define G1_SZ (G1_B + 2*STG)
// GEMM2 smem: slot[128] @0, gate[128] @512, A @1024
#define G2_A  1024
#define G2_B  (G2_A + 2*STG)
#define G2_SZ (G2_B + 2*STG)

// ---------------- zero per-iteration accumulators ----------------------------
__global__ void k_zero() {
    int i = blockIdx.x * blockDim.x + threadIdx.x;
    for (int j = i; j < NE*NB; j += gridDim.x * blockDim.x) g_hist[j] = 0;
    if (i < NE) { g_counts[i] = 0; g_cursor[i] = 0; g_imp[i] = 0.f; }
    if (i == 0) { g_ent = 0.f; g_btotal = 0; }
}

// ---------------- weight preps -----------------------------------------------
__global__ void k_prep_w1(const float* __restrict__ W1) {
    int i = blockIdx.x * blockDim.x + threadIdx.x;
    if (i >= NE * DIMV * HID) return;
    int e = i / (DIMV*HID);
    int rem = i - e * (DIMV*HID);
    int d = rem / HID, h = rem - d * HID;
    g_w1t[((size_t)e*HID + h) * DIMV + d] = __float2half_rn(W1[i]);
}
__global__ void k_prep_w2(const float* __restrict__ W2) {
    int i = blockIdx.x * blockDim.x + threadIdx.x;
    if (i >= NE * HID * DIMV) return;
    int e = i / (HID*DIMV);
    int rem = i - e * (HID*DIMV);
    int h = rem / DIMV, d = rem - h * DIMV;
    g_w2t[((size_t)e*DIMV + d) * HID + h] = __float2half_rn(W2[i]);
}

// ---------------- router: one warp per token (+ fused ctx->fp16 prep) --------
__global__ void k_router(const float* __restrict__ ctx,
                         const float* __restrict__ Wg,
                         const float* __restrict__ bg) {
    __shared__ float sW[NE*DIMV];
    __shared__ float s_imp[NE];
    __shared__ float s_ent;
    int tid = threadIdx.x;
    for (int i = tid; i < NE*DIMV; i += blockDim.x)
        sW[(i & 15) * DIMV + (i >> 4)] = Wg[i];
    if (tid < NE) s_imp[tid] = 0.f;
    if (tid == 0) s_ent = 0.f;
    __syncthreads();

    int warp = tid >> 5, lane = tid & 31;
    int t = blockIdx.x * 8 + warp;
    const float* x = ctx + (size_t)t * DIMV;

    float acc[NE];
#pragma unroll
    for (int e = 0; e < NE; e++) acc[e] = 0.f;
#pragma unroll
    for (int k = 0; k < 8; k++) {
        float xv = x[lane + 32*k];
#pragma unroll
        for (int e = 0; e < NE; e++) acc[e] += xv * sW[e*DIMV + lane + 32*k];
    }
#pragma unroll
    for (int e = 0; e < NE; e++) {
#pragma unroll
        for (int off = 16; off; off >>= 1)
            acc[e] += __shfl_xor_sync(0xffffffffu, acc[e], off);
        acc[e] += bg[e];
    }
    float m = acc[0];
#pragma unroll
    for (int e = 1; e < NE; e++) m = fmaxf(m, acc[e]);
    float sum = 0.f;
#pragma unroll
    for (int e = 0; e < NE; e++) sum += expf(acc[e] - m);

    if (lane < NE) {
        float p = expf(acc[lane] - m) / sum;
        atomicAdd(&s_imp[lane], p);
        float ent = -p * logf(fmaxf(p, 1e-9f));
#pragma unroll
        for (int off = 8; off; off >>= 1)
            ent += __shfl_xor_sync(0xffffu, ent, off);
        if (lane == 0) atomicAdd(&s_ent, ent);
    }

    if (lane == 0) {
        int i0 = 0; float v0 = acc[0];
#pragma unroll
        for (int e = 1; e < NE; e++) if (acc[e] > v0) { v0 = acc[e]; i0 = e; }
        int i1 = (i0 == 0) ? 1 : 0; float v1 = acc[i1];
#pragma unroll
        for (int e = 0; e < NE; e++)
            if (e != i0 && acc[e] > v1) { v1 = acc[e]; i1 = e; }
        float ex = expf(v1 - v0);
        float gg0 = 1.f / (1.f + ex);
        float gg1 = ex / (1.f + ex);
        int s0 = 2*t, s1 = 2*t + 1;
        g_expert[s0] = i0; g_expert[s1] = i1;
        g_gate[s0] = gg0;  g_gate[s1] = gg1;
        atomicAdd(&g_counts[i0], 1);
        atomicAdd(&g_counts[i1], 1);
        atomicAdd(&g_hist[i0*NB + (int)(__float_as_uint(gg0) >> 17)], 1);
        atomicAdd(&g_hist[i1*NB + (int)(__float_as_uint(gg1) >> 17)], 1);
    }
    __syncthreads();
    if (tid < NE) atomicAdd(&g_imp[tid], s_imp[tid]);
    if (tid == 0) atomicAdd(&g_ent, s_ent);

    // fused fp16 conversion of this block's 8 tokens (ctx is L2-hot here)
    {
        const float4* src = (const float4*)(ctx + (size_t)blockIdx.x * 8 * DIMV);
        uint2* dst = (uint2*)(g_ctx_h + (size_t)blockIdx.x * 8 * DIMV);
#pragma unroll
        for (int i = 0; i < 2; i++) {
            int j = tid + i*256;
            float4 v = src[j];
            uint2 p;
            p.x = packh(__float2half_rn(v.x), __float2half_rn(v.y));
            p.y = packh(__float2half_rn(v.z), __float2half_rn(v.w));
            dst[j] = p;
        }
    }
}

// ---------------- exact capacity cutoff per expert ---------------------------
__global__ void k_cutoff() {
    int e = blockIdx.x, tid = threadIdx.x;
    __shared__ int chunk[256], suffix[256];
    if (g_counts[e] <= CAP) {
        if (tid == 0) { g_bstar[e] = -1; g_rrem[e] = 0; }
        return;
    }
    const int* h = g_hist + e*NB;
    int b0 = tid * 128;
    int s = 0;
    for (int b = b0; b < b0 + 128; b++) s += h[b];
    chunk[tid] = s;
    __syncthreads();
    if (tid == 0) {
        int run = 0;
        for (int i = 255; i >= 0; i--) { suffix[i] = run; run += chunk[i]; }
    }
    __syncthreads();
    int cum = suffix[tid];
    for (int b = b0 + 127; b >= b0; b--) {
        int hb = h[b];
        if (cum < CAP && cum + hb >= CAP) {
            g_bstar[e] = b; g_rrem[e] = CAP - cum;
        }
        cum += hb;
    }
}

__global__ void k_flags() {
    int s = blockIdx.x * blockDim.x + threadIdx.x;
    if (s >= NSLOT) return;
    int e = g_expert[s];
    unsigned char kept;
    if (g_counts[e] <= CAP) kept = 1;
    else {
        int b  = (int)(__float_as_uint(g_gate[s]) >> 17);
        int bs = g_bstar[e];
        if (b > bs) kept = 1;
        else if (b < bs) kept = 0;
        else {
            kept = 0;
            int p = atomicAdd(&g_btotal, 1);
            g_blist[p] = s;
        }
    }
    g_kept[s] = kept;
}

// exact stable rank within the boundary bucket (pooled; filter by expert)
__global__ void k_boundary() {
    int total = g_btotal;
    for (int i = blockIdx.x * blockDim.x + threadIdx.x; i < total;
         i += gridDim.x * blockDim.x) {
        int si = g_blist[i];
        int e  = g_expert[si];
        unsigned int ki = __float_as_uint(g_gate[si]);
        int better = 0;
        for (int j = 0; j < total; j++) {
            int sj = g_blist[j];
            if (g_expert[sj] != e) continue;
            unsigned int kj = __float_as_uint(g_gate[sj]);
            better += (kj > ki) || (kj == ki && sj < si);
        }
        if (better < g_rrem[e]) g_kept[si] = 1;
    }
}

__global__ void k_compact() {
    int s = blockIdx.x * blockDim.x + threadIdx.x;
    if (s >= NSLOT) return;
    if (g_kept[s]) {
        int e = g_expert[s];
        int p = atomicAdd(&g_cursor[e], 1);
        g_perm[e*CAP + p] = s;
    }
}

// ---------------- GEMM1 (HMMA): H = relu(Xg @ W1 + b1) -----------------------
__global__ void __launch_bounds__(256, 2)
k_gemm1_mma(const float* __restrict__ b1) {
    int e = blockIdx.z;
    int Me = min(g_counts[e], CAP);
    int m0 = blockIdx.x * 128;
    if (m0 >= Me) return;
    int n0 = blockIdx.y * 128;

    extern __shared__ __align__(16) char smem[];
    uint32_t sb = smem_u32(smem);
    int tid = threadIdx.x;
    int* stok = (int*)smem;
    if (tid < 128) {
        int gr = m0 + tid;
        stok[tid] = (gr < Me) ? (g_perm[e*CAP + gr] >> 1) : -1;
    }
    __syncthreads();

    const __half* W = g_w1t + (size_t)e * HID * DIMV;

    auto fill = [&](int stage, int c) {
#pragma unroll
        for (int i = 0; i < 2; i++) {
            int j = tid + i*256;
            int row = j >> 2, ch = j & 3;
            int tok = stok[row];
            cpasync16(sb + G1_A + stage*STG + row*AROWB + ch*16,
                      g_ctx_h + (size_t)max(tok, 0)*DIMV + c*32 + ch*8,
                      tok >= 0 ? 16 : 0);
        }
#pragma unroll
        for (int i = 0; i < 2; i++) {
            int j = tid + i*256;
            int row = j >> 2, ch = j & 3;
            cpasync16(sb + G1_B + stage*STG + row*AROWB + ch*16,
                      W + (size_t)(n0 + row)*DIMV + c*32 + ch*8, 16);
        }
        CP_COMMIT();
    };

    int warp = tid >> 5, lane = tid & 31;
    int g = lane >> 2, tg = lane & 3;
    int wm = (warp & 3) * 32, wn = (warp >> 2) * 64;

    float acc[2][8][4];
#pragma unroll
    for (int a = 0; a < 2; a++)
#pragma unroll
        for (int b = 0; b < 8; b++)
#pragma unroll
            for (int cc = 0; cc < 4; cc++) acc[a][b][cc] = 0.f;

    fill(0, 0);
    const int NCH = DIMV / 32;  // 8
    for (int c = 0; c < NCH; c++) {
        if (c + 1 < NCH) { fill((c+1)&1, c+1); CP_WAIT1(); }
        else CP_WAIT0();
        __syncthreads();
        uint32_t Ab = sb + G1_A + (c&1)*STG;
        uint32_t Bb = sb + G1_B + (c&1)*STG;
#pragma unroll
        for (int s = 0; s < 2; s++) {
            uint32_t Bf[8][2];
#pragma unroll
            for (int nf = 0; nf < 8; nf++) {
                uint32_t ad = Bb + (wn + nf*8 + g)*AROWB + s*32 + tg*4;
                Bf[nf][0] = lds32(ad); Bf[nf][1] = lds32(ad + 16);
            }
            uint32_t Af[2][4];
#pragma unroll
            for (int mf = 0; mf < 2; mf++) {
                uint32_t ba = Ab + (wm + mf*16 + g)*AROWB + s*32 + tg*4;
                Af[mf][0] = lds32(ba);       Af[mf][1] = lds32(ba + 640);
                Af[mf][2] = lds32(ba + 16);  Af[mf][3] = lds32(ba + 656);
            }
#pragma unroll
            for (int mf = 0; mf < 2; mf++)
#pragma unroll
                for (int nf = 0; nf < 8; nf++)
                    mma16816(acc[mf][nf], Af[mf], Bf[nf]);
        }
        __syncthreads();
    }

    const float* bias = b1 + (size_t)e * HID;
#pragma unroll
    for (int mf = 0; mf < 2; mf++) {
#pragma unroll
        for (int hv = 0; hv < 2; hv++) {
            int gr = m0 + wm + mf*16 + g + hv*8;
            if (gr >= Me) continue;
            __half* hh = g_hh + (size_t)(e*CAP + gr)*HID;
#pragma unroll
            for (int nf = 0; nf < 8; nf++) {
                int col = n0 + wn + nf*8 + tg*2;
                float2 bb = *(const float2*)(bias + col);
                float v0 = fmaxf(acc[mf][nf][hv*2+0] + bb.x, 0.f);
                float v1 = fmaxf(acc[mf][nf][hv*2+1] + bb.y, 0.f);
                *(uint32_t*)(hh + col) = packh(__float2half_rn(v0), __float2half_rn(v1));
            }
        }
    }
}

// ---------------- GEMM2 (HMMA): Y = (H @ W2 + b2)*gate -----------------------
__global__ void __launch_bounds__(256, 2)
k_gemm2_mma(const float* __restrict__ b2) {
    int e = blockIdx.z;
    int Me = min(g_counts[e], CAP);
    int m0 = blockIdx.x * 128;
    if (m0 >= Me) return;
    int n0 = blockIdx.y * 128;

    extern __shared__ __align__(16) char smem[];
    uint32_t sb = smem_u32(smem);
    int tid = threadIdx.x;
    int* sslot = (int*)smem;
    float* sgate = (float*)(smem + 512);
    if (tid < 128) {
        int gr = m0 + tid;
        if (gr < Me) {
            int s = g_perm[e*CAP + gr];
            sslot[tid] = s; sgate[tid] = g_gate[s];
        } else { sslot[tid] = -1; sgate[tid] = 0.f; }
    }
    __syncthreads();

    const __half* W = g_w2t + (size_t)e * DIMV * HID;

    auto fill = [&](int stage, int c) {
#pragma unroll
        for (int i = 0; i < 2; i++) {
            int j = tid + i*256;
            int row = j >> 2, ch = j & 3;
            bool ok = (m0 + row) < Me;
            cpasync16(sb + G2_A + stage*STG + row*AROWB + ch*16,
                      g_hh + (size_t)(e*CAP + m0 + (ok ? row : 0))*HID + c*32 + ch*8,
                      ok ? 16 : 0);
        }
#pragma unroll
        for (int i = 0; i < 2; i++) {
            int j = tid + i*256;
            int row = j >> 2, ch = j & 3;
            cpasync16(sb + G2_B + stage*STG + row*AROWB + ch*16,
                      W + (size_t)(n0 + row)*HID + c*32 + ch*8, 16);
        }
        CP_COMMIT();
    };

    int warp = tid >> 5, lane = tid & 31;
    int g = lane >> 2, tg = lane & 3;
    int wm = (warp & 3) * 32, wn = (warp >> 2) * 64;

    float acc[2][8][4];
#pragma unroll
    for (int a = 0; a < 2; a++)
#pragma unroll
        for (int b = 0; b < 8; b++)
#pragma unroll
            for (int cc = 0; cc < 4; cc++) acc[a][b][cc] = 0.f;

    fill(0, 0);
    const int NCH = HID / 32;  // 16
    for (int c = 0; c < NCH; c++) {
        if (c + 1 < NCH) { fill((c+1)&1, c+1); CP_WAIT1(); }
        else CP_WAIT0();
        __syncthreads();
        uint32_t Ab = sb + G2_A + (c&1)*STG;
        uint32_t Bb = sb + G2_B + (c&1)*STG;
#pragma unroll
        for (int s = 0; s < 2; s++) {
            uint32_t Bf[8][2];
#pragma unroll
            for (int nf = 0; nf < 8; nf++) {
                uint32_t ad = Bb + (wn + nf*8 + g)*AROWB + s*32 + tg*4;
                Bf[nf][0] = lds32(ad); Bf[nf][1] = lds32(ad + 16);
            }
            uint32_t Af[2][4];
#pragma unroll
            for (int mf = 0; mf < 2; mf++) {
                uint32_t ba = Ab + (wm + mf*16 + g)*AROWB + s*32 + tg*4;
                Af[mf][0] = lds32(ba);       Af[mf][1] = lds32(ba + 640);
                Af[mf][2] = lds32(ba + 16);  Af[mf][3] = lds32(ba + 656);
            }
#pragma unroll
            for (int mf = 0; mf < 2; mf++)
#pragma unroll
                for (int nf = 0; nf < 8; nf++)
                    mma16816(acc[mf][nf], Af[mf], Bf[nf]);
        }
        __syncthreads();
    }

    const float* bias = b2 + (size_t)e * DIMV;
#pragma unroll
    for (int mf = 0; mf < 2; mf++) {
#pragma unroll
        for (int hv = 0; hv < 2; hv++) {
            int r = wm + mf*16 + g + hv*8;
            int slot = sslot[r];
            if (slot < 0) continue;
            float gate = sgate[r];
            float* yr = g_y + (size_t)slot * DIMV;
#pragma unroll
            for (int nf = 0; nf < 8; nf++) {
                int col = n0 + wn + nf*8 + tg*2;
                float2 bb = *(const float2*)(bias + col);
                float2 o;
                o.x = (acc[mf][nf][hv*2+0] + bb.x) * gate;
                o.y = (acc[mf][nf][hv*2+1] + bb.y) * gate;
                *(float2*)(yr + col) = o;
            }
        }
    }
}

// ---------------- combine ----------------------------------------------------
__global__ void k_combine(float* __restrict__ out) {
    int idx = blockIdx.x * blockDim.x + threadIdx.x;
    if (idx >= NTOK * 64) return;
    int t = idx >> 6, f = idx & 63;
    const float4* y4 = (const float4*)g_y;
    float4 r = make_float4(0.f, 0.f, 0.f, 0.f);
    if (g_kept[2*t]) {
        float4 a = y4[(size_t)(2*t)*64 + f];
        r.x += a.x; r.y += a.y; r.z += a.z; r.w += a.w;
    }
    if (g_kept[2*t + 1]) {
        float4 a = y4[(size_t)(2*t + 1)*64 + f];
        r.x += a.x; r.y += a.y; r.z += a.z; r.w += a.w;
    }
    ((float4*)out)[(size_t)t*64 + f] = r;
}

// ---------------- finalize ---------------------------------------------------
__global__ void k_final(float* __restrict__ out, int out_size) {
    int lane = threadIdx.x;
    int c = (lane < NE) ? min(g_counts[lane], CAP) : 0;
    int tot = c;
#pragma unroll
    for (int off = 16; off; off >>= 1) tot += __shfl_xor_sync(0xffffffffu, tot, off);
    float denom = fmaxf((float)tot, 1.f);
    float aux = 0.f;
    if (lane < NE)
        aux = (g_imp[lane] / (float)NTOK) * ((float)c / denom) * (float)NE;
#pragma unroll
    for (int off = 16; off; off >>= 1) aux += __shfl_xor_sync(0xffffffffu, aux, off);
    int base = NTOK * DIMV;
    if (lane == 0 && out_size > base)     out[base]     = aux;
    if (lane == 0 && out_size > base + 1) out[base + 1] = g_ent / (float)NTOK;
    if (lane < NE && out_size > base + 2 + lane) out[base + 2 + lane] = (float)c;
}

// ---------------- launch -----------------------------------------------------
extern "C" void kernel_launch(void* const* d_in, const int* in_sizes, int n_in,
                              void* d_out, int out_size) {
    const float* ctx = (const float*)d_in[0];
    const float* Wg  = (const float*)d_in[1];
    const float* bg  = (const float*)d_in[2];
    const float* W1  = (const float*)d_in[3];
    const float* b1  = (const float*)d_in[4];
    const float* W2  = (const float*)d_in[5];
    const float* b2  = (const float*)d_in[6];
    float* out = (float*)d_out;

    static bool attr_done = false;
    if (!attr_done) {
        cudaFuncSetAttribute(k_gemm1_mma, cudaFuncAttributeMaxDynamicSharedMemorySize, G1_SZ);
        cudaFuncSetAttribute(k_gemm2_mma, cudaFuncAttributeMaxDynamicSharedMemorySize, G2_SZ);
        attr_done = true;
    }

    k_zero<<<512, 256>>>();
    k_router<<<NTOK/8, 256>>>(ctx, Wg, bg);
    k_cutoff<<<NE, 256>>>();
    k_flags<<<NSLOT/256, 256>>>();
    k_boundary<<<64, 256>>>();
    k_compact<<<NSLOT/256, 256>>>();
    k_prep_w1<<<(NE*DIMV*HID + 255)/256, 256>>>(W1);
    k_prep_w2<<<(NE*HID*DIMV + 255)/256, 256>>>(W2);

    dim3 g1(MTILES, HID/128, NE);
    k_gemm1_mma<<<g1, 256, G1_SZ>>>(b1);
    dim3 g2(MTILES, DIMV/128, NE);
    k_gemm2_mma<<<g2, 256, G2_SZ>>>(b2);

    k_combine<<<(NTOK*64)/256, 256>>>(out);
    k_final<<<1, 32>>>(out, out_size);
}

// round 6
// speedup vs baseline: 3.3442x; 1.0592x over previous
#include <cuda_runtime.h>
#include <cuda_fp16.h>
#include <math.h>
#include <stdint.h>

#define NTOK  131072
#define DIMV  256
#define HID   512
#define NE    16
#define CAP   18023
#define NSLOT (NTOK*2)
#define ECAP  (NE*CAP)
#define NB    32768
#define MTILES ((CAP+127)/128)

// ---------------- scratch (static device globals) ----------------------------
__device__ float g_gate[NSLOT];
__device__ int   g_expert[NSLOT];
__device__ unsigned char g_kept[NSLOT];
__device__ int   g_counts[NE];
__device__ int   g_cursor[NE];
__device__ int   g_perm[ECAP];
__device__ int   g_hist[NE*NB];
__device__ int   g_bstar[NE], g_rrem[NE];
__device__ int   g_blist[NSLOT];
__device__ int   g_btotal;
__device__ float g_imp[NE];
__device__ float g_ent;

__device__ __half g_ctx_h[(size_t)NTOK * DIMV];
__device__ __half g_w1t[(size_t)NE * HID * DIMV];   // [e][h][d]
__device__ __half g_w2t[(size_t)NE * DIMV * HID];   // [e][d][h]
__device__ __half g_hh[(size_t)ECAP * HID];
__device__ __half g_y[(size_t)NSLOT * DIMV];

// ---------------- helpers ----------------------------------------------------
__device__ __forceinline__ uint32_t smem_u32(const void* p) {
    uint32_t a;
    asm("{ .reg .u64 t; cvta.to.shared.u64 t, %1; cvt.u32.u64 %0, t; }"
        : "=r"(a) : "l"(p));
    return a;
}
__device__ __forceinline__ void cpasync16(uint32_t dst, const void* src, int srcsz) {
    asm volatile("cp.async.cg.shared.global [%0], [%1], 16, %2;"
                 :: "r"(dst), "l"(src), "r"(srcsz) : "memory");
}
#define CP_COMMIT() asm volatile("cp.async.commit_group;" ::: "memory")
#define CP_WAIT1()  asm volatile("cp.async.wait_group 1;" ::: "memory")
#define CP_WAIT0()  asm volatile("cp.async.wait_group 0;" ::: "memory")

__device__ __forceinline__ void ldsm4(uint32_t* r, uint32_t addr) {
    asm volatile("ldmatrix.sync.aligned.m8n8.x4.shared.b16 {%0,%1,%2,%3}, [%4];"
                 : "=r"(r[0]), "=r"(r[1]), "=r"(r[2]), "=r"(r[3]) : "r"(addr));
}
__device__ __forceinline__ void mma16816(float* c, const uint32_t* a, const uint32_t* b) {
    asm volatile(
        "mma.sync.aligned.m16n8k16.row.col.f32.f16.f16.f32 "
        "{%0,%1,%2,%3}, {%4,%5,%6,%7}, {%8,%9}, {%0,%1,%2,%3};"
        : "+f"(c[0]), "+f"(c[1]), "+f"(c[2]), "+f"(c[3])
        : "r"(a[0]), "r"(a[1]), "r"(a[2]), "r"(a[3]), "r"(b[0]), "r"(b[1]));
}
__device__ __forceinline__ uint32_t packh(__half a, __half b) {
    return (uint32_t)__half_as_ushort(a) | ((uint32_t)__half_as_ushort(b) << 16);
}

// padded smem row: 32 fp16 + 8 pad = 80 bytes (conflict-free for LDSM/cp.async)
#define AROWB 80
#define ASTG  10240            // 128 rows
#define BSTG  20480            // 256 rows
// GEMM1: tok[128] @0, A @512 (2 stages), B after
#define G1_A  512
#define G1_B  (G1_A + 2*ASTG)
#define G1_SZ (G1_B + 2*BSTG)
// GEMM2: slot[128] @0, gate[128] @512, A @1024
#define G2_A  1024
#define G2_B  (G2_A + 2*ASTG)
#define G2_SZ (G2_B + 2*BSTG)

// ---------------- zero -------------------------------------------------------
__global__ void k_zero() {
    int i = blockIdx.x * blockDim.x + threadIdx.x;
    for (int j = i; j < NE*NB; j += gridDim.x * blockDim.x) g_hist[j] = 0;
    if (i < NE) { g_counts[i] = 0; g_cursor[i] = 0; g_imp[i] = 0.f; }
    if (i == 0) { g_ent = 0.f; g_btotal = 0; }
}

// ---------------- coalesced transpose + fp16 convert -------------------------
// which=0: dst=g_w1t (R=DIMV,C=HID); which=1: dst=g_w2t (R=HID,C=DIMV)
// dst[e][c][r] = (half)src[e][r][c]; grid (C/32, R/32, NE), 256 threads
__global__ void k_transpose(const float* __restrict__ src, int which, int R, int C) {
    __shared__ float tile[32][33];
    __half* dstg = which ? g_w2t : g_w1t;      // device-side symbol reference
    int e = blockIdx.z;
    const float* S = src + (size_t)e * R * C;
    __half* D = dstg + (size_t)e * R * C;
    int c0 = blockIdx.x * 32, r0 = blockIdx.y * 32;
    int tc = threadIdx.x & 31, tr4 = threadIdx.x >> 5;
#pragma unroll
    for (int i = 0; i < 4; i++) {
        int r = tr4 + i*8;
        tile[r][tc] = S[(size_t)(r0 + r)*C + c0 + tc];
    }
    __syncthreads();
#pragma unroll
    for (int i = 0; i < 4; i++) {
        int r = tr4 + i*8;
        D[(size_t)(c0 + r)*R + r0 + tc] = __float2half_rn(tile[tc][r]);
    }
}

// ---------------- router (+ fused ctx->fp16) ---------------------------------
__global__ void k_router(const float* __restrict__ ctx,
                         const float* __restrict__ Wg,
                         const float* __restrict__ bg) {
    __shared__ float sW[NE*DIMV];
    __shared__ float s_imp[NE];
    __shared__ float s_ent;
    int tid = threadIdx.x;
    for (int i = tid; i < NE*DIMV; i += blockDim.x)
        sW[(i & 15) * DIMV + (i >> 4)] = Wg[i];
    if (tid < NE) s_imp[tid] = 0.f;
    if (tid == 0) s_ent = 0.f;
    __syncthreads();

    int warp = tid >> 5, lane = tid & 31;
    int t = blockIdx.x * 8 + warp;
    const float* x = ctx + (size_t)t * DIMV;

    float acc[NE];
#pragma unroll
    for (int e = 0; e < NE; e++) acc[e] = 0.f;
#pragma unroll
    for (int k = 0; k < 8; k++) {
        float xv = x[lane + 32*k];
#pragma unroll
        for (int e = 0; e < NE; e++) acc[e] += xv * sW[e*DIMV + lane + 32*k];
    }
#pragma unroll
    for (int e = 0; e < NE; e++) {
#pragma unroll
        for (int off = 16; off; off >>= 1)
            acc[e] += __shfl_xor_sync(0xffffffffu, acc[e], off);
        acc[e] += bg[e];
    }
    float m = acc[0];
#pragma unroll
    for (int e = 1; e < NE; e++) m = fmaxf(m, acc[e]);
    float sum = 0.f;
#pragma unroll
    for (int e = 0; e < NE; e++) sum += expf(acc[e] - m);

    if (lane < NE) {
        float p = expf(acc[lane] - m) / sum;
        atomicAdd(&s_imp[lane], p);
        float ent = -p * logf(fmaxf(p, 1e-9f));
#pragma unroll
        for (int off = 8; off; off >>= 1)
            ent += __shfl_xor_sync(0xffffu, ent, off);
        if (lane == 0) atomicAdd(&s_ent, ent);
    }

    if (lane == 0) {
        int i0 = 0; float v0 = acc[0];
#pragma unroll
        for (int e = 1; e < NE; e++) if (acc[e] > v0) { v0 = acc[e]; i0 = e; }
        int i1 = (i0 == 0) ? 1 : 0; float v1 = acc[i1];
#pragma unroll
        for (int e = 0; e < NE; e++)
            if (e != i0 && acc[e] > v1) { v1 = acc[e]; i1 = e; }
        float ex = expf(v1 - v0);
        float gg0 = 1.f / (1.f + ex);
        float gg1 = ex / (1.f + ex);
        int s0 = 2*t, s1 = 2*t + 1;
        g_expert[s0] = i0; g_expert[s1] = i1;
        g_gate[s0] = gg0;  g_gate[s1] = gg1;
        atomicAdd(&g_counts[i0], 1);
        atomicAdd(&g_counts[i1], 1);
        atomicAdd(&g_hist[i0*NB + (int)(__float_as_uint(gg0) >> 17)], 1);
        atomicAdd(&g_hist[i1*NB + (int)(__float_as_uint(gg1) >> 17)], 1);
    }
    __syncthreads();
    if (tid < NE) atomicAdd(&g_imp[tid], s_imp[tid]);
    if (tid == 0) atomicAdd(&g_ent, s_ent);

    {
        const float4* src = (const float4*)(ctx + (size_t)blockIdx.x * 8 * DIMV);
        uint2* dst = (uint2*)(g_ctx_h + (size_t)blockIdx.x * 8 * DIMV);
#pragma unroll
        for (int i = 0; i < 2; i++) {
            int j = tid + i*256;
            float4 v = src[j];
            uint2 p;
            p.x = packh(__float2half_rn(v.x), __float2half_rn(v.y));
            p.y = packh(__float2half_rn(v.z), __float2half_rn(v.w));
            dst[j] = p;
        }
    }
}

// ---------------- capacity cutoff --------------------------------------------
__global__ void k_cutoff() {
    int e = blockIdx.x, tid = threadIdx.x;
    __shared__ int chunk[256], suffix[256];
    if (g_counts[e] <= CAP) {
        if (tid == 0) { g_bstar[e] = -1; g_rrem[e] = 0; }
        return;
    }
    const int* h = g_hist + e*NB;
    int b0 = tid * 128;
    int s = 0;
    for (int b = b0; b < b0 + 128; b++) s += h[b];
    chunk[tid] = s;
    __syncthreads();
    if (tid == 0) {
        int run = 0;
        for (int i = 255; i >= 0; i--) { suffix[i] = run; run += chunk[i]; }
    }
    __syncthreads();
    int cum = suffix[tid];
    for (int b = b0 + 127; b >= b0; b--) {
        int hb = h[b];
        if (cum < CAP && cum + hb >= CAP) {
            g_bstar[e] = b; g_rrem[e] = CAP - cum;
        }
        cum += hb;
    }
}

__global__ void k_flags() {
    int s = blockIdx.x * blockDim.x + threadIdx.x;
    if (s >= NSLOT) return;
    int e = g_expert[s];
    unsigned char kept;
    if (g_counts[e] <= CAP) kept = 1;
    else {
        int b  = (int)(__float_as_uint(g_gate[s]) >> 17);
        int bs = g_bstar[e];
        if (b > bs) kept = 1;
        else if (b < bs) kept = 0;
        else {
            kept = 0;
            int p = atomicAdd(&g_btotal, 1);
            g_blist[p] = s;
        }
    }
    g_kept[s] = kept;
}

__global__ void k_boundary() {
    int total = g_btotal;
    for (int i = blockIdx.x * blockDim.x + threadIdx.x; i < total;
         i += gridDim.x * blockDim.x) {
        int si = g_blist[i];
        int e  = g_expert[si];
        unsigned int ki = __float_as_uint(g_gate[si]);
        int better = 0;
        for (int j = 0; j < total; j++) {
            int sj = g_blist[j];
            if (g_expert[sj] != e) continue;
            unsigned int kj = __float_as_uint(g_gate[sj]);
            better += (kj > ki) || (kj == ki && sj < si);
        }
        if (better < g_rrem[e]) g_kept[si] = 1;
    }
}

// block-aggregated compaction (16 global atomics per block)
__global__ void k_compact() {
    __shared__ int scnt[NE], sbase[NE];
    int tid = threadIdx.x;
    int s = blockIdx.x * 256 + tid;
    if (tid < NE) scnt[tid] = 0;
    __syncthreads();
    int e = -1, rank = 0;
    if (s < NSLOT && g_kept[s]) {
        e = g_expert[s];
        rank = atomicAdd(&scnt[e], 1);
    }
    __syncthreads();
    if (tid < NE && scnt[tid] > 0) sbase[tid] = atomicAdd(&g_cursor[tid], scnt[tid]);
    __syncthreads();
    if (e >= 0) g_perm[e*CAP + sbase[e] + rank] = s;
}

// ---------------- GEMM1: H = relu(Xg @ W1 + b1), 128x256 tile ----------------
__global__ void __launch_bounds__(256, 1)
k_gemm1_mma(const float* __restrict__ b1) {
    int e = blockIdx.z;
    int Me = min(g_counts[e], CAP);
    int m0 = blockIdx.x * 128;
    if (m0 >= Me) return;
    int n0 = blockIdx.y * 256;

    extern __shared__ __align__(16) char smem[];
    uint32_t sb = smem_u32(smem);
    int tid = threadIdx.x;
    int* stok = (int*)smem;
    if (tid < 128) {
        int gr = m0 + tid;
        stok[tid] = (gr < Me) ? (g_perm[e*CAP + gr] >> 1) : -1;
    }
    __syncthreads();

    const __half* W = g_w1t + (size_t)e * HID * DIMV;

    auto fill = [&](int stage, int c) {
#pragma unroll
        for (int i = 0; i < 2; i++) {
            int j = tid + i*256;
            int row = j >> 2, ch = j & 3;
            int tok = stok[row];
            cpasync16(sb + G1_A + stage*ASTG + row*AROWB + ch*16,
                      g_ctx_h + (size_t)max(tok, 0)*DIMV + c*32 + ch*8,
                      tok >= 0 ? 16 : 0);
        }
#pragma unroll
        for (int i = 0; i < 4; i++) {
            int j = tid + i*256;
            int row = j >> 2, ch = j & 3;
            cpasync16(sb + G1_B + stage*BSTG + row*AROWB + ch*16,
                      W + (size_t)(n0 + row)*DIMV + c*32 + ch*8, 16);
        }
        CP_COMMIT();
    };

    int warp = tid >> 5, lane = tid & 31;
    int g = lane >> 2, tg = lane & 3;
    int wm = (warp & 1) * 64, wn = (warp >> 1) * 64;
    uint32_t aOff = (uint32_t)(wm + (lane & 7) + ((lane >> 3) & 1)*8) * AROWB
                    + ((lane >> 4) & 1)*16;
    uint32_t bOff = (uint32_t)(wn + ((lane >> 4) & 1)*8 + (lane & 7)) * AROWB
                    + ((lane >> 3) & 1)*16;

    float acc[4][8][4];
#pragma unroll
    for (int a = 0; a < 4; a++)
#pragma unroll
        for (int b = 0; b < 8; b++)
#pragma unroll
            for (int cc = 0; cc < 4; cc++) acc[a][b][cc] = 0.f;

    fill(0, 0);
    const int NCH = DIMV / 32;  // 8
    for (int c = 0; c < NCH; c++) {
        if (c + 1 < NCH) { fill((c+1)&1, c+1); CP_WAIT1(); }
        else CP_WAIT0();
        __syncthreads();
        uint32_t Ab = sb + G1_A + (c&1)*ASTG + aOff;
        uint32_t Bb = sb + G1_B + (c&1)*BSTG + bOff;
#pragma unroll
        for (int s = 0; s < 2; s++) {
            uint32_t Af[4][4], Bf[8][2];
#pragma unroll
            for (int mf = 0; mf < 4; mf++) ldsm4(Af[mf], Ab + mf*(16*AROWB) + s*32);
#pragma unroll
            for (int p = 0; p < 4; p++)  ldsm4(&Bf[2*p][0], Bb + p*(16*AROWB) + s*32);
#pragma unroll
            for (int mf = 0; mf < 4; mf++)
#pragma unroll
                for (int nf = 0; nf < 8; nf++)
                    mma16816(acc[mf][nf], Af[mf], Bf[nf]);
        }
        __syncthreads();
    }

    const float* bias = b1 + (size_t)e * HID;
#pragma unroll
    for (int mf = 0; mf < 4; mf++) {
#pragma unroll
        for (int hv = 0; hv < 2; hv++) {
            int gr = m0 + wm + mf*16 + g + hv*8;
            if (gr >= Me) continue;
            __half* hh = g_hh + (size_t)(e*CAP + gr)*HID;
#pragma unroll
            for (int nf = 0; nf < 8; nf++) {
                int col = n0 + wn + nf*8 + tg*2;
                float2 bb = *(const float2*)(bias + col);
                float v0 = fmaxf(acc[mf][nf][hv*2+0] + bb.x, 0.f);
                float v1 = fmaxf(acc[mf][nf][hv*2+1] + bb.y, 0.f);
                *(uint32_t*)(hh + col) = packh(__float2half_rn(v0), __float2half_rn(v1));
            }
        }
    }
}

// ---------------- GEMM2: Y = (H @ W2 + b2)*gate, 128x256 tile ----------------
__global__ void __launch_bounds__(256, 1)
k_gemm2_mma(const float* __restrict__ b2) {
    int e = blockIdx.z;
    int Me = min(g_counts[e], CAP);
    int m0 = blockIdx.x * 128;
    if (m0 >= Me) return;

    extern __shared__ __align__(16) char smem[];
    uint32_t sb = smem_u32(smem);
    int tid = threadIdx.x;
    int* sslot = (int*)smem;
    float* sgate = (float*)(smem + 512);
    if (tid < 128) {
        int gr = m0 + tid;
        if (gr < Me) {
            int s = g_perm[e*CAP + gr];
            sslot[tid] = s; sgate[tid] = g_gate[s];
        } else { sslot[tid] = -1; sgate[tid] = 0.f; }
    }
    __syncthreads();

    const __half* W = g_w2t + (size_t)e * DIMV * HID;

    auto fill = [&](int stage, int c) {
#pragma unroll
        for (int i = 0; i < 2; i++) {
            int j = tid + i*256;
            int row = j >> 2, ch = j & 3;
            bool ok = (m0 + row) < Me;
            cpasync16(sb + G2_A + stage*ASTG + row*AROWB + ch*16,
                      g_hh + (size_t)(e*CAP + m0 + (ok ? row : 0))*HID + c*32 + ch*8,
                      ok ? 16 : 0);
        }
#pragma unroll
        for (int i = 0; i < 4; i++) {
            int j = tid + i*256;
            int row = j >> 2, ch = j & 3;
            cpasync16(sb + G2_B + stage*BSTG + row*AROWB + ch*16,
                      W + (size_t)row*HID + c*32 + ch*8, 16);
        }
        CP_COMMIT();
    };

    int warp = tid >> 5, lane = tid & 31;
    int g = lane >> 2, tg = lane & 3;
    int wm = (warp & 1) * 64, wn = (warp >> 1) * 64;
    uint32_t aOff = (uint32_t)(wm + (lane & 7) + ((lane >> 3) & 1)*8) * AROWB
                    + ((lane >> 4) & 1)*16;
    uint32_t bOff = (uint32_t)(wn + ((lane >> 4) & 1)*8 + (lane & 7)) * AROWB
                    + ((lane >> 3) & 1)*16;

    float acc[4][8][4];
#pragma unroll
    for (int a = 0; a < 4; a++)
#pragma unroll
        for (int b = 0; b < 8; b++)
#pragma unroll
            for (int cc = 0; cc < 4; cc++) acc[a][b][cc] = 0.f;

    fill(0, 0);
    const int NCH = HID / 32;  // 16
    for (int c = 0; c < NCH; c++) {
        if (c + 1 < NCH) { fill((c+1)&1, c+1); CP_WAIT1(); }
        else CP_WAIT0();
        __syncthreads();
        uint32_t Ab = sb + G2_A + (c&1)*ASTG + aOff;
        uint32_t Bb = sb + G2_B + (c&1)*BSTG + bOff;
#pragma unroll
        for (int s = 0; s < 2; s++) {
            uint32_t Af[4][4], Bf[8][2];
#pragma unroll
            for (int mf = 0; mf < 4; mf++) ldsm4(Af[mf], Ab + mf*(16*AROWB) + s*32);
#pragma unroll
            for (int p = 0; p < 4; p++)  ldsm4(&Bf[2*p][0], Bb + p*(16*AROWB) + s*32);
#pragma unroll
            for (int mf = 0; mf < 4; mf++)
#pragma unroll
                for (int nf = 0; nf < 8; nf++)
                    mma16816(acc[mf][nf], Af[mf], Bf[nf]);
        }
        __syncthreads();
    }

    const float* bias = b2 + (size_t)e * DIMV;
#pragma unroll
    for (int mf = 0; mf < 4; mf++) {
#pragma unroll
        for (int hv = 0; hv < 2; hv++) {
            int r = wm + mf*16 + g + hv*8;
            int slot = sslot[r];
            if (slot < 0) continue;
            float gate = sgate[r];
            __half* yr = g_y + (size_t)slot * DIMV;
#pragma unroll
            for (int nf = 0; nf < 8; nf++) {
                int col = wn + nf*8 + tg*2;
                float2 bb = *(const float2*)(bias + col);
                float v0 = (acc[mf][nf][hv*2+0] + bb.x) * gate;
                float v1 = (acc[mf][nf][hv*2+1] + bb.y) * gate;
                *(uint32_t*)(yr + col) = packh(__float2half_rn(v0), __float2half_rn(v1));
            }
        }
    }
}

// ---------------- combine (fp16 y) -------------------------------------------
__global__ void k_combine(float* __restrict__ out) {
    int idx = blockIdx.x * blockDim.x + threadIdx.x;   // NTOK*32
    if (idx >= NTOK * 32) return;
    int t = idx >> 5, f = idx & 31;                    // 8 cols per thread
    float r[8];
#pragma unroll
    for (int i = 0; i < 8; i++) r[i] = 0.f;
    if (g_kept[2*t]) {
        uint4 a = *(const uint4*)(g_y + (size_t)(2*t)*DIMV + f*8);
        const uint32_t* w = (const uint32_t*)&a;
#pragma unroll
        for (int i = 0; i < 4; i++) {
            __half2 h2 = *(const __half2*)&w[i];
            float2 v = __half22float2(h2);
            r[2*i] += v.x; r[2*i+1] += v.y;
        }
    }
    if (g_kept[2*t + 1]) {
        uint4 a = *(const uint4*)(g_y + (size_t)(2*t+1)*DIMV + f*8);
        const uint32_t* w = (const uint32_t*)&a;
#pragma unroll
        for (int i = 0; i < 4; i++) {
            __half2 h2 = *(const __half2*)&w[i];
            float2 v = __half22float2(h2);
            r[2*i] += v.x; r[2*i+1] += v.y;
        }
    }
    float* o = out + (size_t)t*DIMV + f*8;
    *(float4*)o     = make_float4(r[0], r[1], r[2], r[3]);
    *(float4*)(o+4) = make_float4(r[4], r[5], r[6], r[7]);
}

// ---------------- finalize ---------------------------------------------------
__global__ void k_final(float* __restrict__ out, int out_size) {
    int lane = threadIdx.x;
    int c = (lane < NE) ? min(g_counts[lane], CAP) : 0;
    int tot = c;
#pragma unroll
    for (int off = 16; off; off >>= 1) tot += __shfl_xor_sync(0xffffffffu, tot, off);
    float denom = fmaxf((float)tot, 1.f);
    float aux = 0.f;
    if (lane < NE)
        aux = (g_imp[lane] / (float)NTOK) * ((float)c / denom) * (float)NE;
#pragma unroll
    for (int off = 16; off; off >>= 1) aux += __shfl_xor_sync(0xffffffffu, aux, off);
    int base = NTOK * DIMV;
    if (lane == 0 && out_size > base)     out[base]     = aux;
    if (lane == 0 && out_size > base + 1) out[base + 1] = g_ent / (float)NTOK;
    if (lane < NE && out_size > base + 2 + lane) out[base + 2 + lane] = (float)c;
}

// ---------------- launch -----------------------------------------------------
extern "C" void kernel_launch(void* const* d_in, const int* in_sizes, int n_in,
                              void* d_out, int out_size) {
    const float* ctx = (const float*)d_in[0];
    const float* Wg  = (const float*)d_in[1];
    const float* bg  = (const float*)d_in[2];
    const float* W1  = (const float*)d_in[3];
    const float* b1  = (const float*)d_in[4];
    const float* W2  = (const float*)d_in[5];
    const float* b2  = (const float*)d_in[6];
    float* out = (float*)d_out;

    static bool attr_done = false;
    if (!attr_done) {
        cudaFuncSetAttribute(k_gemm1_mma, cudaFuncAttributeMaxDynamicSharedMemorySize, G1_SZ);
        cudaFuncSetAttribute(k_gemm2_mma, cudaFuncAttributeMaxDynamicSharedMemorySize, G2_SZ);
        attr_done = true;
    }

    k_zero<<<512, 256>>>();
    k_transpose<<<dim3(HID/32, DIMV/32, NE), 256>>>(W1, 0, DIMV, HID);
    k_transpose<<<dim3(DIMV/32, HID/32, NE), 256>>>(W2, 1, HID, DIMV);
    k_router<<<NTOK/8, 256>>>(ctx, Wg, bg);
    k_cutoff<<<NE, 256>>>();
    k_flags<<<NSLOT/256, 256>>>();
    k_boundary<<<64, 256>>>();
    k_compact<<<(NSLOT + 255)/256, 256>>>();

    dim3 g1(MTILES, HID/256, NE);
    k_gemm1_mma<<<g1, 256, G1_SZ>>>(b1);
    dim3 g2(MTILES, 1, NE);
    k_gemm2_mma<<<g2, 256, G2_SZ>>>(b2);

    k_combine<<<(NTOK*32)/256, 256>>>(out);
    k_final<<<1, 32>>>(out, out_size);
}

// round 7
// speedup vs baseline: 3.6221x; 1.0831x over previous
#include <cuda_runtime.h>
#include <cuda_fp16.h>
#include <math.h>
#include <stdint.h>

#define NTOK  131072
#define DIMV  256
#define HID   512
#define NE    16
#define CAP   18023
#define NSLOT (NTOK*2)
#define ECAP  (NE*CAP)
#define NB    32768
#define MTILES ((CAP+127)/128)

// ---------------- scratch (static device globals) ----------------------------
__device__ float g_gate[NSLOT];
__device__ int   g_expert[NSLOT];
__device__ unsigned char g_kept[NSLOT];
__device__ int   g_counts[NE];
__device__ int   g_cursor[NE];
__device__ int   g_perm[ECAP];
__device__ int   g_hist[NE*NB];
__device__ int   g_bstar[NE], g_rrem[NE];
__device__ int   g_blist[NSLOT];
__device__ int   g_btotal;
__device__ float g_imp[NE];
__device__ float g_ent;

__device__ __half g_ctx_h[(size_t)NTOK * DIMV];
__device__ __half g_w1t[(size_t)NE * HID * DIMV];   // [e][h][d]
__device__ __half g_w2t[(size_t)NE * DIMV * HID];   // [e][d][h]
__device__ __half g_hh[(size_t)ECAP * HID];
__device__ __half g_y[(size_t)NSLOT * DIMV];

// ---------------- helpers ----------------------------------------------------
__device__ __forceinline__ uint32_t smem_u32(const void* p) {
    uint32_t a;
    asm("{ .reg .u64 t; cvta.to.shared.u64 t, %1; cvt.u32.u64 %0, t; }"
        : "=r"(a) : "l"(p));
    return a;
}
__device__ __forceinline__ void cpasync16(uint32_t dst, const void* src, int srcsz) {
    asm volatile("cp.async.cg.shared.global [%0], [%1], 16, %2;"
                 :: "r"(dst), "l"(src), "r"(srcsz) : "memory");
}
#define CP_COMMIT() asm volatile("cp.async.commit_group;" ::: "memory")
#define CP_WAIT1()  asm volatile("cp.async.wait_group 1;" ::: "memory")
#define CP_WAIT0()  asm volatile("cp.async.wait_group 0;" ::: "memory")

__device__ __forceinline__ void ldsm4(uint32_t* r, uint32_t addr) {
    asm volatile("ldmatrix.sync.aligned.m8n8.x4.shared.b16 {%0,%1,%2,%3}, [%4];"
                 : "=r"(r[0]), "=r"(r[1]), "=r"(r[2]), "=r"(r[3]) : "r"(addr));
}
__device__ __forceinline__ void mma16816(float* c, const uint32_t* a, const uint32_t* b) {
    asm volatile(
        "mma.sync.aligned.m16n8k16.row.col.f32.f16.f16.f32 "
        "{%0,%1,%2,%3}, {%4,%5,%6,%7}, {%8,%9}, {%0,%1,%2,%3};"
        : "+f"(c[0]), "+f"(c[1]), "+f"(c[2]), "+f"(c[3])
        : "r"(a[0]), "r"(a[1]), "r"(a[2]), "r"(a[3]), "r"(b[0]), "r"(b[1]));
}
__device__ __forceinline__ uint32_t packh(__half a, __half b) {
    return (uint32_t)__half_as_ushort(a) | ((uint32_t)__half_as_ushort(b) << 16);
}

// padded smem row: 32 fp16 + 8 pad = 80 bytes (conflict-free for LDSM/cp.async)
#define AROWB 80
#define ASTG  10240            // 128 rows
#define BSTG  20480            // 256 rows
// GEMM1: tok[128] @0, A @512 (3 stages), B after
#define G1_A  512
#define G1_B  (G1_A + 3*ASTG)
#define G1_SZ (G1_B + 3*BSTG)
// GEMM2: slot[128] @0, gate[128] @512, A @1024
#define G2_A  1024
#define G2_B  (G2_A + 3*ASTG)
#define G2_SZ (G2_B + 3*BSTG)

// ---------------- zero -------------------------------------------------------
__global__ void k_zero() {
    int i = blockIdx.x * blockDim.x + threadIdx.x;
    for (int j = i; j < NE*NB; j += gridDim.x * blockDim.x) g_hist[j] = 0;
    if (i < NE) { g_counts[i] = 0; g_cursor[i] = 0; g_imp[i] = 0.f; }
    if (i == 0) { g_ent = 0.f; g_btotal = 0; }
}

// ---------------- coalesced transpose + fp16 convert -------------------------
__global__ void k_transpose(const float* __restrict__ src, int which, int R, int C) {
    __shared__ float tile[32][33];
    __half* dstg = which ? g_w2t : g_w1t;
    int e = blockIdx.z;
    const float* S = src + (size_t)e * R * C;
    __half* D = dstg + (size_t)e * R * C;
    int c0 = blockIdx.x * 32, r0 = blockIdx.y * 32;
    int tc = threadIdx.x & 31, tr4 = threadIdx.x >> 5;
#pragma unroll
    for (int i = 0; i < 4; i++) {
        int r = tr4 + i*8;
        tile[r][tc] = S[(size_t)(r0 + r)*C + c0 + tc];
    }
    __syncthreads();
#pragma unroll
    for (int i = 0; i < 4; i++) {
        int r = tr4 + i*8;
        D[(size_t)(c0 + r)*R + r0 + tc] = __float2half_rn(tile[tc][r]);
    }
}

// ---------------- router (+ fused ctx->fp16) ---------------------------------
// sWT[d][e] padded to stride 20 floats: conflict-free LDS.128 fragment loads
__global__ void k_router(const float* __restrict__ ctx,
                         const float* __restrict__ Wg,
                         const float* __restrict__ bg) {
    __shared__ float sWT[DIMV*20];
    __shared__ float s_imp[NE];
    __shared__ float s_ent;
    int tid = threadIdx.x;
    for (int i = tid; i < NE*DIMV; i += blockDim.x)
        sWT[(i >> 4)*20 + (i & 15)] = Wg[i];
    if (tid < NE) s_imp[tid] = 0.f;
    if (tid == 0) s_ent = 0.f;
    __syncthreads();

    int warp = tid >> 5, lane = tid & 31;
    int t = blockIdx.x * 8 + warp;
    const float* x = ctx + (size_t)t * DIMV;

    float acc[NE];
#pragma unroll
    for (int e = 0; e < NE; e++) acc[e] = 0.f;
#pragma unroll
    for (int k = 0; k < 8; k++) {
        int d = lane + 32*k;
        float xv = x[d];
        const float4* wrow = (const float4*)&sWT[d*20];
#pragma unroll
        for (int e4 = 0; e4 < 4; e4++) {
            float4 w = wrow[e4];
            acc[e4*4+0] += xv * w.x;
            acc[e4*4+1] += xv * w.y;
            acc[e4*4+2] += xv * w.z;
            acc[e4*4+3] += xv * w.w;
        }
    }
#pragma unroll
    for (int e = 0; e < NE; e++) {
#pragma unroll
        for (int off = 16; off; off >>= 1)
            acc[e] += __shfl_xor_sync(0xffffffffu, acc[e], off);
        acc[e] += bg[e];
    }
    float m = acc[0];
#pragma unroll
    for (int e = 1; e < NE; e++) m = fmaxf(m, acc[e]);
    float sum = 0.f;
#pragma unroll
    for (int e = 0; e < NE; e++) sum += __expf(acc[e] - m);

    if (lane < NE) {
        float p = __expf(acc[lane] - m) / sum;
        atomicAdd(&s_imp[lane], p);
        float ent = -p * __logf(fmaxf(p, 1e-9f));
#pragma unroll
        for (int off = 8; off; off >>= 1)
            ent += __shfl_xor_sync(0xffffu, ent, off);
        if (lane == 0) atomicAdd(&s_ent, ent);
    }

    if (lane == 0) {
        int i0 = 0; float v0 = acc[0];
#pragma unroll
        for (int e = 1; e < NE; e++) if (acc[e] > v0) { v0 = acc[e]; i0 = e; }
        int i1 = (i0 == 0) ? 1 : 0; float v1 = acc[i1];
#pragma unroll
        for (int e = 0; e < NE; e++)
            if (e != i0 && acc[e] > v1) { v1 = acc[e]; i1 = e; }
        float ex = __expf(v1 - v0);
        float gg0 = 1.f / (1.f + ex);
        float gg1 = ex / (1.f + ex);
        int s0 = 2*t, s1 = 2*t + 1;
        g_expert[s0] = i0; g_expert[s1] = i1;
        g_gate[s0] = gg0;  g_gate[s1] = gg1;
        atomicAdd(&g_counts[i0], 1);
        atomicAdd(&g_counts[i1], 1);
        atomicAdd(&g_hist[i0*NB + (int)(__float_as_uint(gg0) >> 17)], 1);
        atomicAdd(&g_hist[i1*NB + (int)(__float_as_uint(gg1) >> 17)], 1);
    }
    __syncthreads();
    if (tid < NE) atomicAdd(&g_imp[tid], s_imp[tid]);
    if (tid == 0) atomicAdd(&g_ent, s_ent);

    {
        const float4* src = (const float4*)(ctx + (size_t)blockIdx.x * 8 * DIMV);
        uint2* dst = (uint2*)(g_ctx_h + (size_t)blockIdx.x * 8 * DIMV);
#pragma unroll
        for (int i = 0; i < 2; i++) {
            int j = tid + i*256;
            float4 v = src[j];
            uint2 p;
            p.x = packh(__float2half_rn(v.x), __float2half_rn(v.y));
            p.y = packh(__float2half_rn(v.z), __float2half_rn(v.w));
            dst[j] = p;
        }
    }
}

// ---------------- capacity cutoff --------------------------------------------
__global__ void k_cutoff() {
    int e = blockIdx.x, tid = threadIdx.x;
    __shared__ int chunk[256], suffix[256];
    if (g_counts[e] <= CAP) {
        if (tid == 0) { g_bstar[e] = -1; g_rrem[e] = 0; }
        return;
    }
    const int* h = g_hist + e*NB;
    int b0 = tid * 128;
    int s = 0;
    for (int b = b0; b < b0 + 128; b++) s += h[b];
    chunk[tid] = s;
    __syncthreads();
    if (tid == 0) {
        int run = 0;
        for (int i = 255; i >= 0; i--) { suffix[i] = run; run += chunk[i]; }
    }
    __syncthreads();
    int cum = suffix[tid];
    for (int b = b0 + 127; b >= b0; b--) {
        int hb = h[b];
        if (cum < CAP && cum + hb >= CAP) {
            g_bstar[e] = b; g_rrem[e] = CAP - cum;
        }
        cum += hb;
    }
}

__global__ void k_flags() {
    int s = blockIdx.x * blockDim.x + threadIdx.x;
    if (s >= NSLOT) return;
    int e = g_expert[s];
    unsigned char kept;
    if (g_counts[e] <= CAP) kept = 1;
    else {
        int b  = (int)(__float_as_uint(g_gate[s]) >> 17);
        int bs = g_bstar[e];
        if (b > bs) kept = 1;
        else if (b < bs) kept = 0;
        else {
            kept = 0;
            int p = atomicAdd(&g_btotal, 1);
            g_blist[p] = s;
        }
    }
    g_kept[s] = kept;
}

__global__ void k_boundary() {
    int total = g_btotal;
    for (int i = blockIdx.x * blockDim.x + threadIdx.x; i < total;
         i += gridDim.x * blockDim.x) {
        int si = g_blist[i];
        int e  = g_expert[si];
        unsigned int ki = __float_as_uint(g_gate[si]);
        int better = 0;
        for (int j = 0; j < total; j++) {
            int sj = g_blist[j];
            if (g_expert[sj] != e) continue;
            unsigned int kj = __float_as_uint(g_gate[sj]);
            better += (kj > ki) || (kj == ki && sj < si);
        }
        if (better < g_rrem[e]) g_kept[si] = 1;
    }
}

// block-aggregated compaction (16 global atomics per block)
__global__ void k_compact() {
    __shared__ int scnt[NE], sbase[NE];
    int tid = threadIdx.x;
    int s = blockIdx.x * 256 + tid;
    if (tid < NE) scnt[tid] = 0;
    __syncthreads();
    int e = -1, rank = 0;
    if (s < NSLOT && g_kept[s]) {
        e = g_expert[s];
        rank = atomicAdd(&scnt[e], 1);
    }
    __syncthreads();
    if (tid < NE && scnt[tid] > 0) sbase[tid] = atomicAdd(&g_cursor[tid], scnt[tid]);
    __syncthreads();
    if (e >= 0) g_perm[e*CAP + sbase[e] + rank] = s;
}

// ---------------- GEMM1: H = relu(Xg @ W1 + b1), 128x256 tile, 3-stage -------
__global__ void __launch_bounds__(256, 1)
k_gemm1_mma(const float* __restrict__ b1) {
    int e = blockIdx.z;
    int Me = min(g_counts[e], CAP);
    int m0 = blockIdx.x * 128;
    if (m0 >= Me) return;
    int n0 = blockIdx.y * 256;

    extern __shared__ __align__(16) char smem[];
    uint32_t sb = smem_u32(smem);
    int tid = threadIdx.x;
    int* stok = (int*)smem;
    if (tid < 128) {
        int gr = m0 + tid;
        stok[tid] = (gr < Me) ? (g_perm[e*CAP + gr] >> 1) : -1;
    }
    __syncthreads();

    const __half* W = g_w1t + (size_t)e * HID * DIMV;

    auto fill = [&](int stage, int c) {
#pragma unroll
        for (int i = 0; i < 2; i++) {
            int j = tid + i*256;
            int row = j >> 2, ch = j & 3;
            int tok = stok[row];
            cpasync16(sb + G1_A + stage*ASTG + row*AROWB + ch*16,
                      g_ctx_h + (size_t)max(tok, 0)*DIMV + c*32 + ch*8,
                      tok >= 0 ? 16 : 0);
        }
#pragma unroll
        for (int i = 0; i < 4; i++) {
            int j = tid + i*256;
            int row = j >> 2, ch = j & 3;
            cpasync16(sb + G1_B + stage*BSTG + row*AROWB + ch*16,
                      W + (size_t)(n0 + row)*DIMV + c*32 + ch*8, 16);
        }
        CP_COMMIT();
    };

    int warp = tid >> 5, lane = tid & 31;
    int g = lane >> 2, tg = lane & 3;
    int wm = (warp & 1) * 64, wn = (warp >> 1) * 64;
    uint32_t aOff = (uint32_t)(wm + (lane & 7) + ((lane >> 3) & 1)*8) * AROWB
                    + ((lane >> 4) & 1)*16;
    uint32_t bOff = (uint32_t)(wn + ((lane >> 4) & 1)*8 + (lane & 7)) * AROWB
                    + ((lane >> 3) & 1)*16;

    float acc[4][8][4];
#pragma unroll
    for (int a = 0; a < 4; a++)
#pragma unroll
        for (int b = 0; b < 8; b++)
#pragma unroll
            for (int cc = 0; cc < 4; cc++) acc[a][b][cc] = 0.f;

    fill(0, 0); fill(1, 1);
    const int NCH = DIMV / 32;  // 8
    for (int c = 0; c < NCH; c++) {
        if (c + 1 < NCH) CP_WAIT1(); else CP_WAIT0();
        __syncthreads();
        if (c + 2 < NCH) fill((c + 2) % 3, c + 2);
        uint32_t Ab = sb + G1_A + (c % 3)*ASTG + aOff;
        uint32_t Bb = sb + G1_B + (c % 3)*BSTG + bOff;
#pragma unroll
        for (int s = 0; s < 2; s++) {
            uint32_t Af[4][4], Bf[8][2];
#pragma unroll
            for (int mf = 0; mf < 4; mf++) ldsm4(Af[mf], Ab + mf*(16*AROWB) + s*32);
#pragma unroll
            for (int p = 0; p < 4; p++)  ldsm4(&Bf[2*p][0], Bb + p*(16*AROWB) + s*32);
#pragma unroll
            for (int mf = 0; mf < 4; mf++)
#pragma unroll
                for (int nf = 0; nf < 8; nf++)
                    mma16816(acc[mf][nf], Af[mf], Bf[nf]);
        }
    }

    const float* bias = b1 + (size_t)e * HID;
#pragma unroll
    for (int mf = 0; mf < 4; mf++) {
#pragma unroll
        for (int hv = 0; hv < 2; hv++) {
            int gr = m0 + wm + mf*16 + g + hv*8;
            if (gr >= Me) continue;
            __half* hh = g_hh + (size_t)(e*CAP + gr)*HID;
#pragma unroll
            for (int nf = 0; nf < 8; nf++) {
                int col = n0 + wn + nf*8 + tg*2;
                float2 bb = *(const float2*)(bias + col);
                float v0 = fmaxf(acc[mf][nf][hv*2+0] + bb.x, 0.f);
                float v1 = fmaxf(acc[mf][nf][hv*2+1] + bb.y, 0.f);
                *(uint32_t*)(hh + col) = packh(__float2half_rn(v0), __float2half_rn(v1));
            }
        }
    }
}

// ---------------- GEMM2: Y = (H @ W2 + b2)*gate, 128x256 tile, 3-stage -------
__global__ void __launch_bounds__(256, 1)
k_gemm2_mma(const float* __restrict__ b2) {
    int e = blockIdx.z;
    int Me = min(g_counts[e], CAP);
    int m0 = blockIdx.x * 128;
    if (m0 >= Me) return;

    extern __shared__ __align__(16) char smem[];
    uint32_t sb = smem_u32(smem);
    int tid = threadIdx.x;
    int* sslot = (int*)smem;
    float* sgate = (float*)(smem + 512);
    if (tid < 128) {
        int gr = m0 + tid;
        if (gr < Me) {
            int s = g_perm[e*CAP + gr];
            sslot[tid] = s; sgate[tid] = g_gate[s];
        } else { sslot[tid] = -1; sgate[tid] = 0.f; }
    }
    __syncthreads();

    const __half* W = g_w2t + (size_t)e * DIMV * HID;

    auto fill = [&](int stage, int c) {
#pragma unroll
        for (int i = 0; i < 2; i++) {
            int j = tid + i*256;
            int row = j >> 2, ch = j & 3;
            bool ok = (m0 + row) < Me;
            cpasync16(sb + G2_A + stage*ASTG + row*AROWB + ch*16,
                      g_hh + (size_t)(e*CAP + m0 + (ok ? row : 0))*HID + c*32 + ch*8,
                      ok ? 16 : 0);
        }
#pragma unroll
        for (int i = 0; i < 4; i++) {
            int j = tid + i*256;
            int row = j >> 2, ch = j & 3;
            cpasync16(sb + G2_B + stage*BSTG + row*AROWB + ch*16,
                      W + (size_t)row*HID + c*32 + ch*8, 16);
        }
        CP_COMMIT();
    };

    int warp = tid >> 5, lane = tid & 31;
    int g = lane >> 2, tg = lane & 3;
    int wm = (warp & 1) * 64, wn = (warp >> 1) * 64;
    uint32_t aOff = (uint32_t)(wm + (lane & 7) + ((lane >> 3) & 1)*8) * AROWB
                    + ((lane >> 4) & 1)*16;
    uint32_t bOff = (uint32_t)(wn + ((lane >> 4) & 1)*8 + (lane & 7)) * AROWB
                    + ((lane >> 3) & 1)*16;

    float acc[4][8][4];
#pragma unroll
    for (int a = 0; a < 4; a++)
#pragma unroll
        for (int b = 0; b < 8; b++)
#pragma unroll
            for (int cc = 0; cc < 4; cc++) acc[a][b][cc] = 0.f;

    fill(0, 0); fill(1, 1);
    const int NCH = HID / 32;  // 16
    for (int c = 0; c < NCH; c++) {
        if (c + 1 < NCH) CP_WAIT1(); else CP_WAIT0();
        __syncthreads();
        if (c + 2 < NCH) fill((c + 2) % 3, c + 2);
        uint32_t Ab = sb + G2_A + (c % 3)*ASTG + aOff;
        uint32_t Bb = sb + G2_B + (c % 3)*BSTG + bOff;
#pragma unroll
        for (int s = 0; s < 2; s++) {
            uint32_t Af[4][4], Bf[8][2];
#pragma unroll
            for (int mf = 0; mf < 4; mf++) ldsm4(Af[mf], Ab + mf*(16*AROWB) + s*32);
#pragma unroll
            for (int p = 0; p < 4; p++)  ldsm4(&Bf[2*p][0], Bb + p*(16*AROWB) + s*32);
#pragma unroll
            for (int mf = 0; mf < 4; mf++)
#pragma unroll
                for (int nf = 0; nf < 8; nf++)
                    mma16816(acc[mf][nf], Af[mf], Bf[nf]);
        }
    }

    const float* bias = b2 + (size_t)e * DIMV;
#pragma unroll
    for (int mf = 0; mf < 4; mf++) {
#pragma unroll
        for (int hv = 0; hv < 2; hv++) {
            int r = wm + mf*16 + g + hv*8;
            int slot = sslot[r];
            if (slot < 0) continue;
            float gate = sgate[r];
            __half* yr = g_y + (size_t)slot * DIMV;
#pragma unroll
            for (int nf = 0; nf < 8; nf++) {
                int col = wn + nf*8 + tg*2;
                float2 bb = *(const float2*)(bias + col);
                float v0 = (acc[mf][nf][hv*2+0] + bb.x) * gate;
                float v1 = (acc[mf][nf][hv*2+1] + bb.y) * gate;
                *(uint32_t*)(yr + col) = packh(__float2half_rn(v0), __float2half_rn(v1));
            }
        }
    }
}

// ---------------- combine (fp16 y) -------------------------------------------
__global__ void k_combine(float* __restrict__ out) {
    int idx = blockIdx.x * blockDim.x + threadIdx.x;   // NTOK*32
    if (idx >= NTOK * 32) return;
    int t = idx >> 5, f = idx & 31;
    float r[8];
#pragma unroll
    for (int i = 0; i < 8; i++) r[i] = 0.f;
    if (g_kept[2*t]) {
        uint4 a = *(const uint4*)(g_y + (size_t)(2*t)*DIMV + f*8);
        const uint32_t* w = (const uint32_t*)&a;
#pragma unroll
        for (int i = 0; i < 4; i++) {
            __half2 h2 = *(const __half2*)&w[i];
            float2 v = __half22float2(h2);
            r[2*i] += v.x; r[2*i+1] += v.y;
        }
    }
    if (g_kept[2*t + 1]) {
        uint4 a = *(const uint4*)(g_y + (size_t)(2*t+1)*DIMV + f*8);
        const uint32_t* w = (const uint32_t*)&a;
#pragma unroll
        for (int i = 0; i < 4; i++) {
            __half2 h2 = *(const __half2*)&w[i];
            float2 v = __half22float2(h2);
            r[2*i] += v.x; r[2*i+1] += v.y;
        }
    }
    float* o = out + (size_t)t*DIMV + f*8;
    *(float4*)o     = make_float4(r[0], r[1], r[2], r[3]);
    *(float4*)(o+4) = make_float4(r[4], r[5], r[6], r[7]);
}

// ---------------- finalize ---------------------------------------------------
__global__ void k_final(float* __restrict__ out, int out_size) {
    int lane = threadIdx.x;
    int c = (lane < NE) ? min(g_counts[lane], CAP) : 0;
    int tot = c;
#pragma unroll
    for (int off = 16; off; off >>= 1) tot += __shfl_xor_sync(0xffffffffu, tot, off);
    float denom = fmaxf((float)tot, 1.f);
    float aux = 0.f;
    if (lane < NE)
        aux = (g_imp[lane] / (float)NTOK) * ((float)c / denom) * (float)NE;
#pragma unroll
    for (int off = 16; off; off >>= 1) aux += __shfl_xor_sync(0xffffffffu, aux, off);
    int base = NTOK * DIMV;
    if (lane == 0 && out_size > base)     out[base]     = aux;
    if (lane == 0 && out_size > base + 1) out[base + 1] = g_ent / (float)NTOK;
    if (lane < NE && out_size > base + 2 + lane) out[base + 2 + lane] = (float)c;
}

// ---------------- launch -----------------------------------------------------
extern "C" void kernel_launch(void* const* d_in, const int* in_sizes, int n_in,
                              void* d_out, int out_size) {
    const float* ctx = (const float*)d_in[0];
    const float* Wg  = (const float*)d_in[1];
    const float* bg  = (const float*)d_in[2];
    const float* W1  = (const float*)d_in[3];
    const float* b1  = (const float*)d_in[4];
    const float* W2  = (const float*)d_in[5];
    const float* b2  = (const float*)d_in[6];
    float* out = (float*)d_out;

    static bool attr_done = false;
    if (!attr_done) {
        cudaFuncSetAttribute(k_gemm1_mma, cudaFuncAttributeMaxDynamicSharedMemorySize, G1_SZ);
        cudaFuncSetAttribute(k_gemm2_mma, cudaFuncAttributeMaxDynamicSharedMemorySize, G2_SZ);
        attr_done = true;
    }

    k_zero<<<512, 256>>>();
    k_transpose<<<dim3(HID/32, DIMV/32, NE), 256>>>(W1, 0, DIMV, HID);
    k_transpose<<<dim3(DIMV/32, HID/32, NE), 256>>>(W2, 1, HID, DIMV);
    k_router<<<NTOK/8, 256>>>(ctx, Wg, bg);
    k_cutoff<<<NE, 256>>>();
    k_flags<<<NSLOT/256, 256>>>();
    k_boundary<<<64, 256>>>();
    k_compact<<<(NSLOT + 255)/256, 256>>>();

    dim3 g1(MTILES, HID/256, NE);
    k_gemm1_mma<<<g1, 256, G1_SZ>>>(b1);
    dim3 g2(MTILES, 1, NE);
    k_gemm2_mma<<<g2, 256, G2_SZ>>>(b2);

    k_combine<<<(NTOK*32)/256, 256>>>(out);
    k_final<<<1, 32>>>(out, out_size);
}

// round 8
// speedup vs baseline: 3.8707x; 1.0686x over previous
#include <cuda_runtime.h>
#include <cuda_fp16.h>
#include <math.h>
#include <stdint.h>

#define NTOK  131072
#define DIMV  256
#define HID   512
#define NE    16
#define CAP   18023
#define NSLOT (NTOK*2)
#define ECAP  (NE*CAP)
#define NB    32768
#define MTILES ((CAP+127)/128)

// ---------------- scratch (static device globals) ----------------------------
__device__ float g_gate[NSLOT];
__device__ int   g_expert[NSLOT];
__device__ unsigned char g_kept[NSLOT];
__device__ int   g_counts[NE];
__device__ int   g_cursor[NE];
__device__ int   g_perm[ECAP];
__device__ int   g_hist[NE*NB];
__device__ int   g_bstar[NE], g_rrem[NE];
__device__ int   g_blist[NSLOT];
__device__ int   g_btotal;
__device__ float g_imp[NE];
__device__ float g_ent;

__device__ __half g_ctx_h[(size_t)NTOK * DIMV];
__device__ __half g_w1t[(size_t)NE * HID * DIMV];   // [e][h][d]
__device__ __half g_w2t[(size_t)NE * DIMV * HID];   // [e][d][h]
__device__ __half g_hh[(size_t)ECAP * HID];
__device__ __half g_y[(size_t)NSLOT * DIMV];

// ---------------- helpers ----------------------------------------------------
__device__ __forceinline__ uint32_t smem_u32(const void* p) {
    uint32_t a;
    asm("{ .reg .u64 t; cvta.to.shared.u64 t, %1; cvt.u32.u64 %0, t; }"
        : "=r"(a) : "l"(p));
    return a;
}
__device__ __forceinline__ void cpasync16(uint32_t dst, const void* src, int srcsz) {
    asm volatile("cp.async.cg.shared.global [%0], [%1], 16, %2;"
                 :: "r"(dst), "l"(src), "r"(srcsz) : "memory");
}
#define CP_COMMIT() asm volatile("cp.async.commit_group;" ::: "memory")
#define CP_WAIT1()  asm volatile("cp.async.wait_group 1;" ::: "memory")
#define CP_WAIT0()  asm volatile("cp.async.wait_group 0;" ::: "memory")

__device__ __forceinline__ void ldsm4(uint32_t* r, uint32_t addr) {
    asm volatile("ldmatrix.sync.aligned.m8n8.x4.shared.b16 {%0,%1,%2,%3}, [%4];"
                 : "=r"(r[0]), "=r"(r[1]), "=r"(r[2]), "=r"(r[3]) : "r"(addr));
}
__device__ __forceinline__ void mma16816(float* c, const uint32_t* a, const uint32_t* b) {
    asm volatile(
        "mma.sync.aligned.m16n8k16.row.col.f32.f16.f16.f32 "
        "{%0,%1,%2,%3}, {%4,%5,%6,%7}, {%8,%9}, {%0,%1,%2,%3};"
        : "+f"(c[0]), "+f"(c[1]), "+f"(c[2]), "+f"(c[3])
        : "r"(a[0]), "r"(a[1]), "r"(a[2]), "r"(a[3]), "r"(b[0]), "r"(b[1]));
}
__device__ __forceinline__ uint32_t packh(__half a, __half b) {
    return (uint32_t)__half_as_ushort(a) | ((uint32_t)__half_as_ushort(b) << 16);
}

// padded smem row: 32 fp16 + 8 pad = 80 bytes (conflict-free for LDSM/cp.async)
#define AROWB 80
#define ASTG  10240            // 128 rows
#define BSTG  20480            // 256 rows
#define G1_A  512
#define G1_B  (G1_A + 3*ASTG)
#define G1_SZ (G1_B + 3*BSTG)
#define G2_A  1024
#define G2_B  (G2_A + 3*ASTG)
#define G2_SZ (G2_B + 3*BSTG)

// ---------------- zero -------------------------------------------------------
__global__ void k_zero() {
    int i = blockIdx.x * blockDim.x + threadIdx.x;
    for (int j = i; j < NE*NB; j += gridDim.x * blockDim.x) g_hist[j] = 0;
    if (i < NE) { g_counts[i] = 0; g_cursor[i] = 0; g_imp[i] = 0.f; }
    if (i == 0) { g_ent = 0.f; g_btotal = 0; }
}

// ---------------- coalesced transpose + fp16 convert -------------------------
__global__ void k_transpose(const float* __restrict__ src, int which, int R, int C) {
    __shared__ float tile[32][33];
    __half* dstg = which ? g_w2t : g_w1t;
    int e = blockIdx.z;
    const float* S = src + (size_t)e * R * C;
    __half* D = dstg + (size_t)e * R * C;
    int c0 = blockIdx.x * 32, r0 = blockIdx.y * 32;
    int tc = threadIdx.x & 31, tr4 = threadIdx.x >> 5;
#pragma unroll
    for (int i = 0; i < 4; i++) {
        int r = tr4 + i*8;
        tile[r][tc] = S[(size_t)(r0 + r)*C + c0 + tc];
    }
    __syncthreads();
#pragma unroll
    for (int i = 0; i < 4; i++) {
        int r = tr4 + i*8;
        D[(size_t)(c0 + r)*R + r0 + tc] = __float2half_rn(tile[tc][r]);
    }
}

// ---------------- router: 4 threads/token, 8 tokens/warp ---------------------
// sWT[d][e] padded to stride 20 floats; thread q owns d = 4i+q (bank-safe)
__global__ void k_router(const float* __restrict__ ctx,
                         const float* __restrict__ Wg,
                         const float* __restrict__ bg) {
    __shared__ float sWT[DIMV*20];
    __shared__ float s_imp[NE];
    __shared__ float s_ent;
    __shared__ float s_bg[NE];
    int tid = threadIdx.x;
    for (int i = tid; i < NE*DIMV; i += blockDim.x)
        sWT[(i >> 4)*20 + (i & 15)] = Wg[i];
    if (tid < NE) { s_imp[tid] = 0.f; s_bg[tid] = bg[tid]; }
    if (tid == 0) s_ent = 0.f;
    __syncthreads();

    int warp = tid >> 5, lane = tid & 31;
    int q = lane & 3;
    int t = blockIdx.x * 64 + warp * 8 + (lane >> 2);
    const float* x = ctx + (size_t)t * DIMV;

    float acc[NE];
#pragma unroll
    for (int e = 0; e < NE; e++) acc[e] = 0.f;
#pragma unroll 16
    for (int i = 0; i < 64; i++) {
        int d = i*4 + q;
        float xv = x[d];
        const float4* wrow = (const float4*)&sWT[d*20];
#pragma unroll
        for (int e4 = 0; e4 < 4; e4++) {
            float4 w = wrow[e4];
            acc[e4*4+0] += xv * w.x;
            acc[e4*4+1] += xv * w.y;
            acc[e4*4+2] += xv * w.z;
            acc[e4*4+3] += xv * w.w;
        }
    }
    // reduce over the 4-lane q-group; all 4 lanes end with full logits
#pragma unroll
    for (int e = 0; e < NE; e++) {
        acc[e] += __shfl_xor_sync(0xffffffffu, acc[e], 1);
        acc[e] += __shfl_xor_sync(0xffffffffu, acc[e], 2);
        acc[e] += s_bg[e];
    }

    // softmax stats (computed redundantly on all 4 q-lanes; free)
    float m = acc[0];
#pragma unroll
    for (int e = 1; e < NE; e++) m = fmaxf(m, acc[e]);
    float sum = 0.f;
    float p[NE];
#pragma unroll
    for (int e = 0; e < NE; e++) { p[e] = __expf(acc[e] - m); sum += p[e]; }
    float inv = 1.f / sum;
    float ent = 0.f;
#pragma unroll
    for (int e = 0; e < NE; e++) {
        p[e] *= inv;
        ent -= p[e] * __logf(fmaxf(p[e], 1e-9f));
    }
    // sum p[e] and ent over the 8 tokens (offsets 4,8,16; q-duplicates equal)
#pragma unroll
    for (int e = 0; e < NE; e++) {
        p[e] += __shfl_xor_sync(0xffffffffu, p[e], 4);
        p[e] += __shfl_xor_sync(0xffffffffu, p[e], 8);
        p[e] += __shfl_xor_sync(0xffffffffu, p[e], 16);
    }
    ent += __shfl_xor_sync(0xffffffffu, ent, 4);
    ent += __shfl_xor_sync(0xffffffffu, ent, 8);
    ent += __shfl_xor_sync(0xffffffffu, ent, 16);
    if (lane == 0) {
#pragma unroll
        for (int e = 0; e < NE; e++) atomicAdd(&s_imp[e], p[e]);
        atomicAdd(&s_ent, ent);
    }

    // top-2 + gates; q==0 lane commits
    if (q == 0) {
        int i0 = 0; float v0 = acc[0];
#pragma unroll
        for (int e = 1; e < NE; e++) if (acc[e] > v0) { v0 = acc[e]; i0 = e; }
        int i1 = (i0 == 0) ? 1 : 0; float v1 = acc[i1];
#pragma unroll
        for (int e = 0; e < NE; e++)
            if (e != i0 && acc[e] > v1) { v1 = acc[e]; i1 = e; }
        float ex = __expf(v1 - v0);
        float gg0 = 1.f / (1.f + ex);
        float gg1 = ex / (1.f + ex);
        int s0 = 2*t, s1 = 2*t + 1;
        g_expert[s0] = i0; g_expert[s1] = i1;
        g_gate[s0] = gg0;  g_gate[s1] = gg1;
        atomicAdd(&g_counts[i0], 1);
        atomicAdd(&g_counts[i1], 1);
        atomicAdd(&g_hist[i0*NB + (int)(__float_as_uint(gg0) >> 17)], 1);
        atomicAdd(&g_hist[i1*NB + (int)(__float_as_uint(gg1) >> 17)], 1);
    }
    __syncthreads();
    if (tid < NE) atomicAdd(&g_imp[tid], s_imp[tid]);
    if (tid == 0) atomicAdd(&g_ent, s_ent);

    // fused fp16 conversion of this block's 64 tokens
    {
        const float4* src = (const float4*)(ctx + (size_t)blockIdx.x * 64 * DIMV);
        uint2* dst = (uint2*)(g_ctx_h + (size_t)blockIdx.x * 64 * DIMV);
#pragma unroll
        for (int i = 0; i < 16; i++) {
            int j = tid + i*256;
            float4 v = src[j];
            uint2 pk;
            pk.x = packh(__float2half_rn(v.x), __float2half_rn(v.y));
            pk.y = packh(__float2half_rn(v.z), __float2half_rn(v.w));
            dst[j] = pk;
        }
    }
}

// ---------------- capacity cutoff --------------------------------------------
__global__ void k_cutoff() {
    int e = blockIdx.x, tid = threadIdx.x;
    __shared__ int chunk[256], suffix[256];
    if (g_counts[e] <= CAP) {
        if (tid == 0) { g_bstar[e] = -1; g_rrem[e] = 0; }
        return;
    }
    const int* h = g_hist + e*NB;
    int b0 = tid * 128;
    int s = 0;
    for (int b = b0; b < b0 + 128; b++) s += h[b];
    chunk[tid] = s;
    __syncthreads();
    if (tid == 0) {
        int run = 0;
        for (int i = 255; i >= 0; i--) { suffix[i] = run; run += chunk[i]; }
    }
    __syncthreads();
    int cum = suffix[tid];
    for (int b = b0 + 127; b >= b0; b--) {
        int hb = h[b];
        if (cum < CAP && cum + hb >= CAP) {
            g_bstar[e] = b; g_rrem[e] = CAP - cum;
        }
        cum += hb;
    }
}

__global__ void k_flags() {
    int s = blockIdx.x * blockDim.x + threadIdx.x;
    if (s >= NSLOT) return;
    int e = g_expert[s];
    unsigned char kept;
    if (g_counts[e] <= CAP) kept = 1;
    else {
        int b  = (int)(__float_as_uint(g_gate[s]) >> 17);
        int bs = g_bstar[e];
        if (b > bs) kept = 1;
        else if (b < bs) kept = 0;
        else {
            kept = 0;
            int p = atomicAdd(&g_btotal, 1);
            g_blist[p] = s;
        }
    }
    g_kept[s] = kept;
}

__global__ void k_boundary() {
    int total = g_btotal;
    for (int i = blockIdx.x * blockDim.x + threadIdx.x; i < total;
         i += gridDim.x * blockDim.x) {
        int si = g_blist[i];
        int e  = g_expert[si];
        unsigned int ki = __float_as_uint(g_gate[si]);
        int better = 0;
        for (int j = 0; j < total; j++) {
            int sj = g_blist[j];
            if (g_expert[sj] != e) continue;
            unsigned int kj = __float_as_uint(g_gate[sj]);
            better += (kj > ki) || (kj == ki && sj < si);
        }
        if (better < g_rrem[e]) g_kept[si] = 1;
    }
}

__global__ void k_compact() {
    __shared__ int scnt[NE], sbase[NE];
    int tid = threadIdx.x;
    int s = blockIdx.x * 256 + tid;
    if (tid < NE) scnt[tid] = 0;
    __syncthreads();
    int e = -1, rank = 0;
    if (s < NSLOT && g_kept[s]) {
        e = g_expert[s];
        rank = atomicAdd(&scnt[e], 1);
    }
    __syncthreads();
    if (tid < NE && scnt[tid] > 0) sbase[tid] = atomicAdd(&g_cursor[tid], scnt[tid]);
    __syncthreads();
    if (e >= 0) g_perm[e*CAP + sbase[e] + rank] = s;
}

// ---------------- GEMM1: H = relu(Xg @ W1 + b1), 128x256 tile, 3-stage -------
__global__ void __launch_bounds__(256, 1)
k_gemm1_mma(const float* __restrict__ b1) {
    int e = blockIdx.z;
    int Me = min(g_counts[e], CAP);
    int m0 = blockIdx.x * 128;
    if (m0 >= Me) return;
    int n0 = blockIdx.y * 256;

    extern __shared__ __align__(16) char smem[];
    uint32_t sb = smem_u32(smem);
    int tid = threadIdx.x;
    int* stok = (int*)smem;
    if (tid < 128) {
        int gr = m0 + tid;
        stok[tid] = (gr < Me) ? (g_perm[e*CAP + gr] >> 1) : -1;
    }
    __syncthreads();

    const __half* W = g_w1t + (size_t)e * HID * DIMV;

    auto fill = [&](int stage, int c) {
#pragma unroll
        for (int i = 0; i < 2; i++) {
            int j = tid + i*256;
            int row = j >> 2, ch = j & 3;
            int tok = stok[row];
            cpasync16(sb + G1_A + stage*ASTG + row*AROWB + ch*16,
                      g_ctx_h + (size_t)max(tok, 0)*DIMV + c*32 + ch*8,
                      tok >= 0 ? 16 : 0);
        }
#pragma unroll
        for (int i = 0; i < 4; i++) {
            int j = tid + i*256;
            int row = j >> 2, ch = j & 3;
            cpasync16(sb + G1_B + stage*BSTG + row*AROWB + ch*16,
                      W + (size_t)(n0 + row)*DIMV + c*32 + ch*8, 16);
        }
        CP_COMMIT();
    };

    int warp = tid >> 5, lane = tid & 31;
    int g = lane >> 2, tg = lane & 3;
    int wm = (warp & 1) * 64, wn = (warp >> 1) * 64;
    uint32_t aOff = (uint32_t)(wm + (lane & 7) + ((lane >> 3) & 1)*8) * AROWB
                    + ((lane >> 4) & 1)*16;
    uint32_t bOff = (uint32_t)(wn + ((lane >> 4) & 1)*8 + (lane & 7)) * AROWB
                    + ((lane >> 3) & 1)*16;

    float acc[4][8][4];
#pragma unroll
    for (int a = 0; a < 4; a++)
#pragma unroll
        for (int b = 0; b < 8; b++)
#pragma unroll
            for (int cc = 0; cc < 4; cc++) acc[a][b][cc] = 0.f;

    fill(0, 0); fill(1, 1);
    const int NCH = DIMV / 32;  // 8
    for (int c = 0; c < NCH; c++) {
        if (c + 1 < NCH) CP_WAIT1(); else CP_WAIT0();
        __syncthreads();
        if (c + 2 < NCH) fill((c + 2) % 3, c + 2);
        uint32_t Ab = sb + G1_A + (c % 3)*ASTG + aOff;
        uint32_t Bb = sb + G1_B + (c % 3)*BSTG + bOff;
#pragma unroll
        for (int s = 0; s < 2; s++) {
            uint32_t Af[4][4], Bf[8][2];
#pragma unroll
            for (int mf = 0; mf < 4; mf++) ldsm4(Af[mf], Ab + mf*(16*AROWB) + s*32);
#pragma unroll
            for (int p = 0; p < 4; p++)  ldsm4(&Bf[2*p][0], Bb + p*(16*AROWB) + s*32);
#pragma unroll
            for (int mf = 0; mf < 4; mf++)
#pragma unroll
                for (int nf = 0; nf < 8; nf++)
                    mma16816(acc[mf][nf], Af[mf], Bf[nf]);
        }
    }

    const float* bias = b1 + (size_t)e * HID;
#pragma unroll
    for (int mf = 0; mf < 4; mf++) {
#pragma unroll
        for (int hv = 0; hv < 2; hv++) {
            int gr = m0 + wm + mf*16 + g + hv*8;
            if (gr >= Me) continue;
            __half* hh = g_hh + (size_t)(e*CAP + gr)*HID;
#pragma unroll
            for (int nf = 0; nf < 8; nf++) {
                int col = n0 + wn + nf*8 + tg*2;
                float2 bb = *(const float2*)(bias + col);
                float v0 = fmaxf(acc[mf][nf][hv*2+0] + bb.x, 0.f);
                float v1 = fmaxf(acc[mf][nf][hv*2+1] + bb.y, 0.f);
                *(uint32_t*)(hh + col) = packh(__float2half_rn(v0), __float2half_rn(v1));
            }
        }
    }
}

// ---------------- GEMM2: Y = (H @ W2 + b2)*gate, 128x256 tile, 3-stage -------
__global__ void __launch_bounds__(256, 1)
k_gemm2_mma(const float* __restrict__ b2) {
    int e = blockIdx.z;
    int Me = min(g_counts[e], CAP);
    int m0 = blockIdx.x * 128;
    if (m0 >= Me) return;

    extern __shared__ __align__(16) char smem[];
    uint32_t sb = smem_u32(smem);
    int tid = threadIdx.x;
    int* sslot = (int*)smem;
    float* sgate = (float*)(smem + 512);
    if (tid < 128) {
        int gr = m0 + tid;
        if (gr < Me) {
            int s = g_perm[e*CAP + gr];
            sslot[tid] = s; sgate[tid] = g_gate[s];
        } else { sslot[tid] = -1; sgate[tid] = 0.f; }
    }
    __syncthreads();

    const __half* W = g_w2t + (size_t)e * DIMV * HID;

    auto fill = [&](int stage, int c) {
#pragma unroll
        for (int i = 0; i < 2; i++) {
            int j = tid + i*256;
            int row = j >> 2, ch = j & 3;
            bool ok = (m0 + row) < Me;
            cpasync16(sb + G2_A + stage*ASTG + row*AROWB + ch*16,
                      g_hh + (size_t)(e*CAP + m0 + (ok ? row : 0))*HID + c*32 + ch*8,
                      ok ? 16 : 0);
        }
#pragma unroll
        for (int i = 0; i < 4; i++) {
            int j = tid + i*256;
            int row = j >> 2, ch = j & 3;
            cpasync16(sb + G2_B + stage*BSTG + row*AROWB + ch*16,
                      W + (size_t)row*HID + c*32 + ch*8, 16);
        }
        CP_COMMIT();
    };

    int warp = tid >> 5, lane = tid & 31;
    int g = lane >> 2, tg = lane & 3;
    int wm = (warp & 1) * 64, wn = (warp >> 1) * 64;
    uint32_t aOff = (uint32_t)(wm + (lane & 7) + ((lane >> 3) & 1)*8) * AROWB
                    + ((lane >> 4) & 1)*16;
    uint32_t bOff = (uint32_t)(wn + ((lane >> 4) & 1)*8 + (lane & 7)) * AROWB
                    + ((lane >> 3) & 1)*16;

    float acc[4][8][4];
#pragma unroll
    for (int a = 0; a < 4; a++)
#pragma unroll
        for (int b = 0; b < 8; b++)
#pragma unroll
            for (int cc = 0; cc < 4; cc++) acc[a][b][cc] = 0.f;

    fill(0, 0); fill(1, 1);
    const int NCH = HID / 32;  // 16
    for (int c = 0; c < NCH; c++) {
        if (c + 1 < NCH) CP_WAIT1(); else CP_WAIT0();
        __syncthreads();
        if (c + 2 < NCH) fill((c + 2) % 3, c + 2);
        uint32_t Ab = sb + G2_A + (c % 3)*ASTG + aOff;
        uint32_t Bb = sb + G2_B + (c % 3)*BSTG + bOff;
#pragma unroll
        for (int s = 0; s < 2; s++) {
            uint32_t Af[4][4], Bf[8][2];
#pragma unroll
            for (int mf = 0; mf < 4; mf++) ldsm4(Af[mf], Ab + mf*(16*AROWB) + s*32);
#pragma unroll
            for (int p = 0; p < 4; p++)  ldsm4(&Bf[2*p][0], Bb + p*(16*AROWB) + s*32);
#pragma unroll
            for (int mf = 0; mf < 4; mf++)
#pragma unroll
                for (int nf = 0; nf < 8; nf++)
                    mma16816(acc[mf][nf], Af[mf], Bf[nf]);
        }
    }

    const float* bias = b2 + (size_t)e * DIMV;
#pragma unroll
    for (int mf = 0; mf < 4; mf++) {
#pragma unroll
        for (int hv = 0; hv < 2; hv++) {
            int r = wm + mf*16 + g + hv*8;
            int slot = sslot[r];
            if (slot < 0) continue;
            float gate = sgate[r];
            __half* yr = g_y + (size_t)slot * DIMV;
#pragma unroll
            for (int nf = 0; nf < 8; nf++) {
                int col = wn + nf*8 + tg*2;
                float2 bb = *(const float2*)(bias + col);
                float v0 = (acc[mf][nf][hv*2+0] + bb.x) * gate;
                float v1 = (acc[mf][nf][hv*2+1] + bb.y) * gate;
                *(uint32_t*)(yr + col) = packh(__float2half_rn(v0), __float2half_rn(v1));
            }
        }
    }
}

// ---------------- combine (fp16 y) -------------------------------------------
__global__ void k_combine(float* __restrict__ out) {
    int idx = blockIdx.x * blockDim.x + threadIdx.x;
    if (idx >= NTOK * 32) return;
    int t = idx >> 5, f = idx & 31;
    float r[8];
#pragma unroll
    for (int i = 0; i < 8; i++) r[i] = 0.f;
    if (g_kept[2*t]) {
        uint4 a = *(const uint4*)(g_y + (size_t)(2*t)*DIMV + f*8);
        const uint32_t* w = (const uint32_t*)&a;
#pragma unroll
        for (int i = 0; i < 4; i++) {
            __half2 h2 = *(const __half2*)&w[i];
            float2 v = __half22float2(h2);
            r[2*i] += v.x; r[2*i+1] += v.y;
        }
    }
    if (g_kept[2*t + 1]) {
        uint4 a = *(const uint4*)(g_y + (size_t)(2*t+1)*DIMV + f*8);
        const uint32_t* w = (const uint32_t*)&a;
#pragma unroll
        for (int i = 0; i < 4; i++) {
            __half2 h2 = *(const __half2*)&w[i];
            float2 v = __half22float2(h2);
            r[2*i] += v.x; r[2*i+1] += v.y;
        }
    }
    float* o = out + (size_t)t*DIMV + f*8;
    *(float4*)o     = make_float4(r[0], r[1], r[2], r[3]);
    *(float4*)(o+4) = make_float4(r[4], r[5], r[6], r[7]);
}

// ---------------- finalize ---------------------------------------------------
__global__ void k_final(float* __restrict__ out, int out_size) {
    int lane = threadIdx.x;
    int c = (lane < NE) ? min(g_counts[lane], CAP) : 0;
    int tot = c;
#pragma unroll
    for (int off = 16; off; off >>= 1) tot += __shfl_xor_sync(0xffffffffu, tot, off);
    float denom = fmaxf((float)tot, 1.f);
    float aux = 0.f;
    if (lane < NE)
        aux = (g_imp[lane] / (float)NTOK) * ((float)c / denom) * (float)NE;
#pragma unroll
    for (int off = 16; off; off >>= 1) aux += __shfl_xor_sync(0xffffffffu, aux, off);
    int base = NTOK * DIMV;
    if (lane == 0 && out_size > base)     out[base]     = aux;
    if (lane == 0 && out_size > base + 1) out[base + 1] = g_ent / (float)NTOK;
    if (lane < NE && out_size > base + 2 + lane) out[base + 2 + lane] = (float)c;
}

// ---------------- launch -----------------------------------------------------
extern "C" void kernel_launch(void* const* d_in, const int* in_sizes, int n_in,
                              void* d_out, int out_size) {
    const float* ctx = (const float*)d_in[0];
    const float* Wg  = (const float*)d_in[1];
    const float* bg  = (const float*)d_in[2];
    const float* W1  = (const float*)d_in[3];
    const float* b1  = (const float*)d_in[4];
    const float* W2  = (const float*)d_in[5];
    const float* b2  = (const float*)d_in[6];
    float* out = (float*)d_out;

    static bool attr_done = false;
    if (!attr_done) {
        cudaFuncSetAttribute(k_gemm1_mma, cudaFuncAttributeMaxDynamicSharedMemorySize, G1_SZ);
        cudaFuncSetAttribute(k_gemm2_mma, cudaFuncAttributeMaxDynamicSharedMemorySize, G2_SZ);
        attr_done = true;
    }

    k_zero<<<512, 256>>>();
    k_transpose<<<dim3(HID/32, DIMV/32, NE), 256>>>(W1, 0, DIMV, HID);
    k_transpose<<<dim3(DIMV/32, HID/32, NE), 256>>>(W2, 1, HID, DIMV);
    k_router<<<NTOK/64, 256>>>(ctx, Wg, bg);
    k_cutoff<<<NE, 256>>>();
    k_flags<<<NSLOT/256, 256>>>();
    k_boundary<<<64, 256>>>();
    k_compact<<<(NSLOT + 255)/256, 256>>>();

    dim3 g1(MTILES, HID/256, NE);
    k_gemm1_mma<<<g1, 256, G1_SZ>>>(b1);
    dim3 g2(MTILES, 1, NE);
    k_gemm2_mma<<<g2, 256, G2_SZ>>>(b2);

    k_combine<<<(NTOK*32)/256, 256>>>(out);
    k_final<<<1, 32>>>(out, out_size);
}

// round 9
// speedup vs baseline: 3.8897x; 1.0049x over previous
#include <cuda_runtime.h>
#include <cuda_fp16.h>
#include <math.h>
#include <stdint.h>

#define NTOK  131072
#define DIMV  256
#define HID   512
#define NE    16
#define CAP   18023
#define NSLOT (NTOK*2)
#define ECAP  (NE*CAP)
#define NB    32768
#define MTILES ((CAP+127)/128)

// ---------------- scratch (static device globals) ----------------------------
__device__ float g_gate[NSLOT];
__device__ int   g_expert[NSLOT];
__device__ unsigned char g_kept[NSLOT];
__device__ int   g_counts[NE];
__device__ int   g_cursor[NE];
__device__ int   g_perm[ECAP];
__device__ int   g_hist[NE*NB];
__device__ int   g_bstar[NE], g_rrem[NE];
__device__ int   g_blist[NSLOT];
__device__ int   g_btotal;
__device__ float g_imp[NE];
__device__ float g_ent;

__device__ __half g_ctx_h[(size_t)NTOK * DIMV];
__device__ __half g_w1t[(size_t)NE * HID * DIMV];   // [e][h][d]
__device__ __half g_w2t[(size_t)NE * DIMV * HID];   // [e][d][h]
__device__ __half g_hh[(size_t)ECAP * HID];
__device__ __half g_y[(size_t)NSLOT * DIMV];

// ---------------- helpers ----------------------------------------------------
__device__ __forceinline__ uint32_t smem_u32(const void* p) {
    uint32_t a;
    asm("{ .reg .u64 t; cvta.to.shared.u64 t, %1; cvt.u32.u64 %0, t; }"
        : "=r"(a) : "l"(p));
    return a;
}
__device__ __forceinline__ void cpasync16(uint32_t dst, const void* src, int srcsz) {
    asm volatile("cp.async.cg.shared.global [%0], [%1], 16, %2;"
                 :: "r"(dst), "l"(src), "r"(srcsz) : "memory");
}
#define CP_COMMIT() asm volatile("cp.async.commit_group;" ::: "memory")
#define CP_WAIT1()  asm volatile("cp.async.wait_group 1;" ::: "memory")
#define CP_WAIT0()  asm volatile("cp.async.wait_group 0;" ::: "memory")

__device__ __forceinline__ void ldsm4(uint32_t* r, uint32_t addr) {
    asm volatile("ldmatrix.sync.aligned.m8n8.x4.shared.b16 {%0,%1,%2,%3}, [%4];"
                 : "=r"(r[0]), "=r"(r[1]), "=r"(r[2]), "=r"(r[3]) : "r"(addr));
}
__device__ __forceinline__ void mma16816(float* c, const uint32_t* a, const uint32_t* b) {
    asm volatile(
        "mma.sync.aligned.m16n8k16.row.col.f32.f16.f16.f32 "
        "{%0,%1,%2,%3}, {%4,%5,%6,%7}, {%8,%9}, {%0,%1,%2,%3};"
        : "+f"(c[0]), "+f"(c[1]), "+f"(c[2]), "+f"(c[3])
        : "r"(a[0]), "r"(a[1]), "r"(a[2]), "r"(a[3]), "r"(b[0]), "r"(b[1]));
}
__device__ __forceinline__ uint32_t packh(__half a, __half b) {
    return (uint32_t)__half_as_ushort(a) | ((uint32_t)__half_as_ushort(b) << 16);
}

// padded smem row: 32 fp16 + 8 pad = 80 bytes (conflict-free for LDSM/cp.async)
#define AROWB 80
#define ASTG  10240            // 128 rows
#define BSTG  20480            // 256 rows
#define G1_A  512
#define G1_B  (G1_A + 3*ASTG)
#define G1_SZ (G1_B + 3*BSTG)
#define G2_A  1024
#define G2_B  (G2_A + 3*ASTG)
#define G2_SZ (G2_B + 3*BSTG)

// ---------------- zero -------------------------------------------------------
__global__ void k_zero() {
    int i = blockIdx.x * blockDim.x + threadIdx.x;
    for (int j = i; j < NE*NB; j += gridDim.x * blockDim.x) g_hist[j] = 0;
    if (i < NE) { g_counts[i] = 0; g_cursor[i] = 0; g_imp[i] = 0.f; }
    if (i == 0) { g_ent = 0.f; g_btotal = 0; }
}

// ---------------- coalesced transpose + fp16 convert -------------------------
__global__ void k_transpose(const float* __restrict__ src, int which, int R, int C) {
    __shared__ float tile[32][33];
    __half* dstg = which ? g_w2t : g_w1t;
    int e = blockIdx.z;
    const float* S = src + (size_t)e * R * C;
    __half* D = dstg + (size_t)e * R * C;
    int c0 = blockIdx.x * 32, r0 = blockIdx.y * 32;
    int tc = threadIdx.x & 31, tr4 = threadIdx.x >> 5;
#pragma unroll
    for (int i = 0; i < 4; i++) {
        int r = tr4 + i*8;
        tile[r][tc] = S[(size_t)(r0 + r)*C + c0 + tc];
    }
    __syncthreads();
#pragma unroll
    for (int i = 0; i < 4; i++) {
        int r = tr4 + i*8;
        D[(size_t)(c0 + r)*R + r0 + tc] = __float2half_rn(tile[tc][r]);
    }
}

// ---------------- router: 4 threads/token, 8 tokens/warp ---------------------
// sWT[d][e] padded to stride 20 floats; thread q owns d = 4i+q (bank-safe).
// Register diet: top-2 computed first (m = v0), then acc[] overwritten in place
// with softmax probs (no separate p[16]) -> ~32 live regs -> high occupancy.
__global__ void k_router(const float* __restrict__ ctx,
                         const float* __restrict__ Wg,
                         const float* __restrict__ bg) {
    __shared__ float sWT[DIMV*20];
    __shared__ float s_imp[NE];
    __shared__ float s_ent;
    __shared__ float s_bg[NE];
    int tid = threadIdx.x;
    for (int i = tid; i < NE*DIMV; i += blockDim.x)
        sWT[(i >> 4)*20 + (i & 15)] = Wg[i];
    if (tid < NE) { s_imp[tid] = 0.f; s_bg[tid] = bg[tid]; }
    if (tid == 0) s_ent = 0.f;
    __syncthreads();

    int warp = tid >> 5, lane = tid & 31;
    int q = lane & 3;
    int t = blockIdx.x * 64 + warp * 8 + (lane >> 2);
    const float* x = ctx + (size_t)t * DIMV;

    float acc[NE];
#pragma unroll
    for (int e = 0; e < NE; e++) acc[e] = 0.f;
#pragma unroll 16
    for (int i = 0; i < 64; i++) {
        int d = i*4 + q;
        float xv = x[d];
        const float4* wrow = (const float4*)&sWT[d*20];
#pragma unroll
        for (int e4 = 0; e4 < 4; e4++) {
            float4 w = wrow[e4];
            acc[e4*4+0] += xv * w.x;
            acc[e4*4+1] += xv * w.y;
            acc[e4*4+2] += xv * w.z;
            acc[e4*4+3] += xv * w.w;
        }
    }
    // reduce over the 4-lane q-group; all 4 lanes end with full logits
#pragma unroll
    for (int e = 0; e < NE; e++) {
        acc[e] += __shfl_xor_sync(0xffffffffu, acc[e], 1);
        acc[e] += __shfl_xor_sync(0xffffffffu, acc[e], 2);
        acc[e] += s_bg[e];
    }

    // top-2 first (all q-lanes compute redundantly; q==0 commits later)
    int i0 = 0; float v0 = acc[0];
#pragma unroll
    for (int e = 1; e < NE; e++) if (acc[e] > v0) { v0 = acc[e]; i0 = e; }
    int i1 = (i0 == 0) ? 1 : 0; float v1 = acc[i1];
#pragma unroll
    for (int e = 0; e < NE; e++)
        if (e != i0 && acc[e] > v1) { v1 = acc[e]; i1 = e; }

    // softmax stats in place: m = v0 (top-1 IS the max)
    float sum = 0.f;
#pragma unroll
    for (int e = 0; e < NE; e++) { acc[e] = __expf(acc[e] - v0); sum += acc[e]; }
    float inv = 1.f / sum;
    float ent = 0.f;
#pragma unroll
    for (int e = 0; e < NE; e++) {
        acc[e] *= inv;
        ent -= acc[e] * __logf(fmaxf(acc[e], 1e-9f));
    }
    // sum probs and ent over the 8 tokens (offsets 4,8,16; q-duplicates equal)
#pragma unroll
    for (int e = 0; e < NE; e++) {
        acc[e] += __shfl_xor_sync(0xffffffffu, acc[e], 4);
        acc[e] += __shfl_xor_sync(0xffffffffu, acc[e], 8);
        acc[e] += __shfl_xor_sync(0xffffffffu, acc[e], 16);
    }
    ent += __shfl_xor_sync(0xffffffffu, ent, 4);
    ent += __shfl_xor_sync(0xffffffffu, ent, 8);
    ent += __shfl_xor_sync(0xffffffffu, ent, 16);
    if (lane == 0) {
#pragma unroll
        for (int e = 0; e < NE; e++) atomicAdd(&s_imp[e], acc[e]);
        atomicAdd(&s_ent, ent);
    }

    // commit gates; q==0 lane of each token
    if (q == 0) {
        float ex = __expf(v1 - v0);
        float gg0 = 1.f / (1.f + ex);
        float gg1 = ex / (1.f + ex);
        int s0 = 2*t, s1 = 2*t + 1;
        g_expert[s0] = i0; g_expert[s1] = i1;
        g_gate[s0] = gg0;  g_gate[s1] = gg1;
        atomicAdd(&g_counts[i0], 1);
        atomicAdd(&g_counts[i1], 1);
        atomicAdd(&g_hist[i0*NB + (int)(__float_as_uint(gg0) >> 17)], 1);
        atomicAdd(&g_hist[i1*NB + (int)(__float_as_uint(gg1) >> 17)], 1);
    }
    __syncthreads();
    if (tid < NE) atomicAdd(&g_imp[tid], s_imp[tid]);
    if (tid == 0) atomicAdd(&g_ent, s_ent);

    // fused fp16 conversion of this block's 64 tokens
    {
        const float4* src = (const float4*)(ctx + (size_t)blockIdx.x * 64 * DIMV);
        uint2* dst = (uint2*)(g_ctx_h + (size_t)blockIdx.x * 64 * DIMV);
#pragma unroll
        for (int i = 0; i < 16; i++) {
            int j = tid + i*256;
            float4 v = src[j];
            uint2 pk;
            pk.x = packh(__float2half_rn(v.x), __float2half_rn(v.y));
            pk.y = packh(__float2half_rn(v.z), __float2half_rn(v.w));
            dst[j] = pk;
        }
    }
}

// ---------------- capacity cutoff --------------------------------------------
__global__ void k_cutoff() {
    int e = blockIdx.x, tid = threadIdx.x;
    __shared__ int chunk[256], suffix[256];
    if (g_counts[e] <= CAP) {
        if (tid == 0) { g_bstar[e] = -1; g_rrem[e] = 0; }
        return;
    }
    const int* h = g_hist + e*NB;
    int b0 = tid * 128;
    int s = 0;
    for (int b = b0; b < b0 + 128; b++) s += h[b];
    chunk[tid] = s;
    __syncthreads();
    if (tid == 0) {
        int run = 0;
        for (int i = 255; i >= 0; i--) { suffix[i] = run; run += chunk[i]; }
    }
    __syncthreads();
    int cum = suffix[tid];
    for (int b = b0 + 127; b >= b0; b--) {
        int hb = h[b];
        if (cum < CAP && cum + hb >= CAP) {
            g_bstar[e] = b; g_rrem[e] = CAP - cum;
        }
        cum += hb;
    }
}

__global__ void k_flags() {
    int s = blockIdx.x * blockDim.x + threadIdx.x;
    if (s >= NSLOT) return;
    int e = g_expert[s];
    unsigned char kept;
    if (g_counts[e] <= CAP) kept = 1;
    else {
        int b  = (int)(__float_as_uint(g_gate[s]) >> 17);
        int bs = g_bstar[e];
        if (b > bs) kept = 1;
        else if (b < bs) kept = 0;
        else {
            kept = 0;
            int p = atomicAdd(&g_btotal, 1);
            g_blist[p] = s;
        }
    }
    g_kept[s] = kept;
}

__global__ void k_boundary() {
    int total = g_btotal;
    for (int i = blockIdx.x * blockDim.x + threadIdx.x; i < total;
         i += gridDim.x * blockDim.x) {
        int si = g_blist[i];
        int e  = g_expert[si];
        unsigned int ki = __float_as_uint(g_gate[si]);
        int better = 0;
        for (int j = 0; j < total; j++) {
            int sj = g_blist[j];
            if (g_expert[sj] != e) continue;
            unsigned int kj = __float_as_uint(g_gate[sj]);
            better += (kj > ki) || (kj == ki && sj < si);
        }
        if (better < g_rrem[e]) g_kept[si] = 1;
    }
}

__global__ void k_compact() {
    __shared__ int scnt[NE], sbase[NE];
    int tid = threadIdx.x;
    int s = blockIdx.x * 256 + tid;
    if (tid < NE) scnt[tid] = 0;
    __syncthreads();
    int e = -1, rank = 0;
    if (s < NSLOT && g_kept[s]) {
        e = g_expert[s];
        rank = atomicAdd(&scnt[e], 1);
    }
    __syncthreads();
    if (tid < NE && scnt[tid] > 0) sbase[tid] = atomicAdd(&g_cursor[tid], scnt[tid]);
    __syncthreads();
    if (e >= 0) g_perm[e*CAP + sbase[e] + rank] = s;
}

// ---------------- GEMM1: H = relu(Xg @ W1 + b1), 128x256 tile, 3-stage -------
__global__ void __launch_bounds__(256, 1)
k_gemm1_mma(const float* __restrict__ b1) {
    int e = blockIdx.z;
    int Me = min(g_counts[e], CAP);
    int m0 = blockIdx.x * 128;
    if (m0 >= Me) return;
    int n0 = blockIdx.y * 256;

    extern __shared__ __align__(16) char smem[];
    uint32_t sb = smem_u32(smem);
    int tid = threadIdx.x;
    int* stok = (int*)smem;
    if (tid < 128) {
        int gr = m0 + tid;
        stok[tid] = (gr < Me) ? (g_perm[e*CAP + gr] >> 1) : -1;
    }
    __syncthreads();

    const __half* W = g_w1t + (size_t)e * HID * DIMV;

    auto fill = [&](int stage, int c) {
#pragma unroll
        for (int i = 0; i < 2; i++) {
            int j = tid + i*256;
            int row = j >> 2, ch = j & 3;
            int tok = stok[row];
            cpasync16(sb + G1_A + stage*ASTG + row*AROWB + ch*16,
                      g_ctx_h + (size_t)max(tok, 0)*DIMV + c*32 + ch*8,
                      tok >= 0 ? 16 : 0);
        }
#pragma unroll
        for (int i = 0; i < 4; i++) {
            int j = tid + i*256;
            int row = j >> 2, ch = j & 3;
            cpasync16(sb + G1_B + stage*BSTG + row*AROWB + ch*16,
                      W + (size_t)(n0 + row)*DIMV + c*32 + ch*8, 16);
        }
        CP_COMMIT();
    };

    int warp = tid >> 5, lane = tid & 31;
    int g = lane >> 2, tg = lane & 3;
    int wm = (warp & 1) * 64, wn = (warp >> 1) * 64;
    uint32_t aOff = (uint32_t)(wm + (lane & 7) + ((lane >> 3) & 1)*8) * AROWB
                    + ((lane >> 4) & 1)*16;
    uint32_t bOff = (uint32_t)(wn + ((lane >> 4) & 1)*8 + (lane & 7)) * AROWB
                    + ((lane >> 3) & 1)*16;

    float acc[4][8][4];
#pragma unroll
    for (int a = 0; a < 4; a++)
#pragma unroll
        for (int b = 0; b < 8; b++)
#pragma unroll
            for (int cc = 0; cc < 4; cc++) acc[a][b][cc] = 0.f;

    fill(0, 0); fill(1, 1);
    const int NCH = DIMV / 32;  // 8
    for (int c = 0; c < NCH; c++) {
        if (c + 1 < NCH) CP_WAIT1(); else CP_WAIT0();
        __syncthreads();
        if (c + 2 < NCH) fill((c + 2) % 3, c + 2);
        uint32_t Ab = sb + G1_A + (c % 3)*ASTG + aOff;
        uint32_t Bb = sb + G1_B + (c % 3)*BSTG + bOff;
#pragma unroll
        for (int s = 0; s < 2; s++) {
            uint32_t Af[4][4], Bf[8][2];
#pragma unroll
            for (int mf = 0; mf < 4; mf++) ldsm4(Af[mf], Ab + mf*(16*AROWB) + s*32);
#pragma unroll
            for (int p = 0; p < 4; p++)  ldsm4(&Bf[2*p][0], Bb + p*(16*AROWB) + s*32);
#pragma unroll
            for (int mf = 0; mf < 4; mf++)
#pragma unroll
                for (int nf = 0; nf < 8; nf++)
                    mma16816(acc[mf][nf], Af[mf], Bf[nf]);
        }
    }

    const float* bias = b1 + (size_t)e * HID;
#pragma unroll
    for (int mf = 0; mf < 4; mf++) {
#pragma unroll
        for (int hv = 0; hv < 2; hv++) {
            int gr = m0 + wm + mf*16 + g + hv*8;
            if (gr >= Me) continue;
            __half* hh = g_hh + (size_t)(e*CAP + gr)*HID;
#pragma unroll
            for (int nf = 0; nf < 8; nf++) {
                int col = n0 + wn + nf*8 + tg*2;
                float2 bb = *(const float2*)(bias + col);
                float v0 = fmaxf(acc[mf][nf][hv*2+0] + bb.x, 0.f);
                float v1 = fmaxf(acc[mf][nf][hv*2+1] + bb.y, 0.f);
                *(uint32_t*)(hh + col) = packh(__float2half_rn(v0), __float2half_rn(v1));
            }
        }
    }
}

// ---------------- GEMM2: Y = (H @ W2 + b2)*gate, 128x256 tile, 3-stage -------
__global__ void __launch_bounds__(256, 1)
k_gemm2_mma(const float* __restrict__ b2) {
    int e = blockIdx.z;
    int Me = min(g_counts[e], CAP);
    int m0 = blockIdx.x * 128;
    if (m0 >= Me) return;

    extern __shared__ __align__(16) char smem[];
    uint32_t sb = smem_u32(smem);
    int tid = threadIdx.x;
    int* sslot = (int*)smem;
    float* sgate = (float*)(smem + 512);
    if (tid < 128) {
        int gr = m0 + tid;
        if (gr < Me) {
            int s = g_perm[e*CAP + gr];
            sslot[tid] = s; sgate[tid] = g_gate[s];
        } else { sslot[tid] = -1; sgate[tid] = 0.f; }
    }
    __syncthreads();

    const __half* W = g_w2t + (size_t)e * DIMV * HID;

    auto fill = [&](int stage, int c) {
#pragma unroll
        for (int i = 0; i < 2; i++) {
            int j = tid + i*256;
            int row = j >> 2, ch = j & 3;
            bool ok = (m0 + row) < Me;
            cpasync16(sb + G2_A + stage*ASTG + row*AROWB + ch*16,
                      g_hh + (size_t)(e*CAP + m0 + (ok ? row : 0))*HID + c*32 + ch*8,
                      ok ? 16 : 0);
        }
#pragma unroll
        for (int i = 0; i < 4; i++) {
            int j = tid + i*256;
            int row = j >> 2, ch = j & 3;
            cpasync16(sb + G2_B + stage*BSTG + row*AROWB + ch*16,
                      W + (size_t)row*HID + c*32 + ch*8, 16);
        }
        CP_COMMIT();
    };

    int warp = tid >> 5, lane = tid & 31;
    int g = lane >> 2, tg = lane & 3;
    int wm = (warp & 1) * 64, wn = (warp >> 1) * 64;
    uint32_t aOff = (uint32_t)(wm + (lane & 7) + ((lane >> 3) & 1)*8) * AROWB
                    + ((lane >> 4) & 1)*16;
    uint32_t bOff = (uint32_t)(wn + ((lane >> 4) & 1)*8 + (lane & 7)) * AROWB
                    + ((lane >> 3) & 1)*16;

    float acc[4][8][4];
#pragma unroll
    for (int a = 0; a < 4; a++)
#pragma unroll
        for (int b = 0; b < 8; b++)
#pragma unroll
            for (int cc = 0; cc < 4; cc++) acc[a][b][cc] = 0.f;

    fill(0, 0); fill(1, 1);
    const int NCH = HID / 32;  // 16
    for (int c = 0; c < NCH; c++) {
        if (c + 1 < NCH) CP_WAIT1(); else CP_WAIT0();
        __syncthreads();
        if (c + 2 < NCH) fill((c + 2) % 3, c + 2);
        uint32_t Ab = sb + G2_A + (c % 3)*ASTG + aOff;
        uint32_t Bb = sb + G2_B + (c % 3)*BSTG + bOff;
#pragma unroll
        for (int s = 0; s < 2; s++) {
            uint32_t Af[4][4], Bf[8][2];
#pragma unroll
            for (int mf = 0; mf < 4; mf++) ldsm4(Af[mf], Ab + mf*(16*AROWB) + s*32);
#pragma unroll
            for (int p = 0; p < 4; p++)  ldsm4(&Bf[2*p][0], Bb + p*(16*AROWB) + s*32);
#pragma unroll
            for (int mf = 0; mf < 4; mf++)
#pragma unroll
                for (int nf = 0; nf < 8; nf++)
                    mma16816(acc[mf][nf], Af[mf], Bf[nf]);
        }
    }

    const float* bias = b2 + (size_t)e * DIMV;
#pragma unroll
    for (int mf = 0; mf < 4; mf++) {
#pragma unroll
        for (int hv = 0; hv < 2; hv++) {
            int r = wm + mf*16 + g + hv*8;
            int slot = sslot[r];
            if (slot < 0) continue;
            float gate = sgate[r];
            __half* yr = g_y + (size_t)slot * DIMV;
#pragma unroll
            for (int nf = 0; nf < 8; nf++) {
                int col = wn + nf*8 + tg*2;
                float2 bb = *(const float2*)(bias + col);
                float v0 = (acc[mf][nf][hv*2+0] + bb.x) * gate;
                float v1 = (acc[mf][nf][hv*2+1] + bb.y) * gate;
                *(uint32_t*)(yr + col) = packh(__float2half_rn(v0), __float2half_rn(v1));
            }
        }
    }
}

// ---------------- combine (fp16 y) -------------------------------------------
__global__ void k_combine(float* __restrict__ out) {
    int idx = blockIdx.x * blockDim.x + threadIdx.x;
    if (idx >= NTOK * 32) return;
    int t = idx >> 5, f = idx & 31;
    float r[8];
#pragma unroll
    for (int i = 0; i < 8; i++) r[i] = 0.f;
    if (g_kept[2*t]) {
        uint4 a = *(const uint4*)(g_y + (size_t)(2*t)*DIMV + f*8);
        const uint32_t* w = (const uint32_t*)&a;
#pragma unroll
        for (int i = 0; i < 4; i++) {
            __half2 h2 = *(const __half2*)&w[i];
            float2 v = __half22float2(h2);
            r[2*i] += v.x; r[2*i+1] += v.y;
        }
    }
    if (g_kept[2*t + 1]) {
        uint4 a = *(const uint4*)(g_y + (size_t)(2*t+1)*DIMV + f*8);
        const uint32_t* w = (const uint32_t*)&a;
#pragma unroll
        for (int i = 0; i < 4; i++) {
            __half2 h2 = *(const __half2*)&w[i];
            float2 v = __half22float2(h2);
            r[2*i] += v.x; r[2*i+1] += v.y;
        }
    }
    float* o = out + (size_t)t*DIMV + f*8;
    *(float4*)o     = make_float4(r[0], r[1], r[2], r[3]);
    *(float4*)(o+4) = make_float4(r[4], r[5], r[6], r[7]);
}

// ---------------- finalize ---------------------------------------------------
__global__ void k_final(float* __restrict__ out, int out_size) {
    int lane = threadIdx.x;
    int c = (lane < NE) ? min(g_counts[lane], CAP) : 0;
    int tot = c;
#pragma unroll
    for (int off = 16; off; off >>= 1) tot += __shfl_xor_sync(0xffffffffu, tot, off);
    float denom = fmaxf((float)tot, 1.f);
    float aux = 0.f;
    if (lane < NE)
        aux = (g_imp[lane] / (float)NTOK) * ((float)c / denom) * (float)NE;
#pragma unroll
    for (int off = 16; off; off >>= 1) aux += __shfl_xor_sync(0xffffffffu, aux, off);
    int base = NTOK * DIMV;
    if (lane == 0 && out_size > base)     out[base]     = aux;
    if (lane == 0 && out_size > base + 1) out[base + 1] = g_ent / (float)NTOK;
    if (lane < NE && out_size > base + 2 + lane) out[base + 2 + lane] = (float)c;
}

// ---------------- launch -----------------------------------------------------
extern "C" void kernel_launch(void* const* d_in, const int* in_sizes, int n_in,
                              void* d_out, int out_size) {
    const float* ctx = (const float*)d_in[0];
    const float* Wg  = (const float*)d_in[1];
    const float* bg  = (const float*)d_in[2];
    const float* W1  = (const float*)d_in[3];
    const float* b1  = (const float*)d_in[4];
    const float* W2  = (const float*)d_in[5];
    const float* b2  = (const float*)d_in[6];
    float* out = (float*)d_out;

    static bool attr_done = false;
    if (!attr_done) {
        cudaFuncSetAttribute(k_gemm1_mma, cudaFuncAttributeMaxDynamicSharedMemorySize, G1_SZ);
        cudaFuncSetAttribute(k_gemm2_mma, cudaFuncAttributeMaxDynamicSharedMemorySize, G2_SZ);
        attr_done = true;
    }

    k_zero<<<512, 256>>>();
    k_transpose<<<dim3(HID/32, DIMV/32, NE), 256>>>(W1, 0, DIMV, HID);
    k_transpose<<<dim3(DIMV/32, HID/32, NE), 256>>>(W2, 1, HID, DIMV);
    k_router<<<NTOK/64, 256>>>(ctx, Wg, bg);
    k_cutoff<<<NE, 256>>>();
    k_flags<<<NSLOT/256, 256>>>();
    k_boundary<<<64, 256>>>();
    k_compact<<<(NSLOT + 255)/256, 256>>>();

    dim3 g1(MTILES, HID/256, NE);
    k_gemm1_mma<<<g1, 256, G1_SZ>>>(b1);
    dim3 g2(MTILES, 1, NE);
    k_gemm2_mma<<<g2, 256, G2_SZ>>>(b2);

    k_combine<<<(NTOK*32)/256, 256>>>(out);
    k_final<<<1, 32>>>(out, out_size);
}

// round 10
// speedup vs baseline: 4.6586x; 1.1977x over previous
#include <cuda_runtime.h>
#include <cuda_fp16.h>
#include <math.h>
#include <stdint.h>

#define NTOK  131072
#define DIMV  256
#define HID   512
#define NE    16
#define CAP   18023
#define NSLOT (NTOK*2)
#define ECAP  (NE*CAP)
#define NB    32768
#define MTILES ((CAP+127)/128)

// ---------------- scratch (static device globals) ----------------------------
__device__ float g_gate[NSLOT];
__device__ int   g_expert[NSLOT];
__device__ unsigned char g_kept[NSLOT];
__device__ int   g_counts[NE];
__device__ int   g_cursor[NE];
__device__ int   g_perm[ECAP];
__device__ int   g_hist[NE*NB];
__device__ int   g_bstar[NE], g_rrem[NE];
__device__ int   g_blist[NSLOT];
__device__ int   g_btotal;
__device__ float g_imp[NE];
__device__ float g_ent;

__device__ __half g_ctx_h[(size_t)NTOK * DIMV];
__device__ __half g_w1t[(size_t)NE * HID * DIMV];   // [e][h][d]
__device__ __half g_w2t[(size_t)NE * DIMV * HID];   // [e][d][h]
__device__ __half g_y[(size_t)NSLOT * DIMV];

// ---------------- helpers ----------------------------------------------------
__device__ __forceinline__ uint32_t smem_u32(const void* p) {
    uint32_t a;
    asm("{ .reg .u64 t; cvta.to.shared.u64 t, %1; cvt.u32.u64 %0, t; }"
        : "=r"(a) : "l"(p));
    return a;
}
__device__ __forceinline__ void cpasync16(uint32_t dst, const void* src, int srcsz) {
    asm volatile("cp.async.cg.shared.global [%0], [%1], 16, %2;"
                 :: "r"(dst), "l"(src), "r"(srcsz) : "memory");
}
#define CP_COMMIT() asm volatile("cp.async.commit_group;" ::: "memory")
#define CP_WAIT2()  asm volatile("cp.async.wait_group 2;" ::: "memory")
#define CP_WAIT1()  asm volatile("cp.async.wait_group 1;" ::: "memory")
#define CP_WAIT0()  asm volatile("cp.async.wait_group 0;" ::: "memory")

__device__ __forceinline__ void ldsm4(uint32_t* r, uint32_t addr) {
    asm volatile("ldmatrix.sync.aligned.m8n8.x4.shared.b16 {%0,%1,%2,%3}, [%4];"
                 : "=r"(r[0]), "=r"(r[1]), "=r"(r[2]), "=r"(r[3]) : "r"(addr));
}
__device__ __forceinline__ void sts32(uint32_t addr, uint32_t v) {
    asm volatile("st.shared.b32 [%0], %1;" :: "r"(addr), "r"(v) : "memory");
}
__device__ __forceinline__ void mma16816(float* c, const uint32_t* a, const uint32_t* b) {
    asm volatile(
        "mma.sync.aligned.m16n8k16.row.col.f32.f16.f16.f32 "
        "{%0,%1,%2,%3}, {%4,%5,%6,%7}, {%8,%9}, {%0,%1,%2,%3};"
        : "+f"(c[0]), "+f"(c[1]), "+f"(c[2]), "+f"(c[3])
        : "r"(a[0]), "r"(a[1]), "r"(a[2]), "r"(a[3]), "r"(b[0]), "r"(b[1]));
}
__device__ __forceinline__ uint32_t packh(__half a, __half b) {
    return (uint32_t)__half_as_ushort(a) | ((uint32_t)__half_as_ushort(b) << 16);
}

// padded smem row: 32 fp16 + 8 pad = 80 bytes
#define AROWB 80
// fused-MLP smem layout
#define FS_SLOT 0                       // int[128]
#define FS_GATE 512                     // float[128]
#define FS_X    1024                    // 8 kchunks * 128 rows * 80B = 81920
#define FS_W1   (FS_X + 81920)          // 2 stages * 40960
#define FS_W2   (FS_W1 + 81920)         // 40960 (2 kchunks * 256 rows * 80)
#define FS_H    (FS_W2 + 40960)         // 2 kchunks * 128 rows * 80 = 20480
#define FS_SZ   (FS_H + 20480)          // 226304

// ---------------- zero -------------------------------------------------------
__global__ void k_zero() {
    int i = blockIdx.x * blockDim.x + threadIdx.x;
    for (int j = i; j < NE*NB; j += gridDim.x * blockDim.x) g_hist[j] = 0;
    if (i < NE) { g_counts[i] = 0; g_cursor[i] = 0; g_imp[i] = 0.f; }
    if (i == 0) { g_ent = 0.f; g_btotal = 0; }
}

// ---------------- coalesced transpose + fp16 convert -------------------------
__global__ void k_transpose(const float* __restrict__ src, int which, int R, int C) {
    __shared__ float tile[32][33];
    __half* dstg = which ? g_w2t : g_w1t;
    int e = blockIdx.z;
    const float* S = src + (size_t)e * R * C;
    __half* D = dstg + (size_t)e * R * C;
    int c0 = blockIdx.x * 32, r0 = blockIdx.y * 32;
    int tc = threadIdx.x & 31, tr4 = threadIdx.x >> 5;
#pragma unroll
    for (int i = 0; i < 4; i++) {
        int r = tr4 + i*8;
        tile[r][tc] = S[(size_t)(r0 + r)*C + c0 + tc];
    }
    __syncthreads();
#pragma unroll
    for (int i = 0; i < 4; i++) {
        int r = tr4 + i*8;
        D[(size_t)(c0 + r)*R + r0 + tc] = __float2half_rn(tile[tc][r]);
    }
}

// ---------------- router: 4 threads/token, 8 tokens/warp ---------------------
__global__ void k_router(const float* __restrict__ ctx,
                         const float* __restrict__ Wg,
                         const float* __restrict__ bg) {
    __shared__ float sWT[DIMV*20];
    __shared__ float s_imp[NE];
    __shared__ float s_ent;
    __shared__ float s_bg[NE];
    int tid = threadIdx.x;
    for (int i = tid; i < NE*DIMV; i += blockDim.x)
        sWT[(i >> 4)*20 + (i & 15)] = Wg[i];
    if (tid < NE) { s_imp[tid] = 0.f; s_bg[tid] = bg[tid]; }
    if (tid == 0) s_ent = 0.f;
    __syncthreads();

    int warp = tid >> 5, lane = tid & 31;
    int q = lane & 3;
    int t = blockIdx.x * 64 + warp * 8 + (lane >> 2);
    const float* x = ctx + (size_t)t * DIMV;

    float acc[NE];
#pragma unroll
    for (int e = 0; e < NE; e++) acc[e] = 0.f;
#pragma unroll 16
    for (int i = 0; i < 64; i++) {
        int d = i*4 + q;
        float xv = x[d];
        const float4* wrow = (const float4*)&sWT[d*20];
#pragma unroll
        for (int e4 = 0; e4 < 4; e4++) {
            float4 w = wrow[e4];
            acc[e4*4+0] += xv * w.x;
            acc[e4*4+1] += xv * w.y;
            acc[e4*4+2] += xv * w.z;
            acc[e4*4+3] += xv * w.w;
        }
    }
#pragma unroll
    for (int e = 0; e < NE; e++) {
        acc[e] += __shfl_xor_sync(0xffffffffu, acc[e], 1);
        acc[e] += __shfl_xor_sync(0xffffffffu, acc[e], 2);
        acc[e] += s_bg[e];
    }

    int i0 = 0; float v0 = acc[0];
#pragma unroll
    for (int e = 1; e < NE; e++) if (acc[e] > v0) { v0 = acc[e]; i0 = e; }
    int i1 = (i0 == 0) ? 1 : 0; float v1 = acc[i1];
#pragma unroll
    for (int e = 0; e < NE; e++)
        if (e != i0 && acc[e] > v1) { v1 = acc[e]; i1 = e; }

    float sum = 0.f;
#pragma unroll
    for (int e = 0; e < NE; e++) { acc[e] = __expf(acc[e] - v0); sum += acc[e]; }
    float inv = 1.f / sum;
    float ent = 0.f;
#pragma unroll
    for (int e = 0; e < NE; e++) {
        acc[e] *= inv;
        ent -= acc[e] * __logf(fmaxf(acc[e], 1e-9f));
    }
#pragma unroll
    for (int e = 0; e < NE; e++) {
        acc[e] += __shfl_xor_sync(0xffffffffu, acc[e], 4);
        acc[e] += __shfl_xor_sync(0xffffffffu, acc[e], 8);
        acc[e] += __shfl_xor_sync(0xffffffffu, acc[e], 16);
    }
    ent += __shfl_xor_sync(0xffffffffu, ent, 4);
    ent += __shfl_xor_sync(0xffffffffu, ent, 8);
    ent += __shfl_xor_sync(0xffffffffu, ent, 16);
    if (lane == 0) {
#pragma unroll
        for (int e = 0; e < NE; e++) atomicAdd(&s_imp[e], acc[e]);
        atomicAdd(&s_ent, ent);
    }

    if (q == 0) {
        float ex = __expf(v1 - v0);
        float gg0 = 1.f / (1.f + ex);
        float gg1 = ex / (1.f + ex);
        int s0 = 2*t, s1 = 2*t + 1;
        g_expert[s0] = i0; g_expert[s1] = i1;
        g_gate[s0] = gg0;  g_gate[s1] = gg1;
        atomicAdd(&g_counts[i0], 1);
        atomicAdd(&g_counts[i1], 1);
        atomicAdd(&g_hist[i0*NB + (int)(__float_as_uint(gg0) >> 17)], 1);
        atomicAdd(&g_hist[i1*NB + (int)(__float_as_uint(gg1) >> 17)], 1);
    }
    __syncthreads();
    if (tid < NE) atomicAdd(&g_imp[tid], s_imp[tid]);
    if (tid == 0) atomicAdd(&g_ent, s_ent);

    {
        const float4* src = (const float4*)(ctx + (size_t)blockIdx.x * 64 * DIMV);
        uint2* dst = (uint2*)(g_ctx_h + (size_t)blockIdx.x * 64 * DIMV);
#pragma unroll
        for (int i = 0; i < 16; i++) {
            int j = tid + i*256;
            float4 v = src[j];
            uint2 pk;
            pk.x = packh(__float2half_rn(v.x), __float2half_rn(v.y));
            pk.y = packh(__float2half_rn(v.z), __float2half_rn(v.w));
            dst[j] = pk;
        }
    }
}

// ---------------- capacity cutoff --------------------------------------------
__global__ void k_cutoff() {
    int e = blockIdx.x, tid = threadIdx.x;
    __shared__ int chunk[256], suffix[256];
    if (g_counts[e] <= CAP) {
        if (tid == 0) { g_bstar[e] = -1; g_rrem[e] = 0; }
        return;
    }
    const int* h = g_hist + e*NB;
    int b0 = tid * 128;
    int s = 0;
    for (int b = b0; b < b0 + 128; b++) s += h[b];
    chunk[tid] = s;
    __syncthreads();
    if (tid == 0) {
        int run = 0;
        for (int i = 255; i >= 0; i--) { suffix[i] = run; run += chunk[i]; }
    }
    __syncthreads();
    int cum = suffix[tid];
    for (int b = b0 + 127; b >= b0; b--) {
        int hb = h[b];
        if (cum < CAP && cum + hb >= CAP) {
            g_bstar[e] = b; g_rrem[e] = CAP - cum;
        }
        cum += hb;
    }
}

__global__ void k_flags() {
    int s = blockIdx.x * blockDim.x + threadIdx.x;
    if (s >= NSLOT) return;
    int e = g_expert[s];
    unsigned char kept;
    if (g_counts[e] <= CAP) kept = 1;
    else {
        int b  = (int)(__float_as_uint(g_gate[s]) >> 17);
        int bs = g_bstar[e];
        if (b > bs) kept = 1;
        else if (b < bs) kept = 0;
        else {
            kept = 0;
            int p = atomicAdd(&g_btotal, 1);
            g_blist[p] = s;
        }
    }
    g_kept[s] = kept;
}

__global__ void k_boundary() {
    int total = g_btotal;
    for (int i = blockIdx.x * blockDim.x + threadIdx.x; i < total;
         i += gridDim.x * blockDim.x) {
        int si = g_blist[i];
        int e  = g_expert[si];
        unsigned int ki = __float_as_uint(g_gate[si]);
        int better = 0;
        for (int j = 0; j < total; j++) {
            int sj = g_blist[j];
            if (g_expert[sj] != e) continue;
            unsigned int kj = __float_as_uint(g_gate[sj]);
            better += (kj > ki) || (kj == ki && sj < si);
        }
        if (better < g_rrem[e]) g_kept[si] = 1;
    }
}

__global__ void k_compact() {
    __shared__ int scnt[NE], sbase[NE];
    int tid = threadIdx.x;
    int s = blockIdx.x * 256 + tid;
    if (tid < NE) scnt[tid] = 0;
    __syncthreads();
    int e = -1, rank = 0;
    if (s < NSLOT && g_kept[s]) {
        e = g_expert[s];
        rank = atomicAdd(&scnt[e], 1);
    }
    __syncthreads();
    if (tid < NE && scnt[tid] > 0) sbase[tid] = atomicAdd(&g_cursor[tid], scnt[tid]);
    __syncthreads();
    if (e >= 0) g_perm[e*CAP + sbase[e] + rank] = s;
}

// ---------------- fused MLP: Y = (relu(X@W1+b1)@W2 + b2)*gate ---------------
// One CTA per 128-token tile of one expert. X staged once; loop over HID in
// 8 chunks of 64: P-GEMM -> relu/pack -> H smem -> OUT-GEMM accumulate.
__global__ void __launch_bounds__(256, 1)
k_mlp(const float* __restrict__ b1, const float* __restrict__ b2) {
    int e = blockIdx.z;
    int Me = min(g_counts[e], CAP);
    int m0 = blockIdx.x * 128;
    if (m0 >= Me) return;

    extern __shared__ __align__(16) char smem[];
    uint32_t sb = smem_u32(smem);
    int tid = threadIdx.x;
    int* sslot = (int*)smem;
    float* sgate = (float*)(smem + FS_GATE);
    if (tid < 128) {
        int gr = m0 + tid;
        if (gr < Me) {
            int s = g_perm[e*CAP + gr];
            sslot[tid] = s; sgate[tid] = g_gate[s];
        } else { sslot[tid] = -1; sgate[tid] = 0.f; }
    }
    __syncthreads();

    const __half* W1 = g_w1t + (size_t)e * HID * DIMV;
    const __half* W2 = g_w2t + (size_t)e * DIMV * HID;

    // ---- X load: 8 kchunks x (2 cp.async per thread) -> one group ----
#pragma unroll
    for (int c = 0; c < 8; c++) {
#pragma unroll
        for (int i = 0; i < 2; i++) {
            int j = tid + i*256;
            int row = j >> 2, ch = j & 3;
            int tok = sslot[row] >> 1;     // -1 stays -1
            cpasync16(sb + FS_X + c*10240 + row*AROWB + ch*16,
                      g_ctx_h + (size_t)max(tok, 0)*DIMV + c*32 + ch*8,
                      tok >= 0 ? 16 : 0);
        }
    }
    CP_COMMIT();

    auto fill_w1 = [&](int stage, int h0) {
#pragma unroll
        for (int i = 0; i < 8; i++) {
            int c = i;
            int r = tid >> 2, ch = tid & 3;
            cpasync16(sb + FS_W1 + stage*40960 + c*5120 + r*AROWB + ch*16,
                      W1 + (size_t)(h0 + r)*DIMV + c*32 + ch*8, 16);
        }
        CP_COMMIT();
    };
    auto fill_w2 = [&](int h0) {
#pragma unroll
        for (int i = 0; i < 8; i++) {
            int c = i >> 2;
            int r = (tid >> 2) + (i & 3)*64;
            int ch = tid & 3;
            cpasync16(sb + FS_W2 + c*20480 + r*AROWB + ch*16,
                      W2 + (size_t)r*HID + h0 + c*32 + ch*8, 16);
        }
        CP_COMMIT();
    };

    fill_w1(0, 0);

    int warp = tid >> 5, lane = tid & 31;
    int g = lane >> 2, tg = lane & 3;
    // P-GEMM warp map (4m x 2n over 128x64)
    int wmP = (warp & 3) * 32, wnP = (warp >> 2) * 32;
    uint32_t aOffP = (uint32_t)(wmP + (lane & 7) + ((lane >> 3) & 1)*8) * AROWB
                     + ((lane >> 4) & 1)*16;
    uint32_t bOffP = (uint32_t)(wnP + ((lane >> 4) & 1)*8 + (lane & 7)) * AROWB
                     + ((lane >> 3) & 1)*16;
    // OUT-GEMM warp map (2m x 4n over 128x256)
    int wm = (warp & 1) * 64, wn = (warp >> 1) * 64;
    uint32_t aOffO = (uint32_t)(wm + (lane & 7) + ((lane >> 3) & 1)*8) * AROWB
                     + ((lane >> 4) & 1)*16;
    uint32_t bOffO = (uint32_t)(wn + ((lane >> 4) & 1)*8 + (lane & 7)) * AROWB
                     + ((lane >> 3) & 1)*16;

    float accO[4][8][4];
#pragma unroll
    for (int a = 0; a < 4; a++)
#pragma unroll
        for (int b = 0; b < 8; b++)
#pragma unroll
            for (int cc = 0; cc < 4; cc++) accO[a][b][cc] = 0.f;

    const float* bias1 = b1 + (size_t)e * HID;

    for (int h = 0; h < 8; h++) {
        __syncthreads();                       // OUT(h-1) done: W2/H reusable
        fill_w2(h * 64);
        if (h < 7) fill_w1((h + 1) & 1, (h + 1) * 64);
        if (h < 7) CP_WAIT2(); else CP_WAIT1();    // X + W1(h) landed
        __syncthreads();

        // ---- P-GEMM: P[128x64] = X @ W1(h) ----
        float accP[2][4][4];
#pragma unroll
        for (int a = 0; a < 2; a++)
#pragma unroll
            for (int b = 0; b < 4; b++)
#pragma unroll
                for (int cc = 0; cc < 4; cc++) accP[a][b][cc] = 0.f;

        uint32_t w1b = sb + FS_W1 + (h & 1)*40960;
#pragma unroll
        for (int c = 0; c < 8; c++) {
#pragma unroll
            for (int s = 0; s < 2; s++) {
                uint32_t Af[2][4], Bf[4][2];
#pragma unroll
                for (int mf = 0; mf < 2; mf++)
                    ldsm4(Af[mf], sb + FS_X + c*10240 + aOffP + mf*(16*AROWB) + s*32);
#pragma unroll
                for (int p = 0; p < 2; p++)
                    ldsm4(&Bf[2*p][0], w1b + c*5120 + bOffP + p*(16*AROWB) + s*32);
#pragma unroll
                for (int mf = 0; mf < 2; mf++)
#pragma unroll
                    for (int nf = 0; nf < 4; nf++)
                        mma16816(accP[mf][nf], Af[mf], Bf[nf]);
            }
        }

        // ---- P epilogue: bias + relu + pack -> H smem ----
#pragma unroll
        for (int nf = 0; nf < 4; nf++) {
            int cl = wnP + nf*8 + tg*2;                 // local col 0..63
            float2 bb = *(const float2*)(bias1 + h*64 + cl);
            uint32_t kcoff = (uint32_t)(cl >> 5)*10240 + (uint32_t)(cl & 31)*2;
#pragma unroll
            for (int mf = 0; mf < 2; mf++)
#pragma unroll
                for (int hv = 0; hv < 2; hv++) {
                    int row = wmP + mf*16 + g + hv*8;
                    float v0 = fmaxf(accP[mf][nf][hv*2+0] + bb.x, 0.f);
                    float v1 = fmaxf(accP[mf][nf][hv*2+1] + bb.y, 0.f);
                    sts32(sb + FS_H + kcoff + (uint32_t)row*AROWB,
                          packh(__float2half_rn(v0), __float2half_rn(v1)));
                }
        }
        if (h < 7) CP_WAIT1(); else CP_WAIT0();    // W2(h) landed
        __syncthreads();                           // H + W2 visible to all

        // ---- OUT-GEMM: accO += H @ W2(h) ----
#pragma unroll
        for (int kc = 0; kc < 2; kc++) {
#pragma unroll
            for (int s = 0; s < 2; s++) {
                uint32_t Af[4][4], Bf[8][2];
#pragma unroll
                for (int mf = 0; mf < 4; mf++)
                    ldsm4(Af[mf], sb + FS_H + kc*10240 + aOffO + mf*(16*AROWB) + s*32);
#pragma unroll
                for (int p = 0; p < 4; p++)
                    ldsm4(&Bf[2*p][0], sb + FS_W2 + kc*20480 + bOffO + p*(16*AROWB) + s*32);
#pragma unroll
                for (int mf = 0; mf < 4; mf++)
#pragma unroll
                    for (int nf = 0; nf < 8; nf++)
                        mma16816(accO[mf][nf], Af[mf], Bf[nf]);
            }
        }
    }

    // ---- final epilogue: bias2 + gate -> g_y ----
    const float* bias2 = b2 + (size_t)e * DIMV;
#pragma unroll
    for (int mf = 0; mf < 4; mf++) {
#pragma unroll
        for (int hv = 0; hv < 2; hv++) {
            int r = wm + mf*16 + g + hv*8;
            int slot = sslot[r];
            if (slot < 0) continue;
            float gate = sgate[r];
            __half* yr = g_y + (size_t)slot * DIMV;
#pragma unroll
            for (int nf = 0; nf < 8; nf++) {
                int col = wn + nf*8 + tg*2;
                float2 bb = *(const float2*)(bias2 + col);
                float v0 = (accO[mf][nf][hv*2+0] + bb.x) * gate;
                float v1 = (accO[mf][nf][hv*2+1] + bb.y) * gate;
                *(uint32_t*)(yr + col) = packh(__float2half_rn(v0), __float2half_rn(v1));
            }
        }
    }
}

// ---------------- combine (fp16 y) -------------------------------------------
__global__ void k_combine(float* __restrict__ out) {
    int idx = blockIdx.x * blockDim.x + threadIdx.x;
    if (idx >= NTOK * 32) return;
    int t = idx >> 5, f = idx & 31;
    float r[8];
#pragma unroll
    for (int i = 0; i < 8; i++) r[i] = 0.f;
    if (g_kept[2*t]) {
        uint4 a = *(const uint4*)(g_y + (size_t)(2*t)*DIMV + f*8);
        const uint32_t* w = (const uint32_t*)&a;
#pragma unroll
        for (int i = 0; i < 4; i++) {
            __half2 h2 = *(const __half2*)&w[i];
            float2 v = __half22float2(h2);
            r[2*i] += v.x; r[2*i+1] += v.y;
        }
    }
    if (g_kept[2*t + 1]) {
        uint4 a = *(const uint4*)(g_y + (size_t)(2*t+1)*DIMV + f*8);
        const uint32_t* w = (const uint32_t*)&a;
#pragma unroll
        for (int i = 0; i < 4; i++) {
            __half2 h2 = *(const __half2*)&w[i];
            float2 v = __half22float2(h2);
            r[2*i] += v.x; r[2*i+1] += v.y;
        }
    }
    float* o = out + (size_t)t*DIMV + f*8;
    *(float4*)o     = make_float4(r[0], r[1], r[2], r[3]);
    *(float4*)(o+4) = make_float4(r[4], r[5], r[6], r[7]);
}

// ---------------- finalize ---------------------------------------------------
__global__ void k_final(float* __restrict__ out, int out_size) {
    int lane = threadIdx.x;
    int c = (lane < NE) ? min(g_counts[lane], CAP) : 0;
    int tot = c;
#pragma unroll
    for (int off = 16; off; off >>= 1) tot += __shfl_xor_sync(0xffffffffu, tot, off);
    float denom = fmaxf((float)tot, 1.f);
    float aux = 0.f;
    if (lane < NE)
        aux = (g_imp[lane] / (float)NTOK) * ((float)c / denom) * (float)NE;
#pragma unroll
    for (int off = 16; off; off >>= 1) aux += __shfl_xor_sync(0xffffffffu, aux, off);
    int base = NTOK * DIMV;
    if (lane == 0 && out_size > base)     out[base]     = aux;
    if (lane == 0 && out_size > base + 1) out[base + 1] = g_ent / (float)NTOK;
    if (lane < NE && out_size > base + 2 + lane) out[base + 2 + lane] = (float)c;
}

// ---------------- launch -----------------------------------------------------
extern "C" void kernel_launch(void* const* d_in, const int* in_sizes, int n_in,
                              void* d_out, int out_size) {
    const float* ctx = (const float*)d_in[0];
    const float* Wg  = (const float*)d_in[1];
    const float* bg  = (const float*)d_in[2];
    const float* W1  = (const float*)d_in[3];
    const float* b1  = (const float*)d_in[4];
    const float* W2  = (const float*)d_in[5];
    const float* b2  = (const float*)d_in[6];
    float* out = (float*)d_out;

    static bool attr_done = false;
    if (!attr_done) {
        cudaFuncSetAttribute(k_mlp, cudaFuncAttributeMaxDynamicSharedMemorySize, FS_SZ);
        attr_done = true;
    }

    k_zero<<<512, 256>>>();
    k_transpose<<<dim3(HID/32, DIMV/32, NE), 256>>>(W1, 0, DIMV, HID);
    k_transpose<<<dim3(DIMV/32, HID/32, NE), 256>>>(W2, 1, HID, DIMV);
    k_router<<<NTOK/64, 256>>>(ctx, Wg, bg);
    k_cutoff<<<NE, 256>>>();
    k_flags<<<NSLOT/256, 256>>>();
    k_boundary<<<64, 256>>>();
    k_compact<<<(NSLOT + 255)/256, 256>>>();

    dim3 gm(MTILES, 1, NE);
    k_mlp<<<gm, 256, FS_SZ>>>(b1, b2);

    k_combine<<<(NTOK*32)/256, 256>>>(out);
    k_final<<<1, 32>>>(out, out_size);
}

// round 11
// speedup vs baseline: 5.0529x; 1.0847x over previous
#include <cuda_runtime.h>
#include <cuda_fp16.h>
#include <math.h>
#include <stdint.h>

#define NTOK  131072
#define DIMV  256
#define HID   512
#define NE    16
#define CAP   18023
#define NSLOT (NTOK*2)
#define ECAP  (NE*CAP)
#define NB    32768
#define MTILES ((CAP+127)/128)

// ---------------- scratch (static device globals) ----------------------------
__device__ float g_gate[NSLOT];
__device__ int   g_expert[NSLOT];
__device__ unsigned char g_kept[NSLOT];
__device__ int   g_counts[NE];
__device__ int   g_cursor[NE];
__device__ int   g_perm[ECAP];
__device__ int   g_hist[NE*NB];
__device__ int   g_bstar[NE], g_rrem[NE];
__device__ int   g_blist[NSLOT];
__device__ int   g_btotal;
__device__ float g_imp[NE];
__device__ float g_ent;

__device__ __half g_ctx_h[(size_t)NTOK * DIMV];
__device__ __half g_w1t[(size_t)NE * HID * DIMV];   // [e][h][d]
__device__ __half g_w2t[(size_t)NE * DIMV * HID];   // [e][d][h]
__device__ __half g_y[(size_t)NSLOT * DIMV];

// ---------------- helpers ----------------------------------------------------
__device__ __forceinline__ uint32_t smem_u32(const void* p) {
    uint32_t a;
    asm("{ .reg .u64 t; cvta.to.shared.u64 t, %1; cvt.u32.u64 %0, t; }"
        : "=r"(a) : "l"(p));
    return a;
}
__device__ __forceinline__ void cpasync16(uint32_t dst, const void* src, int srcsz) {
    asm volatile("cp.async.cg.shared.global [%0], [%1], 16, %2;"
                 :: "r"(dst), "l"(src), "r"(srcsz) : "memory");
}
#define CP_COMMIT() asm volatile("cp.async.commit_group;" ::: "memory")
#define CP_WAIT2()  asm volatile("cp.async.wait_group 2;" ::: "memory")
#define CP_WAIT1()  asm volatile("cp.async.wait_group 1;" ::: "memory")
#define CP_WAIT0()  asm volatile("cp.async.wait_group 0;" ::: "memory")

__device__ __forceinline__ void ldsm4(uint32_t* r, uint32_t addr) {
    asm volatile("ldmatrix.sync.aligned.m8n8.x4.shared.b16 {%0,%1,%2,%3}, [%4];"
                 : "=r"(r[0]), "=r"(r[1]), "=r"(r[2]), "=r"(r[3]) : "r"(addr));
}
__device__ __forceinline__ void sts32(uint32_t addr, uint32_t v) {
    asm volatile("st.shared.b32 [%0], %1;" :: "r"(addr), "r"(v) : "memory");
}
__device__ __forceinline__ void mma16816(float* c, const uint32_t* a, const uint32_t* b) {
    asm volatile(
        "mma.sync.aligned.m16n8k16.row.col.f32.f16.f16.f32 "
        "{%0,%1,%2,%3}, {%4,%5,%6,%7}, {%8,%9}, {%0,%1,%2,%3};"
        : "+f"(c[0]), "+f"(c[1]), "+f"(c[2]), "+f"(c[3])
        : "r"(a[0]), "r"(a[1]), "r"(a[2]), "r"(a[3]), "r"(b[0]), "r"(b[1]));
}
__device__ __forceinline__ uint32_t packh(__half a, __half b) {
    return (uint32_t)__half_as_ushort(a) | ((uint32_t)__half_as_ushort(b) << 16);
}

// ---------- fused-MLP smem: compact 64B rows, XOR swizzle seg^=(row>>1)&3 ----
// X:  8 chunks * 128 rows * 64B  = 65536
// W1: 2 stages * 8 chunks * 64 rows * 64B  = 65536
// W2: 2 stages * 2 kchunks * 256 rows * 64B = 65536
// H:  2 stages * 2 kchunks * 128 rows * 64B = 32768
#define FS_SLOT 0
#define FS_GATE 512
#define FS_X    1024
#define FS_W1   (FS_X  + 65536)
#define FS_W2   (FS_W1 + 65536)
#define FS_H    (FS_W2 + 65536)
#define FS_SZ   (FS_H  + 32768)        // 230400

// ---------------- zero -------------------------------------------------------
__global__ void k_zero() {
    int i = blockIdx.x * blockDim.x + threadIdx.x;
    for (int j = i; j < NE*NB; j += gridDim.x * blockDim.x) g_hist[j] = 0;
    if (i < NE) { g_counts[i] = 0; g_cursor[i] = 0; g_imp[i] = 0.f; }
    if (i == 0) { g_ent = 0.f; g_btotal = 0; }
}

// ---------------- coalesced transpose + fp16 convert -------------------------
__global__ void k_transpose(const float* __restrict__ src, int which, int R, int C) {
    __shared__ float tile[32][33];
    __half* dstg = which ? g_w2t : g_w1t;
    int e = blockIdx.z;
    const float* S = src + (size_t)e * R * C;
    __half* D = dstg + (size_t)e * R * C;
    int c0 = blockIdx.x * 32, r0 = blockIdx.y * 32;
    int tc = threadIdx.x & 31, tr4 = threadIdx.x >> 5;
#pragma unroll
    for (int i = 0; i < 4; i++) {
        int r = tr4 + i*8;
        tile[r][tc] = S[(size_t)(r0 + r)*C + c0 + tc];
    }
    __syncthreads();
#pragma unroll
    for (int i = 0; i < 4; i++) {
        int r = tr4 + i*8;
        D[(size_t)(c0 + r)*R + r0 + tc] = __float2half_rn(tile[tc][r]);
    }
}

// ---------------- router: 4 threads/token, 8 tokens/warp ---------------------
__global__ void k_router(const float* __restrict__ ctx,
                         const float* __restrict__ Wg,
                         const float* __restrict__ bg) {
    __shared__ float sWT[DIMV*20];
    __shared__ float s_imp[NE];
    __shared__ float s_ent;
    __shared__ float s_bg[NE];
    int tid = threadIdx.x;
    for (int i = tid; i < NE*DIMV; i += blockDim.x)
        sWT[(i >> 4)*20 + (i & 15)] = Wg[i];
    if (tid < NE) { s_imp[tid] = 0.f; s_bg[tid] = bg[tid]; }
    if (tid == 0) s_ent = 0.f;
    __syncthreads();

    int warp = tid >> 5, lane = tid & 31;
    int q = lane & 3;
    int t = blockIdx.x * 64 + warp * 8 + (lane >> 2);
    const float* x = ctx + (size_t)t * DIMV;

    float acc[NE];
#pragma unroll
    for (int e = 0; e < NE; e++) acc[e] = 0.f;
#pragma unroll 16
    for (int i = 0; i < 64; i++) {
        int d = i*4 + q;
        float xv = x[d];
        const float4* wrow = (const float4*)&sWT[d*20];
#pragma unroll
        for (int e4 = 0; e4 < 4; e4++) {
            float4 w = wrow[e4];
            acc[e4*4+0] += xv * w.x;
            acc[e4*4+1] += xv * w.y;
            acc[e4*4+2] += xv * w.z;
            acc[e4*4+3] += xv * w.w;
        }
    }
#pragma unroll
    for (int e = 0; e < NE; e++) {
        acc[e] += __shfl_xor_sync(0xffffffffu, acc[e], 1);
        acc[e] += __shfl_xor_sync(0xffffffffu, acc[e], 2);
        acc[e] += s_bg[e];
    }

    int i0 = 0; float v0 = acc[0];
#pragma unroll
    for (int e = 1; e < NE; e++) if (acc[e] > v0) { v0 = acc[e]; i0 = e; }
    int i1 = (i0 == 0) ? 1 : 0; float v1 = acc[i1];
#pragma unroll
    for (int e = 0; e < NE; e++)
        if (e != i0 && acc[e] > v1) { v1 = acc[e]; i1 = e; }

    float sum = 0.f;
#pragma unroll
    for (int e = 0; e < NE; e++) { acc[e] = __expf(acc[e] - v0); sum += acc[e]; }
    float inv = 1.f / sum;
    float ent = 0.f;
#pragma unroll
    for (int e = 0; e < NE; e++) {
        acc[e] *= inv;
        ent -= acc[e] * __logf(fmaxf(acc[e], 1e-9f));
    }
#pragma unroll
    for (int e = 0; e < NE; e++) {
        acc[e] += __shfl_xor_sync(0xffffffffu, acc[e], 4);
        acc[e] += __shfl_xor_sync(0xffffffffu, acc[e], 8);
        acc[e] += __shfl_xor_sync(0xffffffffu, acc[e], 16);
    }
    ent += __shfl_xor_sync(0xffffffffu, ent, 4);
    ent += __shfl_xor_sync(0xffffffffu, ent, 8);
    ent += __shfl_xor_sync(0xffffffffu, ent, 16);
    if (lane == 0) {
#pragma unroll
        for (int e = 0; e < NE; e++) atomicAdd(&s_imp[e], acc[e]);
        atomicAdd(&s_ent, ent);
    }

    if (q == 0) {
        float ex = __expf(v1 - v0);
        float gg0 = 1.f / (1.f + ex);
        float gg1 = ex / (1.f + ex);
        int s0 = 2*t, s1 = 2*t + 1;
        g_expert[s0] = i0; g_expert[s1] = i1;
        g_gate[s0] = gg0;  g_gate[s1] = gg1;
        atomicAdd(&g_counts[i0], 1);
        atomicAdd(&g_counts[i1], 1);
        atomicAdd(&g_hist[i0*NB + (int)(__float_as_uint(gg0) >> 17)], 1);
        atomicAdd(&g_hist[i1*NB + (int)(__float_as_uint(gg1) >> 17)], 1);
    }
    __syncthreads();
    if (tid < NE) atomicAdd(&g_imp[tid], s_imp[tid]);
    if (tid == 0) atomicAdd(&g_ent, s_ent);

    {
        const float4* src = (const float4*)(ctx + (size_t)blockIdx.x * 64 * DIMV);
        uint2* dst = (uint2*)(g_ctx_h + (size_t)blockIdx.x * 64 * DIMV);
#pragma unroll
        for (int i = 0; i < 16; i++) {
            int j = tid + i*256;
            float4 v = src[j];
            uint2 pk;
            pk.x = packh(__float2half_rn(v.x), __float2half_rn(v.y));
            pk.y = packh(__float2half_rn(v.z), __float2half_rn(v.w));
            dst[j] = pk;
        }
    }
}

// ---------------- capacity cutoff --------------------------------------------
__global__ void k_cutoff() {
    int e = blockIdx.x, tid = threadIdx.x;
    __shared__ int chunk[256], suffix[256];
    if (g_counts[e] <= CAP) {
        if (tid == 0) { g_bstar[e] = -1; g_rrem[e] = 0; }
        return;
    }
    const int* h = g_hist + e*NB;
    int b0 = tid * 128;
    int s = 0;
    for (int b = b0; b < b0 + 128; b++) s += h[b];
    chunk[tid] = s;
    __syncthreads();
    if (tid == 0) {
        int run = 0;
        for (int i = 255; i >= 0; i--) { suffix[i] = run; run += chunk[i]; }
    }
    __syncthreads();
    int cum = suffix[tid];
    for (int b = b0 + 127; b >= b0; b--) {
        int hb = h[b];
        if (cum < CAP && cum + hb >= CAP) {
            g_bstar[e] = b; g_rrem[e] = CAP - cum;
        }
        cum += hb;
    }
}

__global__ void k_flags() {
    int s = blockIdx.x * blockDim.x + threadIdx.x;
    if (s >= NSLOT) return;
    int e = g_expert[s];
    unsigned char kept;
    if (g_counts[e] <= CAP) kept = 1;
    else {
        int b  = (int)(__float_as_uint(g_gate[s]) >> 17);
        int bs = g_bstar[e];
        if (b > bs) kept = 1;
        else if (b < bs) kept = 0;
        else {
            kept = 0;
            int p = atomicAdd(&g_btotal, 1);
            g_blist[p] = s;
        }
    }
    g_kept[s] = kept;
}

__global__ void k_boundary() {
    int total = g_btotal;
    for (int i = blockIdx.x * blockDim.x + threadIdx.x; i < total;
         i += gridDim.x * blockDim.x) {
        int si = g_blist[i];
        int e  = g_expert[si];
        unsigned int ki = __float_as_uint(g_gate[si]);
        int better = 0;
        for (int j = 0; j < total; j++) {
            int sj = g_blist[j];
            if (g_expert[sj] != e) continue;
            unsigned int kj = __float_as_uint(g_gate[sj]);
            better += (kj > ki) || (kj == ki && sj < si);
        }
        if (better < g_rrem[e]) g_kept[si] = 1;
    }
}

__global__ void k_compact() {
    __shared__ int scnt[NE], sbase[NE];
    int tid = threadIdx.x;
    int s = blockIdx.x * 256 + tid;
    if (tid < NE) scnt[tid] = 0;
    __syncthreads();
    int e = -1, rank = 0;
    if (s < NSLOT && g_kept[s]) {
        e = g_expert[s];
        rank = atomicAdd(&scnt[e], 1);
    }
    __syncthreads();
    if (tid < NE && scnt[tid] > 0) sbase[tid] = atomicAdd(&g_cursor[tid], scnt[tid]);
    __syncthreads();
    if (e >= 0) g_perm[e*CAP + sbase[e] + rank] = s;
}

// ---------------- fused MLP, pipelined: Y = (relu(X@W1+b1)@W2 + b2)*gate -----
// 64B-row chunks, XOR swizzle seg' = seg ^ ((row>>1)&3). Per h-iteration:
// S1 -> prefetch W2(h+1),W1(h+2) -> wait -> S2 -> P(h+1) -> OUT(h).
__global__ void __launch_bounds__(256, 1)
k_mlp(const float* __restrict__ b1, const float* __restrict__ b2) {
    int e = blockIdx.z;
    int Me = min(g_counts[e], CAP);
    int m0 = blockIdx.x * 128;
    if (m0 >= Me) return;

    extern __shared__ __align__(16) char smem[];
    uint32_t sb = smem_u32(smem);
    int tid = threadIdx.x;
    int* sslot = (int*)smem;
    float* sgate = (float*)(smem + FS_GATE);
    if (tid < 128) {
        int gr = m0 + tid;
        if (gr < Me) {
            int s = g_perm[e*CAP + gr];
            sslot[tid] = s; sgate[tid] = g_gate[s];
        } else { sslot[tid] = -1; sgate[tid] = 0.f; }
    }
    __syncthreads();

    const __half* W1 = g_w1t + (size_t)e * HID * DIMV;
    const __half* W2 = g_w2t + (size_t)e * DIMV * HID;

    // ---- X: 8 chunks x 128 rows x 4 segs = 4096 cp.async (one group) ----
#pragma unroll
    for (int i = 0; i < 16; i++) {
        int j = tid + i*256;
        int c = j >> 9, rem = j & 511;
        int row = rem >> 2, seg = rem & 3;
        int tok = sslot[row] >> 1;
        cpasync16(sb + FS_X + c*8192 + row*64 + ((seg ^ ((row>>1)&3))*16),
                  g_ctx_h + (size_t)max(tok, 0)*DIMV + c*32 + seg*8,
                  tok >= 0 ? 16 : 0);
    }
    CP_COMMIT();

    auto fill_w1 = [&](int st, int h0) {
#pragma unroll
        for (int i = 0; i < 8; i++) {
            int j = tid + i*256;
            int c = j >> 8, rem = j & 255;
            int r = rem >> 2, seg = rem & 3;
            cpasync16(sb + FS_W1 + st*32768 + c*4096 + r*64 + ((seg ^ ((r>>1)&3))*16),
                      W1 + (size_t)(h0 + r)*DIMV + c*32 + seg*8, 16);
        }
        CP_COMMIT();
    };
    auto fill_w2 = [&](int st, int h0) {
#pragma unroll
        for (int i = 0; i < 8; i++) {
            int j = tid + i*256;
            int kc = j >> 10, rem = j & 1023;
            int r = rem >> 2, seg = rem & 3;
            cpasync16(sb + FS_W2 + st*32768 + kc*16384 + r*64 + ((seg ^ ((r>>1)&3))*16),
                      W2 + (size_t)r*HID + h0 + kc*32 + seg*8, 16);
        }
        CP_COMMIT();
    };

    fill_w1(0, 0);      // for P(0)
    fill_w2(0, 0);      // for OUT(0)
    fill_w1(1, 64);     // for P(1)

    int warp = tid >> 5, lane = tid & 31;
    int g = lane >> 2, tg = lane & 3;
    // P-GEMM warp map (4m x 2n over 128x64)
    int wmP = (warp & 3) * 32, wnP = (warp >> 2) * 32;
    // OUT-GEMM warp map (2m x 4n over 128x256)
    int wm = (warp & 1) * 64, wn = (warp >> 1) * 64;

    // swizzled per-lane ldsm components
    int lrA = lane & 15;
    int lrB = ((lane >> 4) & 1)*8 + (lane & 7);
    uint32_t x0 = (lane >> 1) & 1, x1 = (lane >> 2) & 1;
    uint32_t aSwz = ((((lane >> 4) & 1) ^ x0)) * 16;
    uint32_t bSwz = ((((lane >> 3) & 1) ^ x0)) * 16;
    uint32_t sx   = x1 * 32;
    // A-frag addr = chunkbase + (rowbase + lrA)*64 + aSwz + ((s*32) ^ sx)
    // B-frag addr = chunkbase + (colbase + p*16 + lrB)*64 + bSwz + ((s*32) ^ sx)
    uint32_t aP0 = (uint32_t)(wmP + lrA)*64 + aSwz;
    uint32_t bP0 = (uint32_t)(wnP + lrB)*64 + bSwz;
    uint32_t aO0 = (uint32_t)(wm + lrA)*64 + aSwz;
    uint32_t bO0 = (uint32_t)(wn + lrB)*64 + bSwz;
    uint32_t hsw = (uint32_t)((g >> 1) & 3);   // row-swizzle term for H stores

    float accO[4][8][4];
#pragma unroll
    for (int a = 0; a < 4; a++)
#pragma unroll
        for (int b = 0; b < 8; b++)
#pragma unroll
            for (int cc = 0; cc < 4; cc++) accO[a][b][cc] = 0.f;

    const float* bias1 = b1 + (size_t)e * HID;

    // prologue: wait X + W1(0), then P(0) -> H[0]
    CP_WAIT2();
    __syncthreads();
    {
        float accP[2][4][4];
#pragma unroll
        for (int a = 0; a < 2; a++)
#pragma unroll
            for (int b = 0; b < 4; b++)
#pragma unroll
                for (int cc = 0; cc < 4; cc++) accP[a][b][cc] = 0.f;
        uint32_t w1b = sb + FS_W1;          // stage 0
#pragma unroll
        for (int c = 0; c < 8; c++) {
#pragma unroll
            for (int s = 0; s < 2; s++) {
                uint32_t sterm = ((uint32_t)(s*32)) ^ sx;
                uint32_t Af[2][4], Bf[4][2];
#pragma unroll
                for (int mf = 0; mf < 2; mf++)
                    ldsm4(Af[mf], sb + FS_X + c*8192 + aP0 + mf*(16*64) + sterm);
#pragma unroll
                for (int p = 0; p < 2; p++)
                    ldsm4(&Bf[2*p][0], w1b + c*4096 + bP0 + p*(16*64) + sterm);
#pragma unroll
                for (int mf = 0; mf < 2; mf++)
#pragma unroll
                    for (int nf = 0; nf < 4; nf++)
                        mma16816(accP[mf][nf], Af[mf], Bf[nf]);
            }
        }
        // epilogue -> H stage 0
#pragma unroll
        for (int nf = 0; nf < 4; nf++) {
            int cl = wnP + nf*8 + tg*2;
            float2 bb = *(const float2*)(bias1 + cl);
            int kc = cl >> 5, colb = (cl & 31)*2;
            uint32_t coff = (uint32_t)kc*8192 +
                            (uint32_t)(((uint32_t)(colb >> 4) ^ hsw))*16 + (colb & 15);
#pragma unroll
            for (int mf = 0; mf < 2; mf++)
#pragma unroll
                for (int hv = 0; hv < 2; hv++) {
                    int row = wmP + mf*16 + g + hv*8;
                    float v0 = fmaxf(accP[mf][nf][hv*2+0] + bb.x, 0.f);
                    float v1 = fmaxf(accP[mf][nf][hv*2+1] + bb.y, 0.f);
                    sts32(sb + FS_H + coff + (uint32_t)row*64,
                          packh(__float2half_rn(v0), __float2half_rn(v1)));
                }
        }
    }

    for (int h = 0; h < 8; h++) {
        __syncthreads();                              // S1: P(h)/OUT(h-1) done
        if (h < 7) fill_w2((h + 1) & 1, (h + 1) * 64);
        if (h < 6) fill_w1(h & 1, (h + 2) * 64);
        if (h < 6) CP_WAIT2();
        else if (h == 6) CP_WAIT1();
        else CP_WAIT0();
        __syncthreads();                              // S2: visibility

        if (h < 7) {
            // ---- P(h+1): X @ W1 stage (h+1)&1 -> H[(h+1)&1] ----
            int hp = h + 1;
            float accP[2][4][4];
#pragma unroll
            for (int a = 0; a < 2; a++)
#pragma unroll
                for (int b = 0; b < 4; b++)
#pragma unroll
                    for (int cc = 0; cc < 4; cc++) accP[a][b][cc] = 0.f;
            uint32_t w1b = sb + FS_W1 + (hp & 1)*32768;
#pragma unroll
            for (int c = 0; c < 8; c++) {
#pragma unroll
                for (int s = 0; s < 2; s++) {
                    uint32_t sterm = ((uint32_t)(s*32)) ^ sx;
                    uint32_t Af[2][4], Bf[4][2];
#pragma unroll
                    for (int mf = 0; mf < 2; mf++)
                        ldsm4(Af[mf], sb + FS_X + c*8192 + aP0 + mf*(16*64) + sterm);
#pragma unroll
                    for (int p = 0; p < 2; p++)
                        ldsm4(&Bf[2*p][0], w1b + c*4096 + bP0 + p*(16*64) + sterm);
#pragma unroll
                    for (int mf = 0; mf < 2; mf++)
#pragma unroll
                        for (int nf = 0; nf < 4; nf++)
                            mma16816(accP[mf][nf], Af[mf], Bf[nf]);
                }
            }
            uint32_t hdst = sb + FS_H + (hp & 1)*16384;
#pragma unroll
            for (int nf = 0; nf < 4; nf++) {
                int cl = wnP + nf*8 + tg*2;
                float2 bb = *(const float2*)(bias1 + hp*64 + cl);
                int kc = cl >> 5, colb = (cl & 31)*2;
                uint32_t coff = (uint32_t)kc*8192 +
                                (uint32_t)(((uint32_t)(colb >> 4) ^ hsw))*16 + (colb & 15);
#pragma unroll
                for (int mf = 0; mf < 2; mf++)
#pragma unroll
                    for (int hv = 0; hv < 2; hv++) {
                        int row = wmP + mf*16 + g + hv*8;
                        float v0 = fmaxf(accP[mf][nf][hv*2+0] + bb.x, 0.f);
                        float v1 = fmaxf(accP[mf][nf][hv*2+1] + bb.y, 0.f);
                        sts32(hdst + coff + (uint32_t)row*64,
                              packh(__float2half_rn(v0), __float2half_rn(v1)));
                    }
            }
        }

        // ---- OUT(h): accO += H[h&1] @ W2 stage h&1 ----
        uint32_t hb  = sb + FS_H  + (h & 1)*16384;
        uint32_t w2b = sb + FS_W2 + (h & 1)*32768;
#pragma unroll
        for (int kc = 0; kc < 2; kc++) {
#pragma unroll
            for (int s = 0; s < 2; s++) {
                uint32_t sterm = ((uint32_t)(s*32)) ^ sx;
                uint32_t Af[4][4], Bf[8][2];
#pragma unroll
                for (int mf = 0; mf < 4; mf++)
                    ldsm4(Af[mf], hb + kc*8192 + aO0 + mf*(16*64) + sterm);
#pragma unroll
                for (int p = 0; p < 4; p++)
                    ldsm4(&Bf[2*p][0], w2b + kc*16384 + bO0 + p*(16*64) + sterm);
#pragma unroll
                for (int mf = 0; mf < 4; mf++)
#pragma unroll
                    for (int nf = 0; nf < 8; nf++)
                        mma16816(accO[mf][nf], Af[mf], Bf[nf]);
            }
        }
    }

    // ---- final epilogue: bias2 + gate -> g_y ----
    const float* bias2 = b2 + (size_t)e * DIMV;
#pragma unroll
    for (int mf = 0; mf < 4; mf++) {
#pragma unroll
        for (int hv = 0; hv < 2; hv++) {
            int r = wm + mf*16 + g + hv*8;
            int slot = sslot[r];
            if (slot < 0) continue;
            float gate = sgate[r];
            __half* yr = g_y + (size_t)slot * DIMV;
#pragma unroll
            for (int nf = 0; nf < 8; nf++) {
                int col = wn + nf*8 + tg*2;
                float2 bb = *(const float2*)(bias2 + col);
                float v0 = (accO[mf][nf][hv*2+0] + bb.x) * gate;
                float v1 = (accO[mf][nf][hv*2+1] + bb.y) * gate;
                *(uint32_t*)(yr + col) = packh(__float2half_rn(v0), __float2half_rn(v1));
            }
        }
    }
}

// ---------------- combine (fp16 y) -------------------------------------------
__global__ void k_combine(float* __restrict__ out) {
    int idx = blockIdx.x * blockDim.x + threadIdx.x;
    if (idx >= NTOK * 32) return;
    int t = idx >> 5, f = idx & 31;
    float r[8];
#pragma unroll
    for (int i = 0; i < 8; i++) r[i] = 0.f;
    if (g_kept[2*t]) {
        uint4 a = *(const uint4*)(g_y + (size_t)(2*t)*DIMV + f*8);
        const uint32_t* w = (const uint32_t*)&a;
#pragma unroll
        for (int i = 0; i < 4; i++) {
            __half2 h2 = *(const __half2*)&w[i];
            float2 v = __half22float2(h2);
            r[2*i] += v.x; r[2*i+1] += v.y;
        }
    }
    if (g_kept[2*t + 1]) {
        uint4 a = *(const uint4*)(g_y + (size_t)(2*t+1)*DIMV + f*8);
        const uint32_t* w = (const uint32_t*)&a;
#pragma unroll
        for (int i = 0; i < 4; i++) {
            __half2 h2 = *(const __half2*)&w[i];
            float2 v = __half22float2(h2);
            r[2*i] += v.x; r[2*i+1] += v.y;
        }
    }
    float* o = out + (size_t)t*DIMV + f*8;
    *(float4*)o     = make_float4(r[0], r[1], r[2], r[3]);
    *(float4*)(o+4) = make_float4(r[4], r[5], r[6], r[7]);
}

// ---------------- finalize ---------------------------------------------------
__global__ void k_final(float* __restrict__ out, int out_size) {
    int lane = threadIdx.x;
    int c = (lane < NE) ? min(g_counts[lane], CAP) : 0;
    int tot = c;
#pragma unroll
    for (int off = 16; off; off >>= 1) tot += __shfl_xor_sync(0xffffffffu, tot, off);
    float denom = fmaxf((float)tot, 1.f);
    float aux = 0.f;
    if (lane < NE)
        aux = (g_imp[lane] / (float)NTOK) * ((float)c / denom) * (float)NE;
#pragma unroll
    for (int off = 16; off; off >>= 1) aux += __shfl_xor_sync(0xffffffffu, aux, off);
    int base = NTOK * DIMV;
    if (lane == 0 && out_size > base)     out[base]     = aux;
    if (lane == 0 && out_size > base + 1) out[base + 1] = g_ent / (float)NTOK;
    if (lane < NE && out_size > base + 2 + lane) out[base + 2 + lane] = (float)c;
}

// ---------------- launch -----------------------------------------------------
extern "C" void kernel_launch(void* const* d_in, const int* in_sizes, int n_in,
                              void* d_out, int out_size) {
    const float* ctx = (const float*)d_in[0];
    const float* Wg  = (const float*)d_in[1];
    const float* bg  = (const float*)d_in[2];
    const float* W1  = (const float*)d_in[3];
    const float* b1  = (const float*)d_in[4];
    const float* W2  = (const float*)d_in[5];
    const float* b2  = (const float*)d_in[6];
    float* out = (float*)d_out;

    static bool attr_done = false;
    if (!attr_done) {
        cudaFuncSetAttribute(k_mlp, cudaFuncAttributeMaxDynamicSharedMemorySize, FS_SZ);
        attr_done = true;
    }

    k_zero<<<512, 256>>>();
    k_transpose<<<dim3(HID/32, DIMV/32, NE), 256>>>(W1, 0, DIMV, HID);
    k_transpose<<<dim3(DIMV/32, HID/32, NE), 256>>>(W2, 1, HID, DIMV);
    k_router<<<NTOK/64, 256>>>(ctx, Wg, bg);
    k_cutoff<<<NE, 256>>>();
    k_flags<<<NSLOT/256, 256>>>();
    k_boundary<<<64, 256>>>();
    k_compact<<<(NSLOT + 255)/256, 256>>>();

    dim3 gm(MTILES, 1, NE);
    k_mlp<<<gm, 256, FS_SZ>>>(b1, b2);

    k_combine<<<(NTOK*32)/256, 256>>>(out);
    k_final<<<1, 32>>>(out, out_size);
}